// round 10
// baseline (speedup 1.0000x reference)
#include <cuda_runtime.h>
#include <math.h>
#include <stdint.h>

#define S_ 7
#define H_ 56
#define W_ 56
#define WS 7
#define C_ 384
#define HEADS 12
#define NW 64
#define NTOK 344
#define NWIN 343
#define L_ (S_*H_*W_)          /* 21952 */
#define M1 (NW*NTOK)           /* 22016 */
#define HID 1536
#define EPS_LN 1e-5f
#define QSCALE 0.17677669529663687f  /* 32^-0.5 */

/* ---------------- scratch (static device globals; no allocation) -------- */
__device__ float g_xc     [(size_t)M1 * C_];
__device__ float g_qkv    [(size_t)M1 * 3 * C_];
__device__ float g_attnout[(size_t)M1 * C_];
__device__ float g_xres   [(size_t)L_ * C_];
__device__ float g_ln2    [(size_t)M1 * C_];
__device__ float g_hid    [(size_t)M1 * HID];
__device__ float g_bias   [(size_t)HEADS * NWIN * NWIN];
__device__ float g_wqkv   [(size_t)C_ * 3 * C_];   /* W^T [N][K] tf32 */
__device__ float g_wproj  [(size_t)C_ * C_];
__device__ float g_wfc1   [(size_t)C_ * HID];
__device__ float g_wfc2   [(size_t)HID * C_];

/* ---------------- helpers ---------------------------------------------- */
__device__ __forceinline__ float warp_sum(float v) {
    v += __shfl_xor_sync(0xffffffffu, v, 16);
    v += __shfl_xor_sync(0xffffffffu, v, 8);
    v += __shfl_xor_sync(0xffffffffu, v, 4);
    v += __shfl_xor_sync(0xffffffffu, v, 2);
    v += __shfl_xor_sync(0xffffffffu, v, 1);
    return v;
}
__device__ __forceinline__ float warp_max(float v) {
    v = fmaxf(v, __shfl_xor_sync(0xffffffffu, v, 16));
    v = fmaxf(v, __shfl_xor_sync(0xffffffffu, v, 8));
    v = fmaxf(v, __shfl_xor_sync(0xffffffffu, v, 4));
    v = fmaxf(v, __shfl_xor_sync(0xffffffffu, v, 2));
    v = fmaxf(v, __shfl_xor_sync(0xffffffffu, v, 1));
    return v;
}
__device__ __forceinline__ float gelu_f(float v) {
    return 0.5f * v * (1.f + erff(v * 0.7071067811865475f));
}
__device__ __forceinline__ float tf32r(float x) {
    uint32_t u;
    asm("cvt.rna.tf32.f32 %0, %1;" : "=r"(u) : "f"(x));
    return __uint_as_float(u);
}
__device__ __forceinline__ void cpa16(float* s, const float* g) {
    uint32_t sa = (uint32_t)__cvta_generic_to_shared(s);
    asm volatile("cp.async.cg.shared.global [%0], [%1], 16;\n" :: "r"(sa), "l"(g));
}
#define MMA_TF32(c4, a4, b2)                                                   \
    asm volatile(                                                              \
        "mma.sync.aligned.m16n8k8.row.col.f32.tf32.tf32.f32 "                  \
        "{%0,%1,%2,%3}, {%4,%5,%6,%7}, {%8,%9}, {%0,%1,%2,%3};\n"              \
        : "+f"((c4)[0]), "+f"((c4)[1]), "+f"((c4)[2]), "+f"((c4)[3])           \
        : "r"((a4)[0]), "r"((a4)[1]), "r"((a4)[2]), "r"((a4)[3]),              \
          "r"((b2)[0]), "r"((b2)[1]))
#define LDSM4(r0, r1, r2, r3, addr)                                            \
    asm volatile("ldmatrix.sync.aligned.m8n8.x4.shared.b16 {%0,%1,%2,%3}, [%4];" \
                 : "=r"(r0), "=r"(r1), "=r"(r2), "=r"(r3) : "r"(addr))
#define LDSM2(r0, r1, addr)                                                    \
    asm volatile("ldmatrix.sync.aligned.m8n8.x2.shared.b16 {%0,%1}, [%2];"     \
                 : "=r"(r0), "=r"(r1) : "r"(addr))

__device__ __forceinline__ int scatter_row(int l) {
    int s   = l / (H_ * W_);
    int rem = l % (H_ * W_);
    int h   = rem / W_;
    int w   = rem % W_;
    int s2 = (s >= 3) ? s - 3 : s + 4;
    int h2 = (h >= 3) ? h - 3 : h + 53;
    int w2 = (w >= 3) ? w - 3 : w + 53;
    int win = (h2 / WS) * 8 + (w2 / WS);
    int t   = s2 * 49 + (h2 % WS) * 7 + (w2 % WS);
    return win * NTOK + 1 + t;
}
__device__ __forceinline__ int unscatter_l(int win, int t) {
    int t0 = t - 1;
    int ts = t0 / 49, th = (t0 / 7) % 7, tw = t0 % 7;
    int wh = win >> 3, ww = win & 7;
    int h2 = wh * 7 + th, w2 = ww * 7 + tw;
    int s  = (ts <= 3) ? ts + 3 : ts - 4;
    int hh = (h2 <= 52) ? h2 + 3 : h2 - 53;
    int wo = (w2 <= 52) ? w2 + 3 : w2 - 53;
    return (s * H_ + hh) * W_ + wo;
}

/* ---------------- small kernels ----------------------------------------- */
__global__ void wtrans_pair(const float* __restrict__ w0, float* __restrict__ o0,
                            int K0, int N0,
                            const float* __restrict__ w1, float* __restrict__ o1,
                            int K1, int N1) {
    __shared__ float t[32][33];
    const float* w = blockIdx.z ? w1 : w0;
    float*       o = blockIdx.z ? o1 : o0;
    int K = blockIdx.z ? K1 : K0;
    int N = blockIdx.z ? N1 : N0;
    int bn = blockIdx.x * 32, bk = blockIdx.y * 32;
    if (bn >= N || bk >= K) return;
    int tx = threadIdx.x, ty = threadIdx.y;
#pragma unroll
    for (int i = 0; i < 32; i += 8)
        t[ty + i][tx] = w[(size_t)(bk + ty + i) * N + bn + tx];
    __syncthreads();
#pragma unroll
    for (int i = 0; i < 32; i += 8)
        o[(size_t)(bn + ty + i) * K + bk + tx] = tf32r(t[tx][ty + i]);
}

__global__ void bias_pre(const float* __restrict__ bt) {
    int idx = blockIdx.x * blockDim.x + threadIdx.x;
    if (idx >= NWIN * NWIN) return;
    int i = idx / NWIN, j = idx % NWIN;
    int si = i / 49, hi = (i / 7) % 7, wi = i % 7;
    int sj = j / 49, hj = (j / 7) % 7, wj = j % 7;
    int r = (si - sj + 6) * 20 + (hi - hj + 6) * 13 + (wi - wj + 6);
#pragma unroll
    for (int h = 0; h < HEADS; h++)
        g_bias[(size_t)h * NWIN * NWIN + idx] = bt[r * HEADS + h];
}

__global__ void gt_copy(const float* __restrict__ gt) {
    int idx = blockIdx.x * blockDim.x + threadIdx.x;
    if (idx >= NW * C_) return;
    int w = idx / C_, c = idx % C_;
    g_xc[((size_t)w * NTOK) * C_ + c] = tf32r(gt[idx]);
}

__global__ void ln1_scatter(const float* __restrict__ x,
                            const float* __restrict__ g,
                            const float* __restrict__ b) {
    int gw   = (blockIdx.x * blockDim.x + threadIdx.x) >> 5;
    int lane = threadIdx.x & 31;
    if (gw >= L_) return;
    const float* xi = x + (size_t)gw * C_;
    float v[12];
    float sum = 0.f;
#pragma unroll
    for (int m = 0; m < 12; m++) { v[m] = xi[lane + m * 32]; sum += v[m]; }
    sum = warp_sum(sum);
    float mu = sum * (1.f / 384.f);
    float vs = 0.f;
#pragma unroll
    for (int m = 0; m < 12; m++) { float d = v[m] - mu; vs += d * d; }
    vs = warp_sum(vs);
    float rstd = rsqrtf(vs * (1.f / 384.f) + EPS_LN);
    float* o = g_xc + (size_t)scatter_row(gw) * C_;
#pragma unroll
    for (int m = 0; m < 12; m++) {
        int c = lane + m * 32;
        o[c] = tf32r((v[m] - mu) * rstd * g[c] + b[c]);
    }
}

__global__ void ln2_kernel(const float* __restrict__ g,
                           const float* __restrict__ b) {
    int gw   = (blockIdx.x * blockDim.x + threadIdx.x) >> 5;
    int lane = threadIdx.x & 31;
    if (gw >= L_) return;
    const float* xi = g_xres + (size_t)gw * C_;
    float v[12];
    float sum = 0.f;
#pragma unroll
    for (int m = 0; m < 12; m++) { v[m] = xi[lane + m * 32]; sum += v[m]; }
    sum = warp_sum(sum);
    float mu = sum * (1.f / 384.f);
    float vs = 0.f;
#pragma unroll
    for (int m = 0; m < 12; m++) { float d = v[m] - mu; vs += d * d; }
    vs = warp_sum(vs);
    float rstd = rsqrtf(vs * (1.f / 384.f) + EPS_LN);
    float* o = g_ln2 + (size_t)gw * C_;
#pragma unroll
    for (int m = 0; m < 12; m++) {
        int c = lane + m * 32;
        o[c] = tf32r((v[m] - mu) * rstd * g[c] + b[c]);
    }
}

/* ---------------- attention via tf32 mma + ldmatrix --------------------- */
/* smem: Ks [NPAD][KSTR] (n-major), Vs [NTOK][VSTR], Ss [64][SSTR],
   Qs double-buffered 2x[64][QSTR], lab[NTOK].                             */
#define KSTR 36
#define VSTR 40
#define SSTR 356
#define QSTR 36
#define NPAD 352
#define ATT2_SMEM ((NPAD*KSTR + NTOK*VSTR + 64*SSTR + 2*64*QSTR) * 4 + NTOK * 4)

__global__ __launch_bounds__(256, 1) void attn_mma() {
    extern __shared__ float sm[];
    float* Ks = sm;
    float* Vs = Ks + NPAD * KSTR;
    float* Ss = Vs + NTOK * VSTR;
    float* Qs = Ss + 64 * SSTR;          /* 2 buffers of 64*QSTR */
    int*  lab = (int*)(Qs + 2 * 64 * QSTR);

    int tid = threadIdx.x, lane = tid & 31, wid = tid >> 5;
    int win = blockIdx.x / HEADS, head = blockIdx.x % HEADS;
    const float* base = g_qkv + (size_t)win * NTOK * (3 * C_) + head * 32;

    uint32_t ks_s = (uint32_t)__cvta_generic_to_shared(Ks);
    uint32_t ss_s = (uint32_t)__cvta_generic_to_shared(Ss);
    uint32_t qs_s = (uint32_t)__cvta_generic_to_shared(Qs);

    for (int idx = tid; idx < NPAD * 32; idx += 256) {
        int n = idx >> 5, d = idx & 31;
        Ks[n * KSTR + d] = (n < NTOK) ? tf32r(base[(size_t)n * (3 * C_) + C_ + d]) : 0.f;
    }
    for (int idx = tid; idx < NTOK * 32; idx += 256) {
        int j = idx >> 5, d = idx & 31;
        Vs[j * VSTR + d] = tf32r(base[(size_t)j * (3 * C_) + 2 * C_ + d]);
    }
    int wh = win >> 3, ww = win & 7;
    for (int t = tid; t < NTOK; t += 256) {
        int lv = -1;
        if (t > 0) {
            int t0 = t - 1;
            int ts = t0 / 49, th = (t0 / 7) % 7, tw = t0 % 7;
            int hh = wh * 7 + th, wc = ww * 7 + tw;
            int ia = (ts < 4) ? 1 : 2;
            int ib = (hh < 49) ? 0 : ((hh < 53) ? 1 : 2);
            int ic = (wc < 49) ? 0 : ((wc < 53) ? 1 : 2);
            lv = ia * 9 + ib * 3 + ic;
        }
        lab[t] = lv;
    }
    /* preload Q tile 0 into buffer 0 */
    for (int i = tid; i < 64 * 32; i += 256) {
        int m = i >> 5, d = i & 31;
        Qs[m * QSTR + d] = tf32r(base[(size_t)m * (3 * C_) + d] * QSCALE);
    }
    __syncthreads();

    const float* bh = g_bias + (size_t)head * NWIN * NWIN;
    const int wm  = (wid & 1) * 32;
    const int wn  = (wid >> 1) * 88;
    const int wnO = (wid >> 1) * 8;

    const int r_off = (lane & 7) + ((lane >> 3) & 1) * 8;
    const int a_k4  = ((lane >> 4) & 1) * 4;
    const int b_n   = (lane & 7) + ((lane >> 4) & 1) * 8;
    const int b_k4  = ((lane >> 3) & 1) * 4;

    for (int qt = 0; qt < 6; qt++) {
        int qbase = qt * 64;
        const int cur = qt & 1;
        const uint32_t q_s = qs_s + cur * (64 * QSTR) * 4;

        /* ---- S = Q K^T ---- */
        float c[2][11][4];
#pragma unroll
        for (int mt = 0; mt < 2; mt++)
#pragma unroll
            for (int nt = 0; nt < 11; nt++)
#pragma unroll
                for (int q = 0; q < 4; q++) c[mt][nt][q] = 0.f;

#pragma unroll
        for (int ks = 0; ks < 4; ks++) {
            uint32_t a[2][4], b[11][2];
#pragma unroll
            for (int mt = 0; mt < 2; mt++)
                LDSM4(a[mt][0], a[mt][1], a[mt][2], a[mt][3],
                      q_s + ((wm + mt * 16 + r_off) * QSTR + ks * 8 + a_k4) * 4);
#pragma unroll
            for (int p = 0; p < 5; p++)
                LDSM4(b[2 * p][0], b[2 * p][1], b[2 * p + 1][0], b[2 * p + 1][1],
                      ks_s + ((wn + p * 16 + b_n) * KSTR + ks * 8 + b_k4) * 4);
            LDSM2(b[10][0], b[10][1],
                  ks_s + ((wn + 80 + (b_n & 7)) * KSTR + ks * 8 + b_k4) * 4);
#pragma unroll
            for (int nt = 0; nt < 11; nt++) {
                MMA_TF32(c[0][nt], a[0], b[nt]);
                MMA_TF32(c[1][nt], a[1], b[nt]);
            }
        }

        /* ---- store S + bias + mask ---- */
#pragma unroll
        for (int mt = 0; mt < 2; mt++) {
            int r0 = wm + mt * 16 + (lane >> 2);
#pragma unroll
            for (int nt = 0; nt < 11; nt++) {
                int j0 = wn + nt * 8 + 2 * (lane & 3);
#pragma unroll
                for (int h = 0; h < 2; h++) {
                    int rr = r0 + h * 8;
                    int rg = qbase + rr;
                    float v0 = c[mt][nt][2 * h];
                    float v1 = c[mt][nt][2 * h + 1];
                    if (rg < NTOK && rg > 0) {
                        int lr = lab[rg];
                        if (j0 < NTOK && j0 > 0) {
                            v0 += bh[(rg - 1) * NWIN + (j0 - 1)];
                            if (lr != lab[j0]) v0 -= 100.f;
                        }
                        int j1 = j0 + 1;
                        if (j1 < NTOK) {
                            v1 += bh[(rg - 1) * NWIN + (j1 - 1)];
                            if (lr != lab[j1]) v1 -= 100.f;
                        }
                    }
                    if (j0 >= NTOK)     v0 = -1e30f;
                    if (j0 + 1 >= NTOK) v1 = -1e30f;
                    Ss[rr * SSTR + j0]     = v0;
                    Ss[rr * SSTR + j0 + 1] = v1;
                }
            }
        }
        __syncthreads();

        /* ---- softmax, write P tf32 ---- */
#pragma unroll
        for (int i = 0; i < 8; i++) {
            int rr = wid * 8 + i;
            float s[11];
            float mx = -1e30f;
#pragma unroll
            for (int m = 0; m < 11; m++) {
                s[m] = Ss[rr * SSTR + lane + m * 32];
                mx = fmaxf(mx, s[m]);
            }
            mx = warp_max(mx);
            float sum = 0.f;
#pragma unroll
            for (int m = 0; m < 11; m++) {
                float e = __expf(s[m] - mx);
                s[m] = e; sum += e;
            }
            sum = warp_sum(sum);
            float inv = 1.f / sum;
#pragma unroll
            for (int m = 0; m < 11; m++)
                Ss[rr * SSTR + lane + m * 32] = tf32r(s[m] * inv);
        }

        /* ---- prefetch next Q tile into alternate buffer ---- */
        if (qt + 1 < 6) {
            float* Qn = Qs + (cur ^ 1) * (64 * QSTR);
            int nb = (qt + 1) * 64;
            for (int i = tid; i < 64 * 32; i += 256) {
                int m = i >> 5, d = i & 31;
                int r = nb + m;
                float v = (r < NTOK) ? base[(size_t)r * (3 * C_) + d] * QSCALE : 0.f;
                Qn[m * QSTR + d] = tf32r(v);
            }
        }
        __syncthreads();

        /* ---- O = P V ---- */
        float o[2][4] = {};
#pragma unroll 4
        for (int kt = 0; kt < 43; kt++) {
            uint32_t b[2];
            int kr = kt * 8 + (lane & 3);
            int bc = wnO + (lane >> 2);
            b[0] = __float_as_uint(Vs[(kr    ) * VSTR + bc]);
            b[1] = __float_as_uint(Vs[(kr + 4) * VSTR + bc]);
#pragma unroll
            for (int mt = 0; mt < 2; mt++) {
                uint32_t a[4];
                LDSM4(a[0], a[1], a[2], a[3],
                      ss_s + ((wm + mt * 16 + r_off) * SSTR + kt * 8 + a_k4) * 4);
                MMA_TF32(o[mt], a, b);
            }
        }
#pragma unroll
        for (int mt = 0; mt < 2; mt++)
#pragma unroll
            for (int h = 0; h < 2; h++) {
                int rr = qbase + wm + mt * 16 + (lane >> 2) + h * 8;
                if (rr < NTOK) {
                    float2 v;
                    v.x = tf32r(o[mt][2 * h]);
                    v.y = tf32r(o[mt][2 * h + 1]);
                    *(float2*)&g_attnout[((size_t)win * NTOK + rr) * C_ +
                                         head * 32 + wnO + 2 * (lane & 3)] = v;
                }
            }
        __syncthreads();
    }
}

/* ---------------- TF32 tensor-core GEMM (R8 config: 128x128, 3-stage) --- */
#define ASTR 36
#define ABUF (128*ASTR)
#define STG  (2*ABUF)
#define GEMM_SMEM_BYTES (3 * STG * 4)   /* 110592 */

template<int EPI, int CVT>
__global__ __launch_bounds__(256, 2) void gemm_tc(const float* __restrict__ A,
                                                  const float* __restrict__ Bt,
                                                  const float* __restrict__ bias,
                                                  const float* __restrict__ res,
                                                  float* __restrict__ Cd,
                                                  float* __restrict__ gtout,
                                                  int Mstore, int N, int K) {
    extern __shared__ float sm[];
    const int tid = threadIdx.x, lane = tid & 31, wid = tid >> 5;
    const int bm = blockIdx.y * 128, bn = blockIdx.x * 128;
    const int wm = (wid & 1) * 64, wn = (wid >> 1) * 32;
    const uint32_t sm_s = (uint32_t)__cvta_generic_to_shared(sm);

    const int r_off = (lane & 7) + ((lane >> 3) & 1) * 8;
    const int a_k4  = ((lane >> 4) & 1) * 4;
    const int b_n   = (lane & 7) + ((lane >> 4) & 1) * 8;
    const int b_k4  = ((lane >> 3) & 1) * 4;

    float c[4][4][4];
#pragma unroll
    for (int i = 0; i < 4; i++)
#pragma unroll
        for (int j = 0; j < 4; j++)
#pragma unroll
            for (int k = 0; k < 4; k++) c[i][j][k] = 0.f;

    const int NK = K >> 5;

    auto issue = [&](int kt) {
        int p = kt % 3;
        float* As = sm + p * STG;
        float* Bs = As + ABUF;
        const float* Ag = A  + (size_t)bm * K + kt * 32;
        const float* Bg = Bt + (size_t)bn * K + kt * 32;
#pragma unroll
        for (int i = 0; i < 4; i++) {
            int idx = tid + i * 256;
            int r = idx >> 3, c4 = (idx & 7) * 4;
            cpa16(As + r * ASTR + c4, Ag + (size_t)r * K + c4);
        }
#pragma unroll
        for (int i = 0; i < 4; i++) {
            int idx = tid + i * 256;
            int r = idx >> 3, c4 = (idx & 7) * 4;
            cpa16(Bs + r * ASTR + c4, Bg + (size_t)r * K + c4);
        }
        asm volatile("cp.async.commit_group;\n");
    };

    issue(0);
    if (NK > 1) issue(1);

    for (int kt = 0; kt < NK; kt++) {
        if (kt + 1 < NK)
            asm volatile("cp.async.wait_group 1;\n");
        else
            asm volatile("cp.async.wait_group 0;\n");
        __syncthreads();
        if (kt + 2 < NK) issue(kt + 2);

        const int p = kt % 3;
        const uint32_t as_s = sm_s + p * STG * 4;
        const uint32_t bs_s = as_s + ABUF * 4;
#pragma unroll
        for (int ks = 0; ks < 4; ks++) {
            uint32_t a[4][4], b[4][2];
#pragma unroll
            for (int mt = 0; mt < 4; mt++)
                LDSM4(a[mt][0], a[mt][1], a[mt][2], a[mt][3],
                      as_s + ((wm + mt * 16 + r_off) * ASTR + ks * 8 + a_k4) * 4);
#pragma unroll
            for (int pp = 0; pp < 2; pp++)
                LDSM4(b[2 * pp][0], b[2 * pp][1], b[2 * pp + 1][0], b[2 * pp + 1][1],
                      bs_s + ((wn + pp * 16 + b_n) * ASTR + ks * 8 + b_k4) * 4);
#pragma unroll
            for (int mt = 0; mt < 4; mt++)
#pragma unroll
                for (int nt = 0; nt < 4; nt++)
                    MMA_TF32(c[mt][nt], a[mt], b[nt]);
        }
    }

    if (EPI == 3) {
#pragma unroll
        for (int mt = 0; mt < 4; mt++)
#pragma unroll
            for (int h = 0; h < 2; h++) {
                int row = bm + wm + mt * 16 + (lane >> 2) + h * 8;
                int win = row / NTOK, t = row % NTOK;
                float* dst;
                const float* xsrc = nullptr;
                if (t == 0) {
                    dst = gtout + (size_t)win * C_;
                } else {
                    int l = unscatter_l(win, t);
                    dst  = Cd  + (size_t)l * C_;
                    xsrc = res + (size_t)l * C_;
                }
#pragma unroll
                for (int nt = 0; nt < 4; nt++) {
                    int col = bn + wn + nt * 8 + 2 * (lane & 3);
                    float2 bb = *(const float2*)&bias[col];
                    float2 v;
                    v.x = c[mt][nt][2 * h]     + bb.x;
                    v.y = c[mt][nt][2 * h + 1] + bb.y;
                    if (xsrc) {
                        float2 rv = *(const float2*)&xsrc[col];
                        v.x += rv.x; v.y += rv.y;
                    }
                    *(float2*)&dst[col] = v;
                }
            }
    } else {
#pragma unroll
        for (int nt = 0; nt < 4; nt++) {
            int col = bn + wn + nt * 8 + 2 * (lane & 3);
            float2 bb = *(const float2*)&bias[col];
#pragma unroll
            for (int mt = 0; mt < 4; mt++) {
                int row0 = bm + wm + mt * 16 + (lane >> 2);
#pragma unroll
                for (int h = 0; h < 2; h++) {
                    int row = row0 + h * 8;
                    if (row < Mstore) {
                        float2 v;
                        v.x = c[mt][nt][2 * h]     + bb.x;
                        v.y = c[mt][nt][2 * h + 1] + bb.y;
                        if (EPI == 1) { v.x = gelu_f(v.x); v.y = gelu_f(v.y); }
                        size_t o = (size_t)row * N + col;
                        if (EPI == 2) {
                            float2 rv = *(const float2*)&res[o];
                            v.x += rv.x; v.y += rv.y;
                        }
                        if (CVT) { v.x = tf32r(v.x); v.y = tf32r(v.y); }
                        *(float2*)&Cd[o] = v;
                    }
                }
            }
        }
    }
}

/* ---------------- launch ------------------------------------------------ */
extern "C" void kernel_launch(void* const* d_in, const int* in_sizes, int n_in,
                              void* d_out, int out_size) {
    const float* x     = (const float*)d_in[0];
    const float* gt    = (const float*)d_in[1];
    const float* n1g   = (const float*)d_in[2];
    const float* n1b   = (const float*)d_in[3];
    const float* qkvw  = (const float*)d_in[4];
    const float* qkvb  = (const float*)d_in[5];
    const float* btab  = (const float*)d_in[6];
    const float* projw = (const float*)d_in[7];
    const float* projb = (const float*)d_in[8];
    const float* n2g   = (const float*)d_in[9];
    const float* n2b   = (const float*)d_in[10];
    const float* fc1w  = (const float*)d_in[11];
    const float* fc1b  = (const float*)d_in[12];
    const float* fc2w  = (const float*)d_in[13];
    const float* fc2b  = (const float*)d_in[14];
    float* out = (float*)d_out;

    float *xc, *qkv, *ao, *xres, *ln2b, *hb;
    float *wq, *wp, *w1, *w2;
    cudaGetSymbolAddress((void**)&xc,   g_xc);
    cudaGetSymbolAddress((void**)&qkv,  g_qkv);
    cudaGetSymbolAddress((void**)&ao,   g_attnout);
    cudaGetSymbolAddress((void**)&xres, g_xres);
    cudaGetSymbolAddress((void**)&ln2b, g_ln2);
    cudaGetSymbolAddress((void**)&hb,   g_hid);
    cudaGetSymbolAddress((void**)&wq,   g_wqkv);
    cudaGetSymbolAddress((void**)&wp,   g_wproj);
    cudaGetSymbolAddress((void**)&w1,   g_wfc1);
    cudaGetSymbolAddress((void**)&w2,   g_wfc2);

    cudaFuncSetAttribute(attn_mma,
                         cudaFuncAttributeMaxDynamicSharedMemorySize,
                         ATT2_SMEM);
    cudaFuncSetAttribute(gemm_tc<0, 0>,
                         cudaFuncAttributeMaxDynamicSharedMemorySize,
                         GEMM_SMEM_BYTES);
    cudaFuncSetAttribute(gemm_tc<1, 1>,
                         cudaFuncAttributeMaxDynamicSharedMemorySize,
                         GEMM_SMEM_BYTES);
    cudaFuncSetAttribute(gemm_tc<2, 0>,
                         cudaFuncAttributeMaxDynamicSharedMemorySize,
                         GEMM_SMEM_BYTES);
    cudaFuncSetAttribute(gemm_tc<3, 0>,
                         cudaFuncAttributeMaxDynamicSharedMemorySize,
                         GEMM_SMEM_BYTES);

    /* launches 0-4; qkv GEMM is capture index 5 for ncu (-s 5) */
    dim3 tb(32, 8);
    wtrans_pair<<<dim3((3 * C_) / 32, C_ / 32, 2), tb>>>(
        qkvw, wq, C_, 3 * C_, projw, wp, C_, C_);
    wtrans_pair<<<dim3(HID / 32, HID / 32, 2), tb>>>(
        fc1w, w1, C_, HID, fc2w, w2, HID, C_);
    bias_pre   <<<(NWIN * NWIN + 255) / 256, 256>>>(btab);
    gt_copy    <<<(NW * C_ + 255) / 256, 256>>>(gt);
    ln1_scatter<<<L_ / 8, 256>>>(x, n1g, n1b);

    gemm_tc<0, 0><<<dim3((3 * C_) / 128, M1 / 128), 256, GEMM_SMEM_BYTES>>>(
        xc, wq, qkvb, nullptr, qkv, nullptr, M1, 3 * C_, C_);

    attn_mma<<<NW * HEADS, 256, ATT2_SMEM>>>();

    gemm_tc<3, 0><<<dim3(C_ / 128, M1 / 128), 256, GEMM_SMEM_BYTES>>>(
        ao, wp, projb, x, xres, out + (size_t)L_ * C_, M1, C_, C_);

    ln2_kernel<<<L_ / 8, 256>>>(n2g, n2b);

    gemm_tc<1, 1><<<dim3(HID / 128, M1 / 128), 256, GEMM_SMEM_BYTES>>>(
        ln2b, w1, fc1b, nullptr, hb, nullptr, M1, HID, C_);

    gemm_tc<2, 0><<<dim3(C_ / 128, M1 / 128), 256, GEMM_SMEM_BYTES>>>(
        hb, w2, fc2b, xres, out, nullptr, L_, C_, HID);
}

// round 11
// speedup vs baseline: 1.4920x; 1.4920x over previous
#include <cuda_runtime.h>
#include <math.h>
#include <stdint.h>

#define S_ 7
#define H_ 56
#define W_ 56
#define WS 7
#define C_ 384
#define HEADS 12
#define NW 64
#define NTOK 344
#define NWIN 343
#define L_ (S_*H_*W_)          /* 21952 */
#define M1 (NW*NTOK)           /* 22016 */
#define HID 1536
#define EPS_LN 1e-5f
#define QSCALE 0.17677669529663687f  /* 32^-0.5 */

/* ---------------- scratch (static device globals; no allocation) -------- */
__device__ float g_xc     [(size_t)M1 * C_];
__device__ float g_qkv    [(size_t)M1 * 3 * C_];
__device__ float g_attnout[(size_t)M1 * C_];
__device__ float g_xres   [(size_t)L_ * C_];
__device__ float g_ln2    [(size_t)M1 * C_];
__device__ float g_hid    [(size_t)M1 * HID];
__device__ float g_bias   [(size_t)HEADS * NWIN * NWIN];
__device__ float g_wqkv   [(size_t)C_ * 3 * C_];   /* W^T [N][K] tf32 */
__device__ float g_wproj  [(size_t)C_ * C_];
__device__ float g_wfc1   [(size_t)C_ * HID];
__device__ float g_wfc2   [(size_t)HID * C_];

/* ---------------- helpers ---------------------------------------------- */
__device__ __forceinline__ float warp_sum(float v) {
    v += __shfl_xor_sync(0xffffffffu, v, 16);
    v += __shfl_xor_sync(0xffffffffu, v, 8);
    v += __shfl_xor_sync(0xffffffffu, v, 4);
    v += __shfl_xor_sync(0xffffffffu, v, 2);
    v += __shfl_xor_sync(0xffffffffu, v, 1);
    return v;
}
__device__ __forceinline__ float warp_max(float v) {
    v = fmaxf(v, __shfl_xor_sync(0xffffffffu, v, 16));
    v = fmaxf(v, __shfl_xor_sync(0xffffffffu, v, 8));
    v = fmaxf(v, __shfl_xor_sync(0xffffffffu, v, 4));
    v = fmaxf(v, __shfl_xor_sync(0xffffffffu, v, 2));
    v = fmaxf(v, __shfl_xor_sync(0xffffffffu, v, 1));
    return v;
}
__device__ __forceinline__ float gelu_f(float v) {
    return 0.5f * v * (1.f + erff(v * 0.7071067811865475f));
}
__device__ __forceinline__ float tf32r(float x) {
    uint32_t u;
    asm("cvt.rna.tf32.f32 %0, %1;" : "=r"(u) : "f"(x));
    return __uint_as_float(u);
}
__device__ __forceinline__ void cpa16(float* s, const float* g) {
    uint32_t sa = (uint32_t)__cvta_generic_to_shared(s);
    asm volatile("cp.async.cg.shared.global [%0], [%1], 16;\n" :: "r"(sa), "l"(g));
}
#define MMA_TF32(c4, a4, b2)                                                   \
    asm volatile(                                                              \
        "mma.sync.aligned.m16n8k8.row.col.f32.tf32.tf32.f32 "                  \
        "{%0,%1,%2,%3}, {%4,%5,%6,%7}, {%8,%9}, {%0,%1,%2,%3};\n"              \
        : "+f"((c4)[0]), "+f"((c4)[1]), "+f"((c4)[2]), "+f"((c4)[3])           \
        : "r"((a4)[0]), "r"((a4)[1]), "r"((a4)[2]), "r"((a4)[3]),              \
          "r"((b2)[0]), "r"((b2)[1]))
#define LDSM4(r0, r1, r2, r3, addr)                                            \
    asm volatile("ldmatrix.sync.aligned.m8n8.x4.shared.b16 {%0,%1,%2,%3}, [%4];" \
                 : "=r"(r0), "=r"(r1), "=r"(r2), "=r"(r3) : "r"(addr))
#define LDSM2(r0, r1, addr)                                                    \
    asm volatile("ldmatrix.sync.aligned.m8n8.x2.shared.b16 {%0,%1}, [%2];"     \
                 : "=r"(r0), "=r"(r1) : "r"(addr))

__device__ __forceinline__ int scatter_row(int l) {
    int s   = l / (H_ * W_);
    int rem = l % (H_ * W_);
    int h   = rem / W_;
    int w   = rem % W_;
    int s2 = (s >= 3) ? s - 3 : s + 4;
    int h2 = (h >= 3) ? h - 3 : h + 53;
    int w2 = (w >= 3) ? w - 3 : w + 53;
    int win = (h2 / WS) * 8 + (w2 / WS);
    int t   = s2 * 49 + (h2 % WS) * 7 + (w2 % WS);
    return win * NTOK + 1 + t;
}
__device__ __forceinline__ int unscatter_l(int win, int t) {
    int t0 = t - 1;
    int ts = t0 / 49, th = (t0 / 7) % 7, tw = t0 % 7;
    int wh = win >> 3, ww = win & 7;
    int h2 = wh * 7 + th, w2 = ww * 7 + tw;
    int s  = (ts <= 3) ? ts + 3 : ts - 4;
    int hh = (h2 <= 52) ? h2 + 3 : h2 - 53;
    int wo = (w2 <= 52) ? w2 + 3 : w2 - 53;
    return (s * H_ + hh) * W_ + wo;
}

/* ---------------- small kernels ----------------------------------------- */
__global__ void wtrans_pair(const float* __restrict__ w0, float* __restrict__ o0,
                            int K0, int N0,
                            const float* __restrict__ w1, float* __restrict__ o1,
                            int K1, int N1) {
    __shared__ float t[32][33];
    const float* w = blockIdx.z ? w1 : w0;
    float*       o = blockIdx.z ? o1 : o0;
    int K = blockIdx.z ? K1 : K0;
    int N = blockIdx.z ? N1 : N0;
    int bn = blockIdx.x * 32, bk = blockIdx.y * 32;
    if (bn >= N || bk >= K) return;
    int tx = threadIdx.x, ty = threadIdx.y;
#pragma unroll
    for (int i = 0; i < 32; i += 8)
        t[ty + i][tx] = w[(size_t)(bk + ty + i) * N + bn + tx];
    __syncthreads();
#pragma unroll
    for (int i = 0; i < 32; i += 8)
        o[(size_t)(bn + ty + i) * K + bk + tx] = tf32r(t[tx][ty + i]);
}

__global__ void bias_pre(const float* __restrict__ bt) {
    int idx = blockIdx.x * blockDim.x + threadIdx.x;
    if (idx >= NWIN * NWIN) return;
    int i = idx / NWIN, j = idx % NWIN;
    int si = i / 49, hi = (i / 7) % 7, wi = i % 7;
    int sj = j / 49, hj = (j / 7) % 7, wj = j % 7;
    int r = (si - sj + 6) * 20 + (hi - hj + 6) * 13 + (wi - wj + 6);
#pragma unroll
    for (int h = 0; h < HEADS; h++)
        g_bias[(size_t)h * NWIN * NWIN + idx] = bt[r * HEADS + h];
}

__global__ void gt_copy(const float* __restrict__ gt) {
    int idx = blockIdx.x * blockDim.x + threadIdx.x;
    if (idx >= NW * C_) return;
    int w = idx / C_, c = idx % C_;
    g_xc[((size_t)w * NTOK) * C_ + c] = tf32r(gt[idx]);
}

/* LN kernels: one warp per token, float4 vectorized */
__global__ void ln1_scatter(const float* __restrict__ x,
                            const float* __restrict__ g,
                            const float* __restrict__ b) {
    int gw   = (blockIdx.x * blockDim.x + threadIdx.x) >> 5;
    int lane = threadIdx.x & 31;
    if (gw >= L_) return;
    const float4* xi = (const float4*)(x + (size_t)gw * C_);
    float4 v[3];
    float sum = 0.f;
#pragma unroll
    for (int m = 0; m < 3; m++) {
        v[m] = xi[lane + m * 32];
        sum += v[m].x + v[m].y + v[m].z + v[m].w;
    }
    sum = warp_sum(sum);
    float mu = sum * (1.f / 384.f);
    float vs = 0.f;
#pragma unroll
    for (int m = 0; m < 3; m++) {
        float dx = v[m].x - mu, dy = v[m].y - mu, dz = v[m].z - mu, dw = v[m].w - mu;
        vs += dx * dx + dy * dy + dz * dz + dw * dw;
    }
    vs = warp_sum(vs);
    float rstd = rsqrtf(vs * (1.f / 384.f) + EPS_LN);
    float4* o = (float4*)(g_xc + (size_t)scatter_row(gw) * C_);
    const float4* g4 = (const float4*)g;
    const float4* b4 = (const float4*)b;
#pragma unroll
    for (int m = 0; m < 3; m++) {
        int c = lane + m * 32;
        float4 gg = g4[c], bb = b4[c], ov;
        ov.x = tf32r((v[m].x - mu) * rstd * gg.x + bb.x);
        ov.y = tf32r((v[m].y - mu) * rstd * gg.y + bb.y);
        ov.z = tf32r((v[m].z - mu) * rstd * gg.z + bb.z);
        ov.w = tf32r((v[m].w - mu) * rstd * gg.w + bb.w);
        o[c] = ov;
    }
}

__global__ void ln2_kernel(const float* __restrict__ g,
                           const float* __restrict__ b) {
    int gw   = (blockIdx.x * blockDim.x + threadIdx.x) >> 5;
    int lane = threadIdx.x & 31;
    if (gw >= L_) return;
    const float4* xi = (const float4*)(g_xres + (size_t)gw * C_);
    float4 v[3];
    float sum = 0.f;
#pragma unroll
    for (int m = 0; m < 3; m++) {
        v[m] = xi[lane + m * 32];
        sum += v[m].x + v[m].y + v[m].z + v[m].w;
    }
    sum = warp_sum(sum);
    float mu = sum * (1.f / 384.f);
    float vs = 0.f;
#pragma unroll
    for (int m = 0; m < 3; m++) {
        float dx = v[m].x - mu, dy = v[m].y - mu, dz = v[m].z - mu, dw = v[m].w - mu;
        vs += dx * dx + dy * dy + dz * dz + dw * dw;
    }
    vs = warp_sum(vs);
    float rstd = rsqrtf(vs * (1.f / 384.f) + EPS_LN);
    float4* o = (float4*)(g_ln2 + (size_t)gw * C_);
    const float4* g4 = (const float4*)g;
    const float4* b4 = (const float4*)b;
#pragma unroll
    for (int m = 0; m < 3; m++) {
        int c = lane + m * 32;
        float4 gg = g4[c], bb = b4[c], ov;
        ov.x = tf32r((v[m].x - mu) * rstd * gg.x + bb.x);
        ov.y = tf32r((v[m].y - mu) * rstd * gg.y + bb.y);
        ov.z = tf32r((v[m].z - mu) * rstd * gg.z + bb.z);
        ov.w = tf32r((v[m].w - mu) * rstd * gg.w + bb.w);
        o[c] = ov;
    }
}

/* ---------------- attention via tf32 mma + ldmatrix (R8 config) --------- */
#define KSTR 36
#define VSTR 40
#define SSTR 356
#define QSTR 36
#define NPAD 352
#define ATT2_SMEM ((NPAD*KSTR + NTOK*VSTR + 64*SSTR + 64*QSTR) * 4 + NTOK * 4)

__global__ __launch_bounds__(256, 1) void attn_mma() {
    extern __shared__ float sm[];
    float* Ks = sm;
    float* Vs = Ks + NPAD * KSTR;
    float* Ss = Vs + NTOK * VSTR;
    float* Qs = Ss + 64 * SSTR;
    int*  lab = (int*)(Qs + 64 * QSTR);

    int tid = threadIdx.x, lane = tid & 31, wid = tid >> 5;
    int win = blockIdx.x / HEADS, head = blockIdx.x % HEADS;
    const float* base = g_qkv + (size_t)win * NTOK * (3 * C_) + head * 32;

    uint32_t ks_s = (uint32_t)__cvta_generic_to_shared(Ks);
    uint32_t ss_s = (uint32_t)__cvta_generic_to_shared(Ss);
    uint32_t qs_s = (uint32_t)__cvta_generic_to_shared(Qs);

    for (int idx = tid; idx < NPAD * 32; idx += 256) {
        int n = idx >> 5, d = idx & 31;
        Ks[n * KSTR + d] = (n < NTOK) ? tf32r(base[(size_t)n * (3 * C_) + C_ + d]) : 0.f;
    }
    for (int idx = tid; idx < NTOK * 32; idx += 256) {
        int j = idx >> 5, d = idx & 31;
        Vs[j * VSTR + d] = tf32r(base[(size_t)j * (3 * C_) + 2 * C_ + d]);
    }
    int wh = win >> 3, ww = win & 7;
    for (int t = tid; t < NTOK; t += 256) {
        int lv = -1;
        if (t > 0) {
            int t0 = t - 1;
            int ts = t0 / 49, th = (t0 / 7) % 7, tw = t0 % 7;
            int hh = wh * 7 + th, wc = ww * 7 + tw;
            int ia = (ts < 4) ? 1 : 2;
            int ib = (hh < 49) ? 0 : ((hh < 53) ? 1 : 2);
            int ic = (wc < 49) ? 0 : ((wc < 53) ? 1 : 2);
            lv = ia * 9 + ib * 3 + ic;
        }
        lab[t] = lv;
    }
    __syncthreads();

    const float* bh = g_bias + (size_t)head * NWIN * NWIN;
    const int wm  = (wid & 1) * 32;
    const int wn  = (wid >> 1) * 88;
    const int wnO = (wid >> 1) * 8;

    const int r_off = (lane & 7) + ((lane >> 3) & 1) * 8;
    const int a_k4  = ((lane >> 4) & 1) * 4;
    const int b_n   = (lane & 7) + ((lane >> 4) & 1) * 8;
    const int b_k4  = ((lane >> 3) & 1) * 4;

    for (int qt = 0; qt < 6; qt++) {
        int qbase = qt * 64;
        for (int i = tid; i < 64 * 32; i += 256) {
            int m = i >> 5, d = i & 31;
            int r = qbase + m;
            float v = (r < NTOK) ? base[(size_t)r * (3 * C_) + d] * QSCALE : 0.f;
            Qs[m * QSTR + d] = tf32r(v);
        }
        __syncthreads();

        float c[2][11][4];
#pragma unroll
        for (int mt = 0; mt < 2; mt++)
#pragma unroll
            for (int nt = 0; nt < 11; nt++)
#pragma unroll
                for (int q = 0; q < 4; q++) c[mt][nt][q] = 0.f;

#pragma unroll
        for (int ks = 0; ks < 4; ks++) {
            uint32_t a[2][4], b[11][2];
#pragma unroll
            for (int mt = 0; mt < 2; mt++)
                LDSM4(a[mt][0], a[mt][1], a[mt][2], a[mt][3],
                      qs_s + ((wm + mt * 16 + r_off) * QSTR + ks * 8 + a_k4) * 4);
#pragma unroll
            for (int p = 0; p < 5; p++)
                LDSM4(b[2 * p][0], b[2 * p][1], b[2 * p + 1][0], b[2 * p + 1][1],
                      ks_s + ((wn + p * 16 + b_n) * KSTR + ks * 8 + b_k4) * 4);
            LDSM2(b[10][0], b[10][1],
                  ks_s + ((wn + 80 + (b_n & 7)) * KSTR + ks * 8 + b_k4) * 4);
#pragma unroll
            for (int nt = 0; nt < 11; nt++) {
                MMA_TF32(c[0][nt], a[0], b[nt]);
                MMA_TF32(c[1][nt], a[1], b[nt]);
            }
        }

#pragma unroll
        for (int mt = 0; mt < 2; mt++) {
            int r0 = wm + mt * 16 + (lane >> 2);
#pragma unroll
            for (int nt = 0; nt < 11; nt++) {
                int j0 = wn + nt * 8 + 2 * (lane & 3);
#pragma unroll
                for (int h = 0; h < 2; h++) {
                    int rr = r0 + h * 8;
                    int rg = qbase + rr;
                    float v0 = c[mt][nt][2 * h];
                    float v1 = c[mt][nt][2 * h + 1];
                    if (rg < NTOK && rg > 0) {
                        int lr = lab[rg];
                        if (j0 < NTOK && j0 > 0) {
                            v0 += bh[(rg - 1) * NWIN + (j0 - 1)];
                            if (lr != lab[j0]) v0 -= 100.f;
                        }
                        int j1 = j0 + 1;
                        if (j1 < NTOK) {
                            v1 += bh[(rg - 1) * NWIN + (j1 - 1)];
                            if (lr != lab[j1]) v1 -= 100.f;
                        }
                    }
                    if (j0 >= NTOK)     v0 = -1e30f;
                    if (j0 + 1 >= NTOK) v1 = -1e30f;
                    Ss[rr * SSTR + j0]     = v0;
                    Ss[rr * SSTR + j0 + 1] = v1;
                }
            }
        }
        __syncthreads();

#pragma unroll
        for (int i = 0; i < 8; i++) {
            int rr = wid * 8 + i;
            float s[11];
            float mx = -1e30f;
#pragma unroll
            for (int m = 0; m < 11; m++) {
                s[m] = Ss[rr * SSTR + lane + m * 32];
                mx = fmaxf(mx, s[m]);
            }
            mx = warp_max(mx);
            float sum = 0.f;
#pragma unroll
            for (int m = 0; m < 11; m++) {
                float e = __expf(s[m] - mx);
                s[m] = e; sum += e;
            }
            sum = warp_sum(sum);
            float inv = 1.f / sum;
#pragma unroll
            for (int m = 0; m < 11; m++)
                Ss[rr * SSTR + lane + m * 32] = tf32r(s[m] * inv);
        }
        __syncthreads();

        float o[2][4] = {};
#pragma unroll 4
        for (int kt = 0; kt < 43; kt++) {
            uint32_t b[2];
            int kr = kt * 8 + (lane & 3);
            int bc = wnO + (lane >> 2);
            b[0] = __float_as_uint(Vs[(kr    ) * VSTR + bc]);
            b[1] = __float_as_uint(Vs[(kr + 4) * VSTR + bc]);
#pragma unroll
            for (int mt = 0; mt < 2; mt++) {
                uint32_t a[4];
                LDSM4(a[0], a[1], a[2], a[3],
                      ss_s + ((wm + mt * 16 + r_off) * SSTR + kt * 8 + a_k4) * 4);
                MMA_TF32(o[mt], a, b);
            }
        }
#pragma unroll
        for (int mt = 0; mt < 2; mt++)
#pragma unroll
            for (int h = 0; h < 2; h++) {
                int rr = qbase + wm + mt * 16 + (lane >> 2) + h * 8;
                if (rr < NTOK) {
                    float2 v;
                    v.x = tf32r(o[mt][2 * h]);
                    v.y = tf32r(o[mt][2 * h + 1]);
                    *(float2*)&g_attnout[((size_t)win * NTOK + rr) * C_ +
                                         head * 32 + wnO + 2 * (lane & 3)] = v;
                }
            }
        __syncthreads();
    }
}

/* ---------------- TF32 tensor-core GEMM (R8 config: 128x128, 3-stage) --- */
#define ASTR 36
#define ABUF (128*ASTR)
#define STG  (2*ABUF)
#define GEMM_SMEM_BYTES (3 * STG * 4)   /* 110592 */

template<int EPI, int CVT>
__global__ __launch_bounds__(256, 2) void gemm_tc(const float* __restrict__ A,
                                                  const float* __restrict__ Bt,
                                                  const float* __restrict__ bias,
                                                  const float* __restrict__ res,
                                                  float* __restrict__ Cd,
                                                  float* __restrict__ gtout,
                                                  int Mstore, int N, int K) {
    extern __shared__ float sm[];
    const int tid = threadIdx.x, lane = tid & 31, wid = tid >> 5;
    const int bm = blockIdx.y * 128, bn = blockIdx.x * 128;
    const int wm = (wid & 1) * 64, wn = (wid >> 1) * 32;
    const uint32_t sm_s = (uint32_t)__cvta_generic_to_shared(sm);

    const int r_off = (lane & 7) + ((lane >> 3) & 1) * 8;
    const int a_k4  = ((lane >> 4) & 1) * 4;
    const int b_n   = (lane & 7) + ((lane >> 4) & 1) * 8;
    const int b_k4  = ((lane >> 3) & 1) * 4;

    float c[4][4][4];
#pragma unroll
    for (int i = 0; i < 4; i++)
#pragma unroll
        for (int j = 0; j < 4; j++)
#pragma unroll
            for (int k = 0; k < 4; k++) c[i][j][k] = 0.f;

    const int NK = K >> 5;

    auto issue = [&](int kt) {
        int p = kt % 3;
        float* As = sm + p * STG;
        float* Bs = As + ABUF;
        const float* Ag = A  + (size_t)bm * K + kt * 32;
        const float* Bg = Bt + (size_t)bn * K + kt * 32;
#pragma unroll
        for (int i = 0; i < 4; i++) {
            int idx = tid + i * 256;
            int r = idx >> 3, c4 = (idx & 7) * 4;
            cpa16(As + r * ASTR + c4, Ag + (size_t)r * K + c4);
        }
#pragma unroll
        for (int i = 0; i < 4; i++) {
            int idx = tid + i * 256;
            int r = idx >> 3, c4 = (idx & 7) * 4;
            cpa16(Bs + r * ASTR + c4, Bg + (size_t)r * K + c4);
        }
        asm volatile("cp.async.commit_group;\n");
    };

    issue(0);
    if (NK > 1) issue(1);

    for (int kt = 0; kt < NK; kt++) {
        if (kt + 1 < NK)
            asm volatile("cp.async.wait_group 1;\n");
        else
            asm volatile("cp.async.wait_group 0;\n");
        __syncthreads();
        if (kt + 2 < NK) issue(kt + 2);

        const int p = kt % 3;
        const uint32_t as_s = sm_s + p * STG * 4;
        const uint32_t bs_s = as_s + ABUF * 4;
#pragma unroll
        for (int ks = 0; ks < 4; ks++) {
            uint32_t a[4][4], b[4][2];
#pragma unroll
            for (int mt = 0; mt < 4; mt++)
                LDSM4(a[mt][0], a[mt][1], a[mt][2], a[mt][3],
                      as_s + ((wm + mt * 16 + r_off) * ASTR + ks * 8 + a_k4) * 4);
#pragma unroll
            for (int pp = 0; pp < 2; pp++)
                LDSM4(b[2 * pp][0], b[2 * pp][1], b[2 * pp + 1][0], b[2 * pp + 1][1],
                      bs_s + ((wn + pp * 16 + b_n) * ASTR + ks * 8 + b_k4) * 4);
#pragma unroll
            for (int mt = 0; mt < 4; mt++)
#pragma unroll
                for (int nt = 0; nt < 4; nt++)
                    MMA_TF32(c[mt][nt], a[mt], b[nt]);
        }
    }

    if (EPI == 3) {
#pragma unroll
        for (int mt = 0; mt < 4; mt++)
#pragma unroll
            for (int h = 0; h < 2; h++) {
                int row = bm + wm + mt * 16 + (lane >> 2) + h * 8;
                int win = row / NTOK, t = row % NTOK;
                float* dst;
                const float* xsrc = nullptr;
                if (t == 0) {
                    dst = gtout + (size_t)win * C_;
                } else {
                    int l = unscatter_l(win, t);
                    dst  = Cd  + (size_t)l * C_;
                    xsrc = res + (size_t)l * C_;
                }
#pragma unroll
                for (int nt = 0; nt < 4; nt++) {
                    int col = bn + wn + nt * 8 + 2 * (lane & 3);
                    float2 bb = *(const float2*)&bias[col];
                    float2 v;
                    v.x = c[mt][nt][2 * h]     + bb.x;
                    v.y = c[mt][nt][2 * h + 1] + bb.y;
                    if (xsrc) {
                        float2 rv = *(const float2*)&xsrc[col];
                        v.x += rv.x; v.y += rv.y;
                    }
                    *(float2*)&dst[col] = v;
                }
            }
    } else {
#pragma unroll
        for (int nt = 0; nt < 4; nt++) {
            int col = bn + wn + nt * 8 + 2 * (lane & 3);
            float2 bb = *(const float2*)&bias[col];
#pragma unroll
            for (int mt = 0; mt < 4; mt++) {
                int row0 = bm + wm + mt * 16 + (lane >> 2);
#pragma unroll
                for (int h = 0; h < 2; h++) {
                    int row = row0 + h * 8;
                    if (row < Mstore) {
                        float2 v;
                        v.x = c[mt][nt][2 * h]     + bb.x;
                        v.y = c[mt][nt][2 * h + 1] + bb.y;
                        if (EPI == 1) { v.x = gelu_f(v.x); v.y = gelu_f(v.y); }
                        size_t o = (size_t)row * N + col;
                        if (EPI == 2) {
                            float2 rv = *(const float2*)&res[o];
                            v.x += rv.x; v.y += rv.y;
                        }
                        if (CVT) { v.x = tf32r(v.x); v.y = tf32r(v.y); }
                        *(float2*)&Cd[o] = v;
                    }
                }
            }
        }
    }
}

/* ---------------- launch ------------------------------------------------ */
extern "C" void kernel_launch(void* const* d_in, const int* in_sizes, int n_in,
                              void* d_out, int out_size) {
    const float* x     = (const float*)d_in[0];
    const float* gt    = (const float*)d_in[1];
    const float* n1g   = (const float*)d_in[2];
    const float* n1b   = (const float*)d_in[3];
    const float* qkvw  = (const float*)d_in[4];
    const float* qkvb  = (const float*)d_in[5];
    const float* btab  = (const float*)d_in[6];
    const float* projw = (const float*)d_in[7];
    const float* projb = (const float*)d_in[8];
    const float* n2g   = (const float*)d_in[9];
    const float* n2b   = (const float*)d_in[10];
    const float* fc1w  = (const float*)d_in[11];
    const float* fc1b  = (const float*)d_in[12];
    const float* fc2w  = (const float*)d_in[13];
    const float* fc2b  = (const float*)d_in[14];
    float* out = (float*)d_out;

    float *xc, *qkv, *ao, *xres, *ln2b, *hb;
    float *wq, *wp, *w1, *w2;
    cudaGetSymbolAddress((void**)&xc,   g_xc);
    cudaGetSymbolAddress((void**)&qkv,  g_qkv);
    cudaGetSymbolAddress((void**)&ao,   g_attnout);
    cudaGetSymbolAddress((void**)&xres, g_xres);
    cudaGetSymbolAddress((void**)&ln2b, g_ln2);
    cudaGetSymbolAddress((void**)&hb,   g_hid);
    cudaGetSymbolAddress((void**)&wq,   g_wqkv);
    cudaGetSymbolAddress((void**)&wp,   g_wproj);
    cudaGetSymbolAddress((void**)&w1,   g_wfc1);
    cudaGetSymbolAddress((void**)&w2,   g_wfc2);

    cudaFuncSetAttribute(attn_mma,
                         cudaFuncAttributeMaxDynamicSharedMemorySize,
                         ATT2_SMEM);
    cudaFuncSetAttribute(gemm_tc<0, 0>,
                         cudaFuncAttributeMaxDynamicSharedMemorySize,
                         GEMM_SMEM_BYTES);
    cudaFuncSetAttribute(gemm_tc<1, 1>,
                         cudaFuncAttributeMaxDynamicSharedMemorySize,
                         GEMM_SMEM_BYTES);
    cudaFuncSetAttribute(gemm_tc<2, 0>,
                         cudaFuncAttributeMaxDynamicSharedMemorySize,
                         GEMM_SMEM_BYTES);
    cudaFuncSetAttribute(gemm_tc<3, 0>,
                         cudaFuncAttributeMaxDynamicSharedMemorySize,
                         GEMM_SMEM_BYTES);

    /* launches 0-4; qkv GEMM is capture index 5 for ncu (-s 5) */
    dim3 tb(32, 8);
    wtrans_pair<<<dim3((3 * C_) / 32, C_ / 32, 2), tb>>>(
        qkvw, wq, C_, 3 * C_, projw, wp, C_, C_);
    wtrans_pair<<<dim3(HID / 32, HID / 32, 2), tb>>>(
        fc1w, w1, C_, HID, fc2w, w2, HID, C_);
    bias_pre   <<<(NWIN * NWIN + 255) / 256, 256>>>(btab);
    gt_copy    <<<(NW * C_ + 255) / 256, 256>>>(gt);
    ln1_scatter<<<L_ / 8, 256>>>(x, n1g, n1b);

    gemm_tc<0, 0><<<dim3((3 * C_) / 128, M1 / 128), 256, GEMM_SMEM_BYTES>>>(
        xc, wq, qkvb, nullptr, qkv, nullptr, M1, 3 * C_, C_);

    attn_mma<<<NW * HEADS, 256, ATT2_SMEM>>>();

    gemm_tc<3, 0><<<dim3(C_ / 128, M1 / 128), 256, GEMM_SMEM_BYTES>>>(
        ao, wp, projb, x, xres, out + (size_t)L_ * C_, M1, C_, C_);

    ln2_kernel<<<L_ / 8, 256>>>(n2g, n2b);

    gemm_tc<1, 1><<<dim3(HID / 128, M1 / 128), 256, GEMM_SMEM_BYTES>>>(
        ln2b, w1, fc1b, nullptr, hb, nullptr, M1, HID, C_);

    gemm_tc<2, 0><<<dim3(C_ / 128, M1 / 128), 256, GEMM_SMEM_BYTES>>>(
        hb, w2, fc2b, xres, out, nullptr, L_, C_, HID);
}

// round 12
// speedup vs baseline: 1.8215x; 1.2208x over previous
#include <cuda_runtime.h>
#include <cuda_fp16.h>
#include <math.h>
#include <stdint.h>

#define S_ 7
#define H_ 56
#define W_ 56
#define WS 7
#define C_ 384
#define HEADS 12
#define NW 64
#define NTOK 344
#define NWIN 343
#define L_ (S_*H_*W_)          /* 21952 */
#define M1 (NW*NTOK)           /* 22016 */
#define HID 1536
#define EPS_LN 1e-5f
#define QSCALE 0.17677669529663687f  /* 32^-0.5 */

/* ---------------- scratch (static device globals; no allocation) -------- */
__device__ __half g_xc     [(size_t)M1 * C_];      /* fp16 LN1 out          */
__device__ float  g_qkv    [(size_t)M1 * 3 * C_];  /* fp32 qkv              */
__device__ __half g_attnout[(size_t)M1 * C_];      /* fp16 attn out         */
__device__ float  g_xres   [(size_t)L_ * C_];
__device__ __half g_ln2    [(size_t)M1 * C_];      /* fp16, tail zeros      */
__device__ __half g_hid    [(size_t)M1 * HID];     /* fp16 gelu out         */
__device__ float  g_bias   [(size_t)HEADS * NWIN * NWIN];
__device__ __half g_wqkv   [(size_t)C_ * 3 * C_];  /* W^T [N][K] fp16       */
__device__ __half g_wproj  [(size_t)C_ * C_];
__device__ __half g_wfc1   [(size_t)C_ * HID];
__device__ __half g_wfc2   [(size_t)HID * C_];

/* ---------------- helpers ---------------------------------------------- */
__device__ __forceinline__ float warp_sum(float v) {
    v += __shfl_xor_sync(0xffffffffu, v, 16);
    v += __shfl_xor_sync(0xffffffffu, v, 8);
    v += __shfl_xor_sync(0xffffffffu, v, 4);
    v += __shfl_xor_sync(0xffffffffu, v, 2);
    v += __shfl_xor_sync(0xffffffffu, v, 1);
    return v;
}
__device__ __forceinline__ float warp_max(float v) {
    v = fmaxf(v, __shfl_xor_sync(0xffffffffu, v, 16));
    v = fmaxf(v, __shfl_xor_sync(0xffffffffu, v, 8));
    v = fmaxf(v, __shfl_xor_sync(0xffffffffu, v, 4));
    v = fmaxf(v, __shfl_xor_sync(0xffffffffu, v, 2));
    v = fmaxf(v, __shfl_xor_sync(0xffffffffu, v, 1));
    return v;
}
__device__ __forceinline__ float gelu_f(float v) {
    return 0.5f * v * (1.f + erff(v * 0.7071067811865475f));
}
__device__ __forceinline__ float tf32r(float x) {
    uint32_t u;
    asm("cvt.rna.tf32.f32 %0, %1;" : "=r"(u) : "f"(x));
    return __uint_as_float(u);
}
__device__ __forceinline__ void cpa16h(__half* s, const __half* g) {
    uint32_t sa = (uint32_t)__cvta_generic_to_shared(s);
    asm volatile("cp.async.cg.shared.global [%0], [%1], 16;\n" :: "r"(sa), "l"(g));
}
#define MMA_TF32(c4, a4, b2)                                                   \
    asm volatile(                                                              \
        "mma.sync.aligned.m16n8k8.row.col.f32.tf32.tf32.f32 "                  \
        "{%0,%1,%2,%3}, {%4,%5,%6,%7}, {%8,%9}, {%0,%1,%2,%3};\n"              \
        : "+f"((c4)[0]), "+f"((c4)[1]), "+f"((c4)[2]), "+f"((c4)[3])           \
        : "r"((a4)[0]), "r"((a4)[1]), "r"((a4)[2]), "r"((a4)[3]),              \
          "r"((b2)[0]), "r"((b2)[1]))
#define MMA_F16(c4, a4, b2)                                                    \
    asm volatile(                                                              \
        "mma.sync.aligned.m16n8k16.row.col.f32.f16.f16.f32 "                   \
        "{%0,%1,%2,%3}, {%4,%5,%6,%7}, {%8,%9}, {%0,%1,%2,%3};\n"              \
        : "+f"((c4)[0]), "+f"((c4)[1]), "+f"((c4)[2]), "+f"((c4)[3])           \
        : "r"((a4)[0]), "r"((a4)[1]), "r"((a4)[2]), "r"((a4)[3]),              \
          "r"((b2)[0]), "r"((b2)[1]))
#define LDSM4(r0, r1, r2, r3, addr)                                            \
    asm volatile("ldmatrix.sync.aligned.m8n8.x4.shared.b16 {%0,%1,%2,%3}, [%4];" \
                 : "=r"(r0), "=r"(r1), "=r"(r2), "=r"(r3) : "r"(addr))
#define LDSM2(r0, r1, addr)                                                    \
    asm volatile("ldmatrix.sync.aligned.m8n8.x2.shared.b16 {%0,%1}, [%2];"     \
                 : "=r"(r0), "=r"(r1) : "r"(addr))

__device__ __forceinline__ int scatter_row(int l) {
    int s   = l / (H_ * W_);
    int rem = l % (H_ * W_);
    int h   = rem / W_;
    int w   = rem % W_;
    int s2 = (s >= 3) ? s - 3 : s + 4;
    int h2 = (h >= 3) ? h - 3 : h + 53;
    int w2 = (w >= 3) ? w - 3 : w + 53;
    int win = (h2 / WS) * 8 + (w2 / WS);
    int t   = s2 * 49 + (h2 % WS) * 7 + (w2 % WS);
    return win * NTOK + 1 + t;
}
__device__ __forceinline__ int unscatter_l(int win, int t) {
    int t0 = t - 1;
    int ts = t0 / 49, th = (t0 / 7) % 7, tw = t0 % 7;
    int wh = win >> 3, ww = win & 7;
    int h2 = wh * 7 + th, w2 = ww * 7 + tw;
    int s  = (ts <= 3) ? ts + 3 : ts - 4;
    int hh = (h2 <= 52) ? h2 + 3 : h2 - 53;
    int wo = (w2 <= 52) ? w2 + 3 : w2 - 53;
    return (s * H_ + hh) * W_ + wo;
}

/* ---------------- small kernels ----------------------------------------- */
__global__ void wtrans_pair(const float* __restrict__ w0, __half* __restrict__ o0,
                            int K0, int N0,
                            const float* __restrict__ w1, __half* __restrict__ o1,
                            int K1, int N1) {
    __shared__ float t[32][33];
    const float* w = blockIdx.z ? w1 : w0;
    __half*      o = blockIdx.z ? o1 : o0;
    int K = blockIdx.z ? K1 : K0;
    int N = blockIdx.z ? N1 : N0;
    int bn = blockIdx.x * 32, bk = blockIdx.y * 32;
    if (bn >= N || bk >= K) return;
    int tx = threadIdx.x, ty = threadIdx.y;
#pragma unroll
    for (int i = 0; i < 32; i += 8)
        t[ty + i][tx] = w[(size_t)(bk + ty + i) * N + bn + tx];
    __syncthreads();
#pragma unroll
    for (int i = 0; i < 32; i += 8)
        o[(size_t)(bn + ty + i) * K + bk + tx] = __float2half_rn(t[tx][ty + i]);
}

__global__ void bias_pre(const float* __restrict__ bt) {
    int idx = blockIdx.x * blockDim.x + threadIdx.x;
    if (idx >= NWIN * NWIN) return;
    int i = idx / NWIN, j = idx % NWIN;
    int si = i / 49, hi = (i / 7) % 7, wi = i % 7;
    int sj = j / 49, hj = (j / 7) % 7, wj = j % 7;
    int r = (si - sj + 6) * 20 + (hi - hj + 6) * 13 + (wi - wj + 6);
#pragma unroll
    for (int h = 0; h < HEADS; h++)
        g_bias[(size_t)h * NWIN * NWIN + idx] = bt[r * HEADS + h];
}

__global__ void gt_copy(const float* __restrict__ gt) {
    int idx = blockIdx.x * blockDim.x + threadIdx.x;
    if (idx >= NW * C_) return;
    int w = idx / C_, c = idx % C_;
    g_xc[((size_t)w * NTOK) * C_ + c] = __float2half_rn(gt[idx]);
}

/* LN kernels: one warp per token, float4 loads, fp16 stores */
__global__ void ln1_scatter(const float* __restrict__ x,
                            const float* __restrict__ g,
                            const float* __restrict__ b) {
    int gw   = (blockIdx.x * blockDim.x + threadIdx.x) >> 5;
    int lane = threadIdx.x & 31;
    if (gw >= L_) return;
    const float4* xi = (const float4*)(x + (size_t)gw * C_);
    float4 v[3];
    float sum = 0.f;
#pragma unroll
    for (int m = 0; m < 3; m++) {
        v[m] = xi[lane + m * 32];
        sum += v[m].x + v[m].y + v[m].z + v[m].w;
    }
    sum = warp_sum(sum);
    float mu = sum * (1.f / 384.f);
    float vs = 0.f;
#pragma unroll
    for (int m = 0; m < 3; m++) {
        float dx = v[m].x - mu, dy = v[m].y - mu, dz = v[m].z - mu, dw = v[m].w - mu;
        vs += dx * dx + dy * dy + dz * dz + dw * dw;
    }
    vs = warp_sum(vs);
    float rstd = rsqrtf(vs * (1.f / 384.f) + EPS_LN);
    __half* orow = g_xc + (size_t)scatter_row(gw) * C_;
    const float4* g4 = (const float4*)g;
    const float4* b4 = (const float4*)b;
#pragma unroll
    for (int m = 0; m < 3; m++) {
        int c = lane + m * 32;
        float4 gg = g4[c], bb = b4[c];
        __half2 h0 = __floats2half2_rn((v[m].x - mu) * rstd * gg.x + bb.x,
                                       (v[m].y - mu) * rstd * gg.y + bb.y);
        __half2 h1 = __floats2half2_rn((v[m].z - mu) * rstd * gg.z + bb.z,
                                       (v[m].w - mu) * rstd * gg.w + bb.w);
        uint2 pk;
        pk.x = *(uint32_t*)&h0;
        pk.y = *(uint32_t*)&h1;
        *(uint2*)&orow[c * 4] = pk;
    }
}

__global__ void ln2_kernel(const float* __restrict__ g,
                           const float* __restrict__ b) {
    int gw   = (blockIdx.x * blockDim.x + threadIdx.x) >> 5;
    int lane = threadIdx.x & 31;
    if (gw >= L_) return;
    const float4* xi = (const float4*)(g_xres + (size_t)gw * C_);
    float4 v[3];
    float sum = 0.f;
#pragma unroll
    for (int m = 0; m < 3; m++) {
        v[m] = xi[lane + m * 32];
        sum += v[m].x + v[m].y + v[m].z + v[m].w;
    }
    sum = warp_sum(sum);
    float mu = sum * (1.f / 384.f);
    float vs = 0.f;
#pragma unroll
    for (int m = 0; m < 3; m++) {
        float dx = v[m].x - mu, dy = v[m].y - mu, dz = v[m].z - mu, dw = v[m].w - mu;
        vs += dx * dx + dy * dy + dz * dz + dw * dw;
    }
    vs = warp_sum(vs);
    float rstd = rsqrtf(vs * (1.f / 384.f) + EPS_LN);
    __half* orow = g_ln2 + (size_t)gw * C_;
    const float4* g4 = (const float4*)g;
    const float4* b4 = (const float4*)b;
#pragma unroll
    for (int m = 0; m < 3; m++) {
        int c = lane + m * 32;
        float4 gg = g4[c], bb = b4[c];
        __half2 h0 = __floats2half2_rn((v[m].x - mu) * rstd * gg.x + bb.x,
                                       (v[m].y - mu) * rstd * gg.y + bb.y);
        __half2 h1 = __floats2half2_rn((v[m].z - mu) * rstd * gg.z + bb.z,
                                       (v[m].w - mu) * rstd * gg.w + bb.w);
        uint2 pk;
        pk.x = *(uint32_t*)&h0;
        pk.y = *(uint32_t*)&h1;
        *(uint2*)&orow[c * 4] = pk;
    }
}

/* ---------------- attention via tf32 mma + ldmatrix (R8 config) --------- */
#define KSTR 36
#define VSTR 40
#define SSTR 356
#define QSTR 36
#define NPAD 352
#define ATT2_SMEM ((NPAD*KSTR + NTOK*VSTR + 64*SSTR + 64*QSTR) * 4 + NTOK * 4)

__global__ __launch_bounds__(256, 1) void attn_mma() {
    extern __shared__ float sm[];
    float* Ks = sm;
    float* Vs = Ks + NPAD * KSTR;
    float* Ss = Vs + NTOK * VSTR;
    float* Qs = Ss + 64 * SSTR;
    int*  lab = (int*)(Qs + 64 * QSTR);

    int tid = threadIdx.x, lane = tid & 31, wid = tid >> 5;
    int win = blockIdx.x / HEADS, head = blockIdx.x % HEADS;
    const float* base = g_qkv + (size_t)win * NTOK * (3 * C_) + head * 32;

    uint32_t ks_s = (uint32_t)__cvta_generic_to_shared(Ks);
    uint32_t ss_s = (uint32_t)__cvta_generic_to_shared(Ss);
    uint32_t qs_s = (uint32_t)__cvta_generic_to_shared(Qs);

    for (int idx = tid; idx < NPAD * 32; idx += 256) {
        int n = idx >> 5, d = idx & 31;
        Ks[n * KSTR + d] = (n < NTOK) ? tf32r(base[(size_t)n * (3 * C_) + C_ + d]) : 0.f;
    }
    for (int idx = tid; idx < NTOK * 32; idx += 256) {
        int j = idx >> 5, d = idx & 31;
        Vs[j * VSTR + d] = tf32r(base[(size_t)j * (3 * C_) + 2 * C_ + d]);
    }
    int wh = win >> 3, ww = win & 7;
    for (int t = tid; t < NTOK; t += 256) {
        int lv = -1;
        if (t > 0) {
            int t0 = t - 1;
            int ts = t0 / 49, th = (t0 / 7) % 7, tw = t0 % 7;
            int hh = wh * 7 + th, wc = ww * 7 + tw;
            int ia = (ts < 4) ? 1 : 2;
            int ib = (hh < 49) ? 0 : ((hh < 53) ? 1 : 2);
            int ic = (wc < 49) ? 0 : ((wc < 53) ? 1 : 2);
            lv = ia * 9 + ib * 3 + ic;
        }
        lab[t] = lv;
    }
    __syncthreads();

    const float* bh = g_bias + (size_t)head * NWIN * NWIN;
    const int wm  = (wid & 1) * 32;
    const int wn  = (wid >> 1) * 88;
    const int wnO = (wid >> 1) * 8;

    const int r_off = (lane & 7) + ((lane >> 3) & 1) * 8;
    const int a_k4  = ((lane >> 4) & 1) * 4;
    const int b_n   = (lane & 7) + ((lane >> 4) & 1) * 8;
    const int b_k4  = ((lane >> 3) & 1) * 4;

    for (int qt = 0; qt < 6; qt++) {
        int qbase = qt * 64;
        for (int i = tid; i < 64 * 32; i += 256) {
            int m = i >> 5, d = i & 31;
            int r = qbase + m;
            float v = (r < NTOK) ? base[(size_t)r * (3 * C_) + d] * QSCALE : 0.f;
            Qs[m * QSTR + d] = tf32r(v);
        }
        __syncthreads();

        float c[2][11][4];
#pragma unroll
        for (int mt = 0; mt < 2; mt++)
#pragma unroll
            for (int nt = 0; nt < 11; nt++)
#pragma unroll
                for (int q = 0; q < 4; q++) c[mt][nt][q] = 0.f;

#pragma unroll
        for (int ks = 0; ks < 4; ks++) {
            uint32_t a[2][4], b[11][2];
#pragma unroll
            for (int mt = 0; mt < 2; mt++)
                LDSM4(a[mt][0], a[mt][1], a[mt][2], a[mt][3],
                      qs_s + ((wm + mt * 16 + r_off) * QSTR + ks * 8 + a_k4) * 4);
#pragma unroll
            for (int p = 0; p < 5; p++)
                LDSM4(b[2 * p][0], b[2 * p][1], b[2 * p + 1][0], b[2 * p + 1][1],
                      ks_s + ((wn + p * 16 + b_n) * KSTR + ks * 8 + b_k4) * 4);
            LDSM2(b[10][0], b[10][1],
                  ks_s + ((wn + 80 + (b_n & 7)) * KSTR + ks * 8 + b_k4) * 4);
#pragma unroll
            for (int nt = 0; nt < 11; nt++) {
                MMA_TF32(c[0][nt], a[0], b[nt]);
                MMA_TF32(c[1][nt], a[1], b[nt]);
            }
        }

#pragma unroll
        for (int mt = 0; mt < 2; mt++) {
            int r0 = wm + mt * 16 + (lane >> 2);
#pragma unroll
            for (int nt = 0; nt < 11; nt++) {
                int j0 = wn + nt * 8 + 2 * (lane & 3);
#pragma unroll
                for (int h = 0; h < 2; h++) {
                    int rr = r0 + h * 8;
                    int rg = qbase + rr;
                    float v0 = c[mt][nt][2 * h];
                    float v1 = c[mt][nt][2 * h + 1];
                    if (rg < NTOK && rg > 0) {
                        int lr = lab[rg];
                        if (j0 < NTOK && j0 > 0) {
                            v0 += bh[(rg - 1) * NWIN + (j0 - 1)];
                            if (lr != lab[j0]) v0 -= 100.f;
                        }
                        int j1 = j0 + 1;
                        if (j1 < NTOK) {
                            v1 += bh[(rg - 1) * NWIN + (j1 - 1)];
                            if (lr != lab[j1]) v1 -= 100.f;
                        }
                    }
                    if (j0 >= NTOK)     v0 = -1e30f;
                    if (j0 + 1 >= NTOK) v1 = -1e30f;
                    Ss[rr * SSTR + j0]     = v0;
                    Ss[rr * SSTR + j0 + 1] = v1;
                }
            }
        }
        __syncthreads();

#pragma unroll
        for (int i = 0; i < 8; i++) {
            int rr = wid * 8 + i;
            float s[11];
            float mx = -1e30f;
#pragma unroll
            for (int m = 0; m < 11; m++) {
                s[m] = Ss[rr * SSTR + lane + m * 32];
                mx = fmaxf(mx, s[m]);
            }
            mx = warp_max(mx);
            float sum = 0.f;
#pragma unroll
            for (int m = 0; m < 11; m++) {
                float e = __expf(s[m] - mx);
                s[m] = e; sum += e;
            }
            sum = warp_sum(sum);
            float inv = 1.f / sum;
#pragma unroll
            for (int m = 0; m < 11; m++)
                Ss[rr * SSTR + lane + m * 32] = tf32r(s[m] * inv);
        }
        __syncthreads();

        float o[2][4] = {};
#pragma unroll 4
        for (int kt = 0; kt < 43; kt++) {
            uint32_t b[2];
            int kr = kt * 8 + (lane & 3);
            int bc = wnO + (lane >> 2);
            b[0] = __float_as_uint(Vs[(kr    ) * VSTR + bc]);
            b[1] = __float_as_uint(Vs[(kr + 4) * VSTR + bc]);
#pragma unroll
            for (int mt = 0; mt < 2; mt++) {
                uint32_t a[4];
                LDSM4(a[0], a[1], a[2], a[3],
                      ss_s + ((wm + mt * 16 + r_off) * SSTR + kt * 8 + a_k4) * 4);
                MMA_TF32(o[mt], a, b);
            }
        }
#pragma unroll
        for (int mt = 0; mt < 2; mt++)
#pragma unroll
            for (int h = 0; h < 2; h++) {
                int rr = qbase + wm + mt * 16 + (lane >> 2) + h * 8;
                if (rr < NTOK) {
                    __half2 hv = __floats2half2_rn(o[mt][2 * h], o[mt][2 * h + 1]);
                    *(__half2*)&g_attnout[((size_t)win * NTOK + rr) * C_ +
                                          head * 32 + wnO + 2 * (lane & 3)] = hv;
                }
            }
        __syncthreads();
    }
}

/* ---------------- FP16 tensor-core GEMM (128x128, 3-stage, ldmatrix) ---- */
/* A [M][K] fp16 row-major; B = W^T [N][K] fp16 (n-major).
   smem rows: 32 fp16 + pad -> ASTR=40 halfs (80B, conflict-free ldmatrix).
   EPI: 0 none->float Cd, 1 gelu->half Cdh, 2 +res->float Cd,
        3 swin-unscatter->float.                                            */
#define ASTR 40
#define ABUF (128*ASTR)          /* halfs */
#define STG  (2*ABUF)
#define GEMM_SMEM_BYTES (3 * STG * 2)   /* 61440 */

template<int EPI>
__global__ __launch_bounds__(256, 2) void gemm_tc(const __half* __restrict__ A,
                                                  const __half* __restrict__ Bt,
                                                  const float* __restrict__ bias,
                                                  const float* __restrict__ res,
                                                  float* __restrict__ Cd,
                                                  __half* __restrict__ Cdh,
                                                  float* __restrict__ gtout,
                                                  int Mstore, int N, int K) {
    extern __shared__ float sm[];
    __half* smh = (__half*)sm;
    const int tid = threadIdx.x, lane = tid & 31, wid = tid >> 5;
    const int bm = blockIdx.y * 128, bn = blockIdx.x * 128;
    const int wm = (wid & 1) * 64, wn = (wid >> 1) * 32;
    const uint32_t sm_s = (uint32_t)__cvta_generic_to_shared(smh);

    const int r_off = (lane & 7) + ((lane >> 3) & 1) * 8;
    const int a_hi  = ((lane >> 4) & 1) * 16;   /* byte offset */
    const int b_n   = (lane & 7) + ((lane >> 4) & 1) * 8;
    const int b_hi  = ((lane >> 3) & 1) * 16;   /* byte offset */

    float c[4][4][4];
#pragma unroll
    for (int i = 0; i < 4; i++)
#pragma unroll
        for (int j = 0; j < 4; j++)
#pragma unroll
            for (int k = 0; k < 4; k++) c[i][j][k] = 0.f;

    const int NK = K >> 5;

    auto issue = [&](int kt) {
        int p = kt % 3;
        __half* As = smh + p * STG;
        __half* Bs = As + ABUF;
        const __half* Ag = A  + (size_t)bm * K + kt * 32;
        const __half* Bg = Bt + (size_t)bn * K + kt * 32;
        /* 128 rows x 64B = 512 chunks of 16B; 2 per thread, each side */
#pragma unroll
        for (int i = 0; i < 2; i++) {
            int idx = tid + i * 256;
            int r = idx >> 2, c8 = (idx & 3) * 8;
            cpa16h(As + r * ASTR + c8, Ag + (size_t)r * K + c8);
        }
#pragma unroll
        for (int i = 0; i < 2; i++) {
            int idx = tid + i * 256;
            int r = idx >> 2, c8 = (idx & 3) * 8;
            cpa16h(Bs + r * ASTR + c8, Bg + (size_t)r * K + c8);
        }
        asm volatile("cp.async.commit_group;\n");
    };

    issue(0);
    if (NK > 1) issue(1);

    for (int kt = 0; kt < NK; kt++) {
        if (kt + 1 < NK)
            asm volatile("cp.async.wait_group 1;\n");
        else
            asm volatile("cp.async.wait_group 0;\n");
        __syncthreads();
        if (kt + 2 < NK) issue(kt + 2);

        const int p = kt % 3;
        const uint32_t as_s = sm_s + p * STG * 2;
        const uint32_t bs_s = as_s + ABUF * 2;
#pragma unroll
        for (int ks = 0; ks < 2; ks++) {
            uint32_t a[4][4], b[4][2];
#pragma unroll
            for (int mt = 0; mt < 4; mt++)
                LDSM4(a[mt][0], a[mt][1], a[mt][2], a[mt][3],
                      as_s + ((wm + mt * 16 + r_off) * ASTR + ks * 16) * 2 + a_hi);
#pragma unroll
            for (int pp = 0; pp < 2; pp++)
                LDSM4(b[2 * pp][0], b[2 * pp][1], b[2 * pp + 1][0], b[2 * pp + 1][1],
                      bs_s + ((wn + pp * 16 + b_n) * ASTR + ks * 16) * 2 + b_hi);
#pragma unroll
            for (int mt = 0; mt < 4; mt++)
#pragma unroll
                for (int nt = 0; nt < 4; nt++)
                    MMA_F16(c[mt][nt], a[mt], b[nt]);
        }
    }

    if (EPI == 3) {
#pragma unroll
        for (int mt = 0; mt < 4; mt++)
#pragma unroll
            for (int h = 0; h < 2; h++) {
                int row = bm + wm + mt * 16 + (lane >> 2) + h * 8;
                int win = row / NTOK, t = row % NTOK;
                float* dst;
                const float* xsrc = nullptr;
                if (t == 0) {
                    dst = gtout + (size_t)win * C_;
                } else {
                    int l = unscatter_l(win, t);
                    dst  = Cd  + (size_t)l * C_;
                    xsrc = res + (size_t)l * C_;
                }
#pragma unroll
                for (int nt = 0; nt < 4; nt++) {
                    int col = bn + wn + nt * 8 + 2 * (lane & 3);
                    float2 bb = *(const float2*)&bias[col];
                    float2 v;
                    v.x = c[mt][nt][2 * h]     + bb.x;
                    v.y = c[mt][nt][2 * h + 1] + bb.y;
                    if (xsrc) {
                        float2 rv = *(const float2*)&xsrc[col];
                        v.x += rv.x; v.y += rv.y;
                    }
                    *(float2*)&dst[col] = v;
                }
            }
    } else {
#pragma unroll
        for (int nt = 0; nt < 4; nt++) {
            int col = bn + wn + nt * 8 + 2 * (lane & 3);
            float2 bb = *(const float2*)&bias[col];
#pragma unroll
            for (int mt = 0; mt < 4; mt++) {
                int row0 = bm + wm + mt * 16 + (lane >> 2);
#pragma unroll
                for (int h = 0; h < 2; h++) {
                    int row = row0 + h * 8;
                    if (row < Mstore) {
                        float2 v;
                        v.x = c[mt][nt][2 * h]     + bb.x;
                        v.y = c[mt][nt][2 * h + 1] + bb.y;
                        size_t o = (size_t)row * N + col;
                        if (EPI == 1) {
                            v.x = gelu_f(v.x); v.y = gelu_f(v.y);
                            *(__half2*)&Cdh[o] = __floats2half2_rn(v.x, v.y);
                        } else {
                            if (EPI == 2) {
                                float2 rv = *(const float2*)&res[o];
                                v.x += rv.x; v.y += rv.y;
                            }
                            *(float2*)&Cd[o] = v;
                        }
                    }
                }
            }
        }
    }
}

/* ---------------- launch ------------------------------------------------ */
extern "C" void kernel_launch(void* const* d_in, const int* in_sizes, int n_in,
                              void* d_out, int out_size) {
    const float* x     = (const float*)d_in[0];
    const float* gt    = (const float*)d_in[1];
    const float* n1g   = (const float*)d_in[2];
    const float* n1b   = (const float*)d_in[3];
    const float* qkvw  = (const float*)d_in[4];
    const float* qkvb  = (const float*)d_in[5];
    const float* btab  = (const float*)d_in[6];
    const float* projw = (const float*)d_in[7];
    const float* projb = (const float*)d_in[8];
    const float* n2g   = (const float*)d_in[9];
    const float* n2b   = (const float*)d_in[10];
    const float* fc1w  = (const float*)d_in[11];
    const float* fc1b  = (const float*)d_in[12];
    const float* fc2w  = (const float*)d_in[13];
    const float* fc2b  = (const float*)d_in[14];
    float* out = (float*)d_out;

    __half *xc, *ao, *ln2b, *hb, *wq, *wp, *w1, *w2;
    float *qkv, *xres;
    cudaGetSymbolAddress((void**)&xc,   g_xc);
    cudaGetSymbolAddress((void**)&qkv,  g_qkv);
    cudaGetSymbolAddress((void**)&ao,   g_attnout);
    cudaGetSymbolAddress((void**)&xres, g_xres);
    cudaGetSymbolAddress((void**)&ln2b, g_ln2);
    cudaGetSymbolAddress((void**)&hb,   g_hid);
    cudaGetSymbolAddress((void**)&wq,   g_wqkv);
    cudaGetSymbolAddress((void**)&wp,   g_wproj);
    cudaGetSymbolAddress((void**)&w1,   g_wfc1);
    cudaGetSymbolAddress((void**)&w2,   g_wfc2);

    cudaFuncSetAttribute(attn_mma,
                         cudaFuncAttributeMaxDynamicSharedMemorySize,
                         ATT2_SMEM);
    cudaFuncSetAttribute(gemm_tc<0>,
                         cudaFuncAttributeMaxDynamicSharedMemorySize,
                         GEMM_SMEM_BYTES);
    cudaFuncSetAttribute(gemm_tc<1>,
                         cudaFuncAttributeMaxDynamicSharedMemorySize,
                         GEMM_SMEM_BYTES);
    cudaFuncSetAttribute(gemm_tc<2>,
                         cudaFuncAttributeMaxDynamicSharedMemorySize,
                         GEMM_SMEM_BYTES);
    cudaFuncSetAttribute(gemm_tc<3>,
                         cudaFuncAttributeMaxDynamicSharedMemorySize,
                         GEMM_SMEM_BYTES);

    dim3 tb(32, 8);
    wtrans_pair<<<dim3((3 * C_) / 32, C_ / 32, 2), tb>>>(
        qkvw, wq, C_, 3 * C_, projw, wp, C_, C_);
    wtrans_pair<<<dim3(HID / 32, HID / 32, 2), tb>>>(
        fc1w, w1, C_, HID, fc2w, w2, HID, C_);
    bias_pre   <<<(NWIN * NWIN + 255) / 256, 256>>>(btab);
    gt_copy    <<<(NW * C_ + 255) / 256, 256>>>(gt);
    ln1_scatter<<<L_ / 8, 256>>>(x, n1g, n1b);

    gemm_tc<0><<<dim3((3 * C_) / 128, M1 / 128), 256, GEMM_SMEM_BYTES>>>(
        xc, wq, qkvb, nullptr, qkv, nullptr, nullptr, M1, 3 * C_, C_);

    attn_mma<<<NW * HEADS, 256, ATT2_SMEM>>>();

    gemm_tc<3><<<dim3(C_ / 128, M1 / 128), 256, GEMM_SMEM_BYTES>>>(
        ao, wp, projb, x, xres, nullptr, out + (size_t)L_ * C_, M1, C_, C_);

    ln2_kernel<<<L_ / 8, 256>>>(n2g, n2b);

    gemm_tc<1><<<dim3(HID / 128, M1 / 128), 256, GEMM_SMEM_BYTES>>>(
        ln2b, w1, fc1b, nullptr, nullptr, hb, nullptr, M1, HID, C_);

    gemm_tc<2><<<dim3(C_ / 128, M1 / 128), 256, GEMM_SMEM_BYTES>>>(
        hb, w2, fc2b, xres, out, nullptr, nullptr, L_, C_, HID);
}

// round 13
// speedup vs baseline: 2.1764x; 1.1948x over previous
#include <cuda_runtime.h>
#include <cuda_fp16.h>
#include <math.h>
#include <stdint.h>

#define S_ 7
#define H_ 56
#define W_ 56
#define WS 7
#define C_ 384
#define HEADS 12
#define NW 64
#define NTOK 344
#define NWIN 343
#define L_ (S_*H_*W_)          /* 21952 */
#define M1 (NW*NTOK)           /* 22016 */
#define HID 1536
#define EPS_LN 1e-5f
#define QSCALE 0.17677669529663687f  /* 32^-0.5 */

/* ---------------- scratch (static device globals; no allocation) -------- */
__device__ __half g_xc     [(size_t)M1 * C_];      /* fp16 LN1 out          */
__device__ __half g_qkv    [(size_t)M1 * 3 * C_];  /* fp16 qkv              */
__device__ __half g_attnout[(size_t)M1 * C_];      /* fp16 attn out         */
__device__ float  g_xres   [(size_t)L_ * C_];
__device__ __half g_ln2    [(size_t)M1 * C_];      /* fp16, tail zeros      */
__device__ __half g_hid    [(size_t)M1 * HID];     /* fp16 gelu out         */
__device__ float  g_bias   [(size_t)HEADS * NWIN * NWIN];
__device__ __half g_wqkv   [(size_t)C_ * 3 * C_];  /* W^T [N][K] fp16       */
__device__ __half g_wproj  [(size_t)C_ * C_];
__device__ __half g_wfc1   [(size_t)C_ * HID];
__device__ __half g_wfc2   [(size_t)HID * C_];

/* ---------------- helpers ---------------------------------------------- */
__device__ __forceinline__ float warp_sum(float v) {
    v += __shfl_xor_sync(0xffffffffu, v, 16);
    v += __shfl_xor_sync(0xffffffffu, v, 8);
    v += __shfl_xor_sync(0xffffffffu, v, 4);
    v += __shfl_xor_sync(0xffffffffu, v, 2);
    v += __shfl_xor_sync(0xffffffffu, v, 1);
    return v;
}
__device__ __forceinline__ float warp_max(float v) {
    v = fmaxf(v, __shfl_xor_sync(0xffffffffu, v, 16));
    v = fmaxf(v, __shfl_xor_sync(0xffffffffu, v, 8));
    v = fmaxf(v, __shfl_xor_sync(0xffffffffu, v, 4));
    v = fmaxf(v, __shfl_xor_sync(0xffffffffu, v, 2));
    v = fmaxf(v, __shfl_xor_sync(0xffffffffu, v, 1));
    return v;
}
__device__ __forceinline__ float gelu_f(float v) {
    return 0.5f * v * (1.f + erff(v * 0.7071067811865475f));
}
__device__ __forceinline__ void cpa16h(__half* s, const __half* g) {
    uint32_t sa = (uint32_t)__cvta_generic_to_shared(s);
    asm volatile("cp.async.cg.shared.global [%0], [%1], 16;\n" :: "r"(sa), "l"(g));
}
#define MMA_F16(c4, a4, b2)                                                    \
    asm volatile(                                                              \
        "mma.sync.aligned.m16n8k16.row.col.f32.f16.f16.f32 "                   \
        "{%0,%1,%2,%3}, {%4,%5,%6,%7}, {%8,%9}, {%0,%1,%2,%3};\n"              \
        : "+f"((c4)[0]), "+f"((c4)[1]), "+f"((c4)[2]), "+f"((c4)[3])           \
        : "r"((a4)[0]), "r"((a4)[1]), "r"((a4)[2]), "r"((a4)[3]),              \
          "r"((b2)[0]), "r"((b2)[1]))
#define LDSM4(r0, r1, r2, r3, addr)                                            \
    asm volatile("ldmatrix.sync.aligned.m8n8.x4.shared.b16 {%0,%1,%2,%3}, [%4];" \
                 : "=r"(r0), "=r"(r1), "=r"(r2), "=r"(r3) : "r"(addr))
#define LDSM2(r0, r1, addr)                                                    \
    asm volatile("ldmatrix.sync.aligned.m8n8.x2.shared.b16 {%0,%1}, [%2];"     \
                 : "=r"(r0), "=r"(r1) : "r"(addr))
#define LDSM2T(r0, r1, addr)                                                   \
    asm volatile("ldmatrix.sync.aligned.m8n8.x2.trans.shared.b16 {%0,%1}, [%2];" \
                 : "=r"(r0), "=r"(r1) : "r"(addr))

__device__ __forceinline__ int scatter_row(int l) {
    int s   = l / (H_ * W_);
    int rem = l % (H_ * W_);
    int h   = rem / W_;
    int w   = rem % W_;
    int s2 = (s >= 3) ? s - 3 : s + 4;
    int h2 = (h >= 3) ? h - 3 : h + 53;
    int w2 = (w >= 3) ? w - 3 : w + 53;
    int win = (h2 / WS) * 8 + (w2 / WS);
    int t   = s2 * 49 + (h2 % WS) * 7 + (w2 % WS);
    return win * NTOK + 1 + t;
}
__device__ __forceinline__ int unscatter_l(int win, int t) {
    int t0 = t - 1;
    int ts = t0 / 49, th = (t0 / 7) % 7, tw = t0 % 7;
    int wh = win >> 3, ww = win & 7;
    int h2 = wh * 7 + th, w2 = ww * 7 + tw;
    int s  = (ts <= 3) ? ts + 3 : ts - 4;
    int hh = (h2 <= 52) ? h2 + 3 : h2 - 53;
    int wo = (w2 <= 52) ? w2 + 3 : w2 - 53;
    return (s * H_ + hh) * W_ + wo;
}

/* ---------------- small kernels ----------------------------------------- */
__global__ void wtrans_pair(const float* __restrict__ w0, __half* __restrict__ o0,
                            int K0, int N0,
                            const float* __restrict__ w1, __half* __restrict__ o1,
                            int K1, int N1) {
    __shared__ float t[32][33];
    const float* w = blockIdx.z ? w1 : w0;
    __half*      o = blockIdx.z ? o1 : o0;
    int K = blockIdx.z ? K1 : K0;
    int N = blockIdx.z ? N1 : N0;
    int bn = blockIdx.x * 32, bk = blockIdx.y * 32;
    if (bn >= N || bk >= K) return;
    int tx = threadIdx.x, ty = threadIdx.y;
#pragma unroll
    for (int i = 0; i < 32; i += 8)
        t[ty + i][tx] = w[(size_t)(bk + ty + i) * N + bn + tx];
    __syncthreads();
#pragma unroll
    for (int i = 0; i < 32; i += 8)
        o[(size_t)(bn + ty + i) * K + bk + tx] = __float2half_rn(t[tx][ty + i]);
}

__global__ void bias_pre(const float* __restrict__ bt) {
    int idx = blockIdx.x * blockDim.x + threadIdx.x;
    if (idx >= NWIN * NWIN) return;
    int i = idx / NWIN, j = idx % NWIN;
    int si = i / 49, hi = (i / 7) % 7, wi = i % 7;
    int sj = j / 49, hj = (j / 7) % 7, wj = j % 7;
    int r = (si - sj + 6) * 20 + (hi - hj + 6) * 13 + (wi - wj + 6);
#pragma unroll
    for (int h = 0; h < HEADS; h++)
        g_bias[(size_t)h * NWIN * NWIN + idx] = bt[r * HEADS + h];
}

__global__ void gt_copy(const float* __restrict__ gt) {
    int idx = blockIdx.x * blockDim.x + threadIdx.x;
    if (idx >= NW * C_) return;
    int w = idx / C_, c = idx % C_;
    g_xc[((size_t)w * NTOK) * C_ + c] = __float2half_rn(gt[idx]);
}

/* LN kernels: one warp per token, float4 loads, fp16 stores */
__global__ void ln1_scatter(const float* __restrict__ x,
                            const float* __restrict__ g,
                            const float* __restrict__ b) {
    int gw   = (blockIdx.x * blockDim.x + threadIdx.x) >> 5;
    int lane = threadIdx.x & 31;
    if (gw >= L_) return;
    const float4* xi = (const float4*)(x + (size_t)gw * C_);
    float4 v[3];
    float sum = 0.f;
#pragma unroll
    for (int m = 0; m < 3; m++) {
        v[m] = xi[lane + m * 32];
        sum += v[m].x + v[m].y + v[m].z + v[m].w;
    }
    sum = warp_sum(sum);
    float mu = sum * (1.f / 384.f);
    float vs = 0.f;
#pragma unroll
    for (int m = 0; m < 3; m++) {
        float dx = v[m].x - mu, dy = v[m].y - mu, dz = v[m].z - mu, dw = v[m].w - mu;
        vs += dx * dx + dy * dy + dz * dz + dw * dw;
    }
    vs = warp_sum(vs);
    float rstd = rsqrtf(vs * (1.f / 384.f) + EPS_LN);
    __half* orow = g_xc + (size_t)scatter_row(gw) * C_;
    const float4* g4 = (const float4*)g;
    const float4* b4 = (const float4*)b;
#pragma unroll
    for (int m = 0; m < 3; m++) {
        int c = lane + m * 32;
        float4 gg = g4[c], bb = b4[c];
        __half2 h0 = __floats2half2_rn((v[m].x - mu) * rstd * gg.x + bb.x,
                                       (v[m].y - mu) * rstd * gg.y + bb.y);
        __half2 h1 = __floats2half2_rn((v[m].z - mu) * rstd * gg.z + bb.z,
                                       (v[m].w - mu) * rstd * gg.w + bb.w);
        uint2 pk;
        pk.x = *(uint32_t*)&h0;
        pk.y = *(uint32_t*)&h1;
        *(uint2*)&orow[c * 4] = pk;
    }
}

__global__ void ln2_kernel(const float* __restrict__ g,
                           const float* __restrict__ b) {
    int gw   = (blockIdx.x * blockDim.x + threadIdx.x) >> 5;
    int lane = threadIdx.x & 31;
    if (gw >= L_) return;
    const float4* xi = (const float4*)(g_xres + (size_t)gw * C_);
    float4 v[3];
    float sum = 0.f;
#pragma unroll
    for (int m = 0; m < 3; m++) {
        v[m] = xi[lane + m * 32];
        sum += v[m].x + v[m].y + v[m].z + v[m].w;
    }
    sum = warp_sum(sum);
    float mu = sum * (1.f / 384.f);
    float vs = 0.f;
#pragma unroll
    for (int m = 0; m < 3; m++) {
        float dx = v[m].x - mu, dy = v[m].y - mu, dz = v[m].z - mu, dw = v[m].w - mu;
        vs += dx * dx + dy * dy + dz * dz + dw * dw;
    }
    vs = warp_sum(vs);
    float rstd = rsqrtf(vs * (1.f / 384.f) + EPS_LN);
    __half* orow = g_ln2 + (size_t)gw * C_;
    const float4* g4 = (const float4*)g;
    const float4* b4 = (const float4*)b;
#pragma unroll
    for (int m = 0; m < 3; m++) {
        int c = lane + m * 32;
        float4 gg = g4[c], bb = b4[c];
        __half2 h0 = __floats2half2_rn((v[m].x - mu) * rstd * gg.x + bb.x,
                                       (v[m].y - mu) * rstd * gg.y + bb.y);
        __half2 h1 = __floats2half2_rn((v[m].z - mu) * rstd * gg.z + bb.z,
                                       (v[m].w - mu) * rstd * gg.w + bb.w);
        uint2 pk;
        pk.x = *(uint32_t*)&h0;
        pk.y = *(uint32_t*)&h1;
        *(uint2*)&orow[c * 4] = pk;
    }
}

/* ---------------- attention via fp16 mma + ldmatrix --------------------- */
/* smem: Ss fp32 [64][SSTR]; Ks half [NPAD][KSTRH] n-major; Vs half
   [NPAD][VSTRH] token-major (b-frags via ldmatrix.trans); Ps half
   [64][PSTR]; Qs half [64][QSTRH]; lab[NTOK].
   Strides (bytes): KSTRH/QSTRH/VSTRH = 80, PSTR = 720 -> all odd*16 mod
   128 => ldmatrix conflict-free.                                          */
#define SSTR  356
#define KSTRH 40
#define VSTRH 40
#define PSTR  360
#define QSTRH 40
#define NPAD  352
#define ATT_SMEM (64*SSTR*4 + (NPAD*KSTRH + NPAD*VSTRH + 64*PSTR + 64*QSTRH)*2 + NTOK*4)

__global__ __launch_bounds__(256, 1) void attn_mma() {
    extern __shared__ float sm[];
    float*  Ss = sm;
    __half* Ks = (__half*)(Ss + 64 * SSTR);
    __half* Vs = Ks + NPAD * KSTRH;
    __half* Ps = Vs + NPAD * VSTRH;
    __half* Qs = Ps + 64 * PSTR;
    int*   lab = (int*)(Qs + 64 * QSTRH);

    int tid = threadIdx.x, lane = tid & 31, wid = tid >> 5;
    int win = blockIdx.x / HEADS, head = blockIdx.x % HEADS;
    const __half* base = g_qkv + (size_t)win * NTOK * (3 * C_) + head * 32;

    uint32_t ks_s = (uint32_t)__cvta_generic_to_shared(Ks);
    uint32_t vs_s = (uint32_t)__cvta_generic_to_shared(Vs);
    uint32_t ps_s = (uint32_t)__cvta_generic_to_shared(Ps);
    uint32_t qs_s = (uint32_t)__cvta_generic_to_shared(Qs);

    /* K, V: uint4 copies (8 halfs per chunk, 4 chunks per row) */
    const uint4 z4 = {0, 0, 0, 0};
    for (int idx = tid; idx < NPAD * 4; idx += 256) {
        int n = idx >> 2, ch = (idx & 3) * 8;
        uint4 kv = (n < NTOK) ? *(const uint4*)(base + (size_t)n * (3 * C_) + C_ + ch) : z4;
        uint4 vv = (n < NTOK) ? *(const uint4*)(base + (size_t)n * (3 * C_) + 2 * C_ + ch) : z4;
        *(uint4*)(Ks + n * KSTRH + ch) = kv;
        *(uint4*)(Vs + n * VSTRH + ch) = vv;
    }
    int wh = win >> 3, ww = win & 7;
    for (int t = tid; t < NTOK; t += 256) {
        int lv = -1;
        if (t > 0) {
            int t0 = t - 1;
            int ts = t0 / 49, th = (t0 / 7) % 7, tw = t0 % 7;
            int hh = wh * 7 + th, wc = ww * 7 + tw;
            int ia = (ts < 4) ? 1 : 2;
            int ib = (hh < 49) ? 0 : ((hh < 53) ? 1 : 2);
            int ic = (wc < 49) ? 0 : ((wc < 53) ? 1 : 2);
            lv = ia * 9 + ib * 3 + ic;
        }
        lab[t] = lv;
    }
    __syncthreads();

    const float* bh = g_bias + (size_t)head * NWIN * NWIN;
    const int wm  = (wid & 1) * 32;
    const int wn  = (wid >> 1) * 88;
    const int wnO = (wid >> 1) * 8;

    const int r_off = (lane & 7) + ((lane >> 3) & 1) * 8;
    const int a_hi  = ((lane >> 4) & 1) * 16;   /* byte offset */
    const int b_n   = (lane & 7) + ((lane >> 4) & 1) * 8;
    const int b_hi  = ((lane >> 3) & 1) * 16;   /* byte offset */

    const __half2 qsc2 = __floats2half2_rn(QSCALE, QSCALE);

    for (int qt = 0; qt < 6; qt++) {
        int qbase = qt * 64;
        /* Q tile: uint4 load, half2 scale */
        for (int idx = tid; idx < 64 * 4; idx += 256) {
            int m = idx >> 2, ch = (idx & 3) * 8;
            int r = qbase + m;
            uint4 qv = z4;
            if (r < NTOK) {
                qv = *(const uint4*)(base + (size_t)r * (3 * C_) + ch);
                __half2* q2 = (__half2*)&qv;
#pragma unroll
                for (int e = 0; e < 4; e++) q2[e] = __hmul2(q2[e], qsc2);
            }
            *(uint4*)(Qs + m * QSTRH + ch) = qv;
        }
        __syncthreads();

        /* ---- S = Q K^T (fp16 k16, 2 k-steps) ---- */
        float c[2][11][4];
#pragma unroll
        for (int mt = 0; mt < 2; mt++)
#pragma unroll
            for (int nt = 0; nt < 11; nt++)
#pragma unroll
                for (int q = 0; q < 4; q++) c[mt][nt][q] = 0.f;

#pragma unroll
        for (int kst = 0; kst < 2; kst++) {
            uint32_t a[2][4], b[11][2];
#pragma unroll
            for (int mt = 0; mt < 2; mt++)
                LDSM4(a[mt][0], a[mt][1], a[mt][2], a[mt][3],
                      qs_s + ((wm + mt * 16 + r_off) * QSTRH + kst * 16) * 2 + a_hi);
#pragma unroll
            for (int p = 0; p < 5; p++)
                LDSM4(b[2 * p][0], b[2 * p][1], b[2 * p + 1][0], b[2 * p + 1][1],
                      ks_s + ((wn + p * 16 + b_n) * KSTRH + kst * 16) * 2 + b_hi);
            LDSM2(b[10][0], b[10][1],
                  ks_s + ((wn + 80 + (lane & 7)) * KSTRH + kst * 16) * 2 + b_hi);
#pragma unroll
            for (int nt = 0; nt < 11; nt++) {
                MMA_F16(c[0][nt], a[0], b[nt]);
                MMA_F16(c[1][nt], a[1], b[nt]);
            }
        }

        /* ---- store S + bias + mask (fp32) ---- */
#pragma unroll
        for (int mt = 0; mt < 2; mt++) {
            int r0 = wm + mt * 16 + (lane >> 2);
#pragma unroll
            for (int nt = 0; nt < 11; nt++) {
                int j0 = wn + nt * 8 + 2 * (lane & 3);
#pragma unroll
                for (int h = 0; h < 2; h++) {
                    int rr = r0 + h * 8;
                    int rg = qbase + rr;
                    float v0 = c[mt][nt][2 * h];
                    float v1 = c[mt][nt][2 * h + 1];
                    if (rg < NTOK && rg > 0) {
                        int lr = lab[rg];
                        if (j0 < NTOK && j0 > 0) {
                            v0 += bh[(rg - 1) * NWIN + (j0 - 1)];
                            if (lr != lab[j0]) v0 -= 100.f;
                        }
                        int j1 = j0 + 1;
                        if (j1 < NTOK) {
                            v1 += bh[(rg - 1) * NWIN + (j1 - 1)];
                            if (lr != lab[j1]) v1 -= 100.f;
                        }
                    }
                    if (j0 >= NTOK)     v0 = -1e30f;
                    if (j0 + 1 >= NTOK) v1 = -1e30f;
                    Ss[rr * SSTR + j0]     = v0;
                    Ss[rr * SSTR + j0 + 1] = v1;
                }
            }
        }
        __syncthreads();

        /* ---- softmax: read Ss fp32, write P fp16 ---- */
#pragma unroll
        for (int i = 0; i < 8; i++) {
            int rr = wid * 8 + i;
            float s[11];
            float mx = -1e30f;
#pragma unroll
            for (int m = 0; m < 11; m++) {
                s[m] = Ss[rr * SSTR + lane + m * 32];
                mx = fmaxf(mx, s[m]);
            }
            mx = warp_max(mx);
            float sum = 0.f;
#pragma unroll
            for (int m = 0; m < 11; m++) {
                float e = __expf(s[m] - mx);
                s[m] = e; sum += e;
            }
            sum = warp_sum(sum);
            float inv = 1.f / sum;
#pragma unroll
            for (int m = 0; m < 11; m++)
                Ps[rr * PSTR + lane + m * 32] = __float2half_rn(s[m] * inv);
        }
        __syncthreads();

        /* ---- O = P V (fp16 k16, V b-frags via ldmatrix.trans) ---- */
        float o[2][4] = {};
#pragma unroll 2
        for (int kt = 0; kt < 22; kt++) {
            uint32_t b[2];
            LDSM2T(b[0], b[1],
                   vs_s + ((kt * 16 + (lane & 15)) * VSTRH + wnO) * 2);
#pragma unroll
            for (int mt = 0; mt < 2; mt++) {
                uint32_t a[4];
                LDSM4(a[0], a[1], a[2], a[3],
                      ps_s + ((wm + mt * 16 + r_off) * PSTR + kt * 16) * 2 + a_hi);
                MMA_F16(o[mt], a, b);
            }
        }
#pragma unroll
        for (int mt = 0; mt < 2; mt++)
#pragma unroll
            for (int h = 0; h < 2; h++) {
                int rr = qbase + wm + mt * 16 + (lane >> 2) + h * 8;
                if (rr < NTOK) {
                    __half2 hv = __floats2half2_rn(o[mt][2 * h], o[mt][2 * h + 1]);
                    *(__half2*)&g_attnout[((size_t)win * NTOK + rr) * C_ +
                                          head * 32 + wnO + 2 * (lane & 3)] = hv;
                }
            }
        __syncthreads();
    }
}

/* ---------------- FP16 tensor-core GEMM (128x128, 3-stage, ldmatrix) ---- */
/* EPI: 0 bias->half Cdh, 1 gelu->half Cdh, 2 +res->float Cd,
        3 swin-unscatter->float.                                            */
#define ASTR 40
#define ABUF (128*ASTR)          /* halfs */
#define STG  (2*ABUF)
#define GEMM_SMEM_BYTES (3 * STG * 2)   /* 61440 */

template<int EPI>
__global__ __launch_bounds__(256, 2) void gemm_tc(const __half* __restrict__ A,
                                                  const __half* __restrict__ Bt,
                                                  const float* __restrict__ bias,
                                                  const float* __restrict__ res,
                                                  float* __restrict__ Cd,
                                                  __half* __restrict__ Cdh,
                                                  float* __restrict__ gtout,
                                                  int Mstore, int N, int K) {
    extern __shared__ float sm[];
    __half* smh = (__half*)sm;
    const int tid = threadIdx.x, lane = tid & 31, wid = tid >> 5;
    const int bm = blockIdx.y * 128, bn = blockIdx.x * 128;
    const int wm = (wid & 1) * 64, wn = (wid >> 1) * 32;
    const uint32_t sm_s = (uint32_t)__cvta_generic_to_shared(smh);

    const int r_off = (lane & 7) + ((lane >> 3) & 1) * 8;
    const int a_hi  = ((lane >> 4) & 1) * 16;
    const int b_n   = (lane & 7) + ((lane >> 4) & 1) * 8;
    const int b_hi  = ((lane >> 3) & 1) * 16;

    float c[4][4][4];
#pragma unroll
    for (int i = 0; i < 4; i++)
#pragma unroll
        for (int j = 0; j < 4; j++)
#pragma unroll
            for (int k = 0; k < 4; k++) c[i][j][k] = 0.f;

    const int NK = K >> 5;

    auto issue = [&](int kt) {
        int p = kt % 3;
        __half* As = smh + p * STG;
        __half* Bs = As + ABUF;
        const __half* Ag = A  + (size_t)bm * K + kt * 32;
        const __half* Bg = Bt + (size_t)bn * K + kt * 32;
#pragma unroll
        for (int i = 0; i < 2; i++) {
            int idx = tid + i * 256;
            int r = idx >> 2, c8 = (idx & 3) * 8;
            cpa16h(As + r * ASTR + c8, Ag + (size_t)r * K + c8);
        }
#pragma unroll
        for (int i = 0; i < 2; i++) {
            int idx = tid + i * 256;
            int r = idx >> 2, c8 = (idx & 3) * 8;
            cpa16h(Bs + r * ASTR + c8, Bg + (size_t)r * K + c8);
        }
        asm volatile("cp.async.commit_group;\n");
    };

    issue(0);
    if (NK > 1) issue(1);

    for (int kt = 0; kt < NK; kt++) {
        if (kt + 1 < NK)
            asm volatile("cp.async.wait_group 1;\n");
        else
            asm volatile("cp.async.wait_group 0;\n");
        __syncthreads();
        if (kt + 2 < NK) issue(kt + 2);

        const int p = kt % 3;
        const uint32_t as_s = sm_s + p * STG * 2;
        const uint32_t bs_s = as_s + ABUF * 2;
#pragma unroll
        for (int ks = 0; ks < 2; ks++) {
            uint32_t a[4][4], b[4][2];
#pragma unroll
            for (int mt = 0; mt < 4; mt++)
                LDSM4(a[mt][0], a[mt][1], a[mt][2], a[mt][3],
                      as_s + ((wm + mt * 16 + r_off) * ASTR + ks * 16) * 2 + a_hi);
#pragma unroll
            for (int pp = 0; pp < 2; pp++)
                LDSM4(b[2 * pp][0], b[2 * pp][1], b[2 * pp + 1][0], b[2 * pp + 1][1],
                      bs_s + ((wn + pp * 16 + b_n) * ASTR + ks * 16) * 2 + b_hi);
#pragma unroll
            for (int mt = 0; mt < 4; mt++)
#pragma unroll
                for (int nt = 0; nt < 4; nt++)
                    MMA_F16(c[mt][nt], a[mt], b[nt]);
        }
    }

    if (EPI == 3) {
#pragma unroll
        for (int mt = 0; mt < 4; mt++)
#pragma unroll
            for (int h = 0; h < 2; h++) {
                int row = bm + wm + mt * 16 + (lane >> 2) + h * 8;
                int win = row / NTOK, t = row % NTOK;
                float* dst;
                const float* xsrc = nullptr;
                if (t == 0) {
                    dst = gtout + (size_t)win * C_;
                } else {
                    int l = unscatter_l(win, t);
                    dst  = Cd  + (size_t)l * C_;
                    xsrc = res + (size_t)l * C_;
                }
#pragma unroll
                for (int nt = 0; nt < 4; nt++) {
                    int col = bn + wn + nt * 8 + 2 * (lane & 3);
                    float2 bb = *(const float2*)&bias[col];
                    float2 v;
                    v.x = c[mt][nt][2 * h]     + bb.x;
                    v.y = c[mt][nt][2 * h + 1] + bb.y;
                    if (xsrc) {
                        float2 rv = *(const float2*)&xsrc[col];
                        v.x += rv.x; v.y += rv.y;
                    }
                    *(float2*)&dst[col] = v;
                }
            }
    } else {
#pragma unroll
        for (int nt = 0; nt < 4; nt++) {
            int col = bn + wn + nt * 8 + 2 * (lane & 3);
            float2 bb = *(const float2*)&bias[col];
#pragma unroll
            for (int mt = 0; mt < 4; mt++) {
                int row0 = bm + wm + mt * 16 + (lane >> 2);
#pragma unroll
                for (int h = 0; h < 2; h++) {
                    int row = row0 + h * 8;
                    if (row < Mstore) {
                        float2 v;
                        v.x = c[mt][nt][2 * h]     + bb.x;
                        v.y = c[mt][nt][2 * h + 1] + bb.y;
                        size_t o = (size_t)row * N + col;
                        if (EPI == 0) {
                            *(__half2*)&Cdh[o] = __floats2half2_rn(v.x, v.y);
                        } else if (EPI == 1) {
                            v.x = gelu_f(v.x); v.y = gelu_f(v.y);
                            *(__half2*)&Cdh[o] = __floats2half2_rn(v.x, v.y);
                        } else {
                            float2 rv = *(const float2*)&res[o];
                            v.x += rv.x; v.y += rv.y;
                            *(float2*)&Cd[o] = v;
                        }
                    }
                }
            }
        }
    }
}

/* ---------------- launch ------------------------------------------------ */
extern "C" void kernel_launch(void* const* d_in, const int* in_sizes, int n_in,
                              void* d_out, int out_size) {
    const float* x     = (const float*)d_in[0];
    const float* gt    = (const float*)d_in[1];
    const float* n1g   = (const float*)d_in[2];
    const float* n1b   = (const float*)d_in[3];
    const float* qkvw  = (const float*)d_in[4];
    const float* qkvb  = (const float*)d_in[5];
    const float* btab  = (const float*)d_in[6];
    const float* projw = (const float*)d_in[7];
    const float* projb = (const float*)d_in[8];
    const float* n2g   = (const float*)d_in[9];
    const float* n2b   = (const float*)d_in[10];
    const float* fc1w  = (const float*)d_in[11];
    const float* fc1b  = (const float*)d_in[12];
    const float* fc2w  = (const float*)d_in[13];
    const float* fc2b  = (const float*)d_in[14];
    float* out = (float*)d_out;

    __half *xc, *qkv, *ao, *ln2b, *hb, *wq, *wp, *w1, *w2;
    float *xres;
    cudaGetSymbolAddress((void**)&xc,   g_xc);
    cudaGetSymbolAddress((void**)&qkv,  g_qkv);
    cudaGetSymbolAddress((void**)&ao,   g_attnout);
    cudaGetSymbolAddress((void**)&xres, g_xres);
    cudaGetSymbolAddress((void**)&ln2b, g_ln2);
    cudaGetSymbolAddress((void**)&hb,   g_hid);
    cudaGetSymbolAddress((void**)&wq,   g_wqkv);
    cudaGetSymbolAddress((void**)&wp,   g_wproj);
    cudaGetSymbolAddress((void**)&w1,   g_wfc1);
    cudaGetSymbolAddress((void**)&w2,   g_wfc2);

    cudaFuncSetAttribute(attn_mma,
                         cudaFuncAttributeMaxDynamicSharedMemorySize,
                         ATT_SMEM);
    cudaFuncSetAttribute(gemm_tc<0>,
                         cudaFuncAttributeMaxDynamicSharedMemorySize,
                         GEMM_SMEM_BYTES);
    cudaFuncSetAttribute(gemm_tc<1>,
                         cudaFuncAttributeMaxDynamicSharedMemorySize,
                         GEMM_SMEM_BYTES);
    cudaFuncSetAttribute(gemm_tc<2>,
                         cudaFuncAttributeMaxDynamicSharedMemorySize,
                         GEMM_SMEM_BYTES);
    cudaFuncSetAttribute(gemm_tc<3>,
                         cudaFuncAttributeMaxDynamicSharedMemorySize,
                         GEMM_SMEM_BYTES);

    dim3 tb(32, 8);
    wtrans_pair<<<dim3((3 * C_) / 32, C_ / 32, 2), tb>>>(
        qkvw, wq, C_, 3 * C_, projw, wp, C_, C_);
    wtrans_pair<<<dim3(HID / 32, HID / 32, 2), tb>>>(
        fc1w, w1, C_, HID, fc2w, w2, HID, C_);
    bias_pre   <<<(NWIN * NWIN + 255) / 256, 256>>>(btab);
    gt_copy    <<<(NW * C_ + 255) / 256, 256>>>(gt);
    ln1_scatter<<<L_ / 8, 256>>>(x, n1g, n1b);

    gemm_tc<0><<<dim3((3 * C_) / 128, M1 / 128), 256, GEMM_SMEM_BYTES>>>(
        xc, wq, qkvb, nullptr, nullptr, qkv, nullptr, M1, 3 * C_, C_);

    attn_mma<<<NW * HEADS, 256, ATT_SMEM>>>();

    gemm_tc<3><<<dim3(C_ / 128, M1 / 128), 256, GEMM_SMEM_BYTES>>>(
        ao, wp, projb, x, xres, nullptr, out + (size_t)L_ * C_, M1, C_, C_);

    ln2_kernel<<<L_ / 8, 256>>>(n2g, n2b);

    gemm_tc<1><<<dim3(HID / 128, M1 / 128), 256, GEMM_SMEM_BYTES>>>(
        ln2b, w1, fc1b, nullptr, nullptr, hb, nullptr, M1, HID, C_);

    gemm_tc<2><<<dim3(C_ / 128, M1 / 128), 256, GEMM_SMEM_BYTES>>>(
        hb, w2, fc2b, xres, out, nullptr, nullptr, L_, C_, HID);
}

// round 14
// speedup vs baseline: 2.2827x; 1.0489x over previous
#include <cuda_runtime.h>
#include <cuda_fp16.h>
#include <math.h>
#include <stdint.h>

#define S_ 7
#define H_ 56
#define W_ 56
#define WS 7
#define C_ 384
#define HEADS 12
#define NW 64
#define NTOK 344
#define NWIN 343
#define L_ (S_*H_*W_)          /* 21952 */
#define M1 (NW*NTOK)           /* 22016 */
#define HID 1536
#define EPS_LN 1e-5f
#define QSCALE 0.17677669529663687f  /* 32^-0.5 */

/* ---------------- scratch (static device globals; no allocation) -------- */
__device__ __half g_xc     [(size_t)M1 * C_];
__device__ __half g_qkv    [(size_t)M1 * 3 * C_];
__device__ __half g_attnout[(size_t)M1 * C_];
__device__ float  g_xres   [(size_t)L_ * C_];
__device__ __half g_ln2    [(size_t)M1 * C_];
__device__ __half g_hid    [(size_t)M1 * HID];
__device__ float  g_bias   [(size_t)HEADS * NWIN * NWIN];
__device__ __half g_wqkv   [(size_t)C_ * 3 * C_];  /* W^T [N][K] fp16 */
__device__ __half g_wproj  [(size_t)C_ * C_];
__device__ __half g_wfc1   [(size_t)C_ * HID];
__device__ __half g_wfc2   [(size_t)HID * C_];

/* ---------------- helpers ---------------------------------------------- */
__device__ __forceinline__ float warp_sum(float v) {
    v += __shfl_xor_sync(0xffffffffu, v, 16);
    v += __shfl_xor_sync(0xffffffffu, v, 8);
    v += __shfl_xor_sync(0xffffffffu, v, 4);
    v += __shfl_xor_sync(0xffffffffu, v, 2);
    v += __shfl_xor_sync(0xffffffffu, v, 1);
    return v;
}
__device__ __forceinline__ float warp_max(float v) {
    v = fmaxf(v, __shfl_xor_sync(0xffffffffu, v, 16));
    v = fmaxf(v, __shfl_xor_sync(0xffffffffu, v, 8));
    v = fmaxf(v, __shfl_xor_sync(0xffffffffu, v, 4));
    v = fmaxf(v, __shfl_xor_sync(0xffffffffu, v, 2));
    v = fmaxf(v, __shfl_xor_sync(0xffffffffu, v, 1));
    return v;
}
__device__ __forceinline__ float gelu_f(float v) {
    return 0.5f * v * (1.f + erff(v * 0.7071067811865475f));
}
__device__ __forceinline__ void cpa16h(__half* s, const __half* g) {
    uint32_t sa = (uint32_t)__cvta_generic_to_shared(s);
    asm volatile("cp.async.cg.shared.global [%0], [%1], 16;\n" :: "r"(sa), "l"(g));
}
#define MMA_F16(c4, a4, b2)                                                    \
    asm volatile(                                                              \
        "mma.sync.aligned.m16n8k16.row.col.f32.f16.f16.f32 "                   \
        "{%0,%1,%2,%3}, {%4,%5,%6,%7}, {%8,%9}, {%0,%1,%2,%3};\n"              \
        : "+f"((c4)[0]), "+f"((c4)[1]), "+f"((c4)[2]), "+f"((c4)[3])           \
        : "r"((a4)[0]), "r"((a4)[1]), "r"((a4)[2]), "r"((a4)[3]),              \
          "r"((b2)[0]), "r"((b2)[1]))
#define LDSM4(r0, r1, r2, r3, addr)                                            \
    asm volatile("ldmatrix.sync.aligned.m8n8.x4.shared.b16 {%0,%1,%2,%3}, [%4];" \
                 : "=r"(r0), "=r"(r1), "=r"(r2), "=r"(r3) : "r"(addr))
#define LDSM2(r0, r1, addr)                                                    \
    asm volatile("ldmatrix.sync.aligned.m8n8.x2.shared.b16 {%0,%1}, [%2];"     \
                 : "=r"(r0), "=r"(r1) : "r"(addr))
#define LDSM2T(r0, r1, addr)                                                   \
    asm volatile("ldmatrix.sync.aligned.m8n8.x2.trans.shared.b16 {%0,%1}, [%2];" \
                 : "=r"(r0), "=r"(r1) : "r"(addr))

__device__ __forceinline__ int scatter_row(int l) {
    int s   = l / (H_ * W_);
    int rem = l % (H_ * W_);
    int h   = rem / W_;
    int w   = rem % W_;
    int s2 = (s >= 3) ? s - 3 : s + 4;
    int h2 = (h >= 3) ? h - 3 : h + 53;
    int w2 = (w >= 3) ? w - 3 : w + 53;
    int win = (h2 / WS) * 8 + (w2 / WS);
    int t   = s2 * 49 + (h2 % WS) * 7 + (w2 % WS);
    return win * NTOK + 1 + t;
}
__device__ __forceinline__ int unscatter_l(int win, int t) {
    int t0 = t - 1;
    int ts = t0 / 49, th = (t0 / 7) % 7, tw = t0 % 7;
    int wh = win >> 3, ww = win & 7;
    int h2 = wh * 7 + th, w2 = ww * 7 + tw;
    int s  = (ts <= 3) ? ts + 3 : ts - 4;
    int hh = (h2 <= 52) ? h2 + 3 : h2 - 53;
    int wo = (w2 <= 52) ? w2 + 3 : w2 - 53;
    return (s * H_ + hh) * W_ + wo;
}

/* ---------------- small kernels ----------------------------------------- */
__global__ void wtrans_pair(const float* __restrict__ w0, __half* __restrict__ o0,
                            int K0, int N0,
                            const float* __restrict__ w1, __half* __restrict__ o1,
                            int K1, int N1) {
    __shared__ float t[32][33];
    const float* w = blockIdx.z ? w1 : w0;
    __half*      o = blockIdx.z ? o1 : o0;
    int K = blockIdx.z ? K1 : K0;
    int N = blockIdx.z ? N1 : N0;
    int bn = blockIdx.x * 32, bk = blockIdx.y * 32;
    if (bn >= N || bk >= K) return;
    int tx = threadIdx.x, ty = threadIdx.y;
#pragma unroll
    for (int i = 0; i < 32; i += 8)
        t[ty + i][tx] = w[(size_t)(bk + ty + i) * N + bn + tx];
    __syncthreads();
#pragma unroll
    for (int i = 0; i < 32; i += 8)
        o[(size_t)(bn + ty + i) * K + bk + tx] = __float2half_rn(t[tx][ty + i]);
}

/* fused bias gather + global-token copy */
__global__ void bias_gt(const float* __restrict__ bt, const float* __restrict__ gt) {
    int idx = blockIdx.x * blockDim.x + threadIdx.x;
    if (idx < NWIN * NWIN) {
        int i = idx / NWIN, j = idx % NWIN;
        int si = i / 49, hi = (i / 7) % 7, wi = i % 7;
        int sj = j / 49, hj = (j / 7) % 7, wj = j % 7;
        int r = (si - sj + 6) * 20 + (hi - hj + 6) * 13 + (wi - wj + 6);
#pragma unroll
        for (int h = 0; h < HEADS; h++)
            g_bias[(size_t)h * NWIN * NWIN + idx] = bt[r * HEADS + h];
        return;
    }
    idx -= NWIN * NWIN;
    if (idx < NW * C_) {
        int w = idx / C_, c = idx % C_;
        g_xc[((size_t)w * NTOK) * C_ + c] = __float2half_rn(gt[idx]);
    }
}

/* LN kernels: one warp per token, float4 loads, fp16 stores */
__global__ void ln1_scatter(const float* __restrict__ x,
                            const float* __restrict__ g,
                            const float* __restrict__ b) {
    int gw   = (blockIdx.x * blockDim.x + threadIdx.x) >> 5;
    int lane = threadIdx.x & 31;
    if (gw >= L_) return;
    const float4* xi = (const float4*)(x + (size_t)gw * C_);
    float4 v[3];
    float sum = 0.f;
#pragma unroll
    for (int m = 0; m < 3; m++) {
        v[m] = xi[lane + m * 32];
        sum += v[m].x + v[m].y + v[m].z + v[m].w;
    }
    sum = warp_sum(sum);
    float mu = sum * (1.f / 384.f);
    float vs = 0.f;
#pragma unroll
    for (int m = 0; m < 3; m++) {
        float dx = v[m].x - mu, dy = v[m].y - mu, dz = v[m].z - mu, dw = v[m].w - mu;
        vs += dx * dx + dy * dy + dz * dz + dw * dw;
    }
    vs = warp_sum(vs);
    float rstd = rsqrtf(vs * (1.f / 384.f) + EPS_LN);
    __half* orow = g_xc + (size_t)scatter_row(gw) * C_;
    const float4* g4 = (const float4*)g;
    const float4* b4 = (const float4*)b;
#pragma unroll
    for (int m = 0; m < 3; m++) {
        int c = lane + m * 32;
        float4 gg = g4[c], bb = b4[c];
        __half2 h0 = __floats2half2_rn((v[m].x - mu) * rstd * gg.x + bb.x,
                                       (v[m].y - mu) * rstd * gg.y + bb.y);
        __half2 h1 = __floats2half2_rn((v[m].z - mu) * rstd * gg.z + bb.z,
                                       (v[m].w - mu) * rstd * gg.w + bb.w);
        uint2 pk;
        pk.x = *(uint32_t*)&h0;
        pk.y = *(uint32_t*)&h1;
        *(uint2*)&orow[c * 4] = pk;
    }
}

__global__ void ln2_kernel(const float* __restrict__ g,
                           const float* __restrict__ b) {
    int gw   = (blockIdx.x * blockDim.x + threadIdx.x) >> 5;
    int lane = threadIdx.x & 31;
    if (gw >= L_) return;
    const float4* xi = (const float4*)(g_xres + (size_t)gw * C_);
    float4 v[3];
    float sum = 0.f;
#pragma unroll
    for (int m = 0; m < 3; m++) {
        v[m] = xi[lane + m * 32];
        sum += v[m].x + v[m].y + v[m].z + v[m].w;
    }
    sum = warp_sum(sum);
    float mu = sum * (1.f / 384.f);
    float vs = 0.f;
#pragma unroll
    for (int m = 0; m < 3; m++) {
        float dx = v[m].x - mu, dy = v[m].y - mu, dz = v[m].z - mu, dw = v[m].w - mu;
        vs += dx * dx + dy * dy + dz * dz + dw * dw;
    }
    vs = warp_sum(vs);
    float rstd = rsqrtf(vs * (1.f / 384.f) + EPS_LN);
    __half* orow = g_ln2 + (size_t)gw * C_;
    const float4* g4 = (const float4*)g;
    const float4* b4 = (const float4*)b;
#pragma unroll
    for (int m = 0; m < 3; m++) {
        int c = lane + m * 32;
        float4 gg = g4[c], bb = b4[c];
        __half2 h0 = __floats2half2_rn((v[m].x - mu) * rstd * gg.x + bb.x,
                                       (v[m].y - mu) * rstd * gg.y + bb.y);
        __half2 h1 = __floats2half2_rn((v[m].z - mu) * rstd * gg.z + bb.z,
                                       (v[m].w - mu) * rstd * gg.w + bb.w);
        uint2 pk;
        pk.x = *(uint32_t*)&h0;
        pk.y = *(uint32_t*)&h1;
        *(uint2*)&orow[c * 4] = pk;
    }
}

/* ---------------- attention via fp16 mma + ldmatrix (R13 config) -------- */
#define SSTR  356
#define KSTRH 40
#define VSTRH 40
#define PSTR  360
#define QSTRH 40
#define NPAD  352
#define ATT_SMEM (64*SSTR*4 + (NPAD*KSTRH + NPAD*VSTRH + 64*PSTR + 64*QSTRH)*2 + NTOK*4)

__global__ __launch_bounds__(256, 1) void attn_mma() {
    extern __shared__ float sm[];
    float*  Ss = sm;
    __half* Ks = (__half*)(Ss + 64 * SSTR);
    __half* Vs = Ks + NPAD * KSTRH;
    __half* Ps = Vs + NPAD * VSTRH;
    __half* Qs = Ps + 64 * PSTR;
    int*   lab = (int*)(Qs + 64 * QSTRH);

    int tid = threadIdx.x, lane = tid & 31, wid = tid >> 5;
    int win = blockIdx.x / HEADS, head = blockIdx.x % HEADS;
    const __half* base = g_qkv + (size_t)win * NTOK * (3 * C_) + head * 32;

    uint32_t ks_s = (uint32_t)__cvta_generic_to_shared(Ks);
    uint32_t vs_s = (uint32_t)__cvta_generic_to_shared(Vs);
    uint32_t ps_s = (uint32_t)__cvta_generic_to_shared(Ps);
    uint32_t qs_s = (uint32_t)__cvta_generic_to_shared(Qs);

    const uint4 z4 = {0, 0, 0, 0};
    for (int idx = tid; idx < NPAD * 4; idx += 256) {
        int n = idx >> 2, ch = (idx & 3) * 8;
        uint4 kv = (n < NTOK) ? *(const uint4*)(base + (size_t)n * (3 * C_) + C_ + ch) : z4;
        uint4 vv = (n < NTOK) ? *(const uint4*)(base + (size_t)n * (3 * C_) + 2 * C_ + ch) : z4;
        *(uint4*)(Ks + n * KSTRH + ch) = kv;
        *(uint4*)(Vs + n * VSTRH + ch) = vv;
    }
    int wh = win >> 3, ww = win & 7;
    for (int t = tid; t < NTOK; t += 256) {
        int lv = -1;
        if (t > 0) {
            int t0 = t - 1;
            int ts = t0 / 49, th = (t0 / 7) % 7, tw = t0 % 7;
            int hh = wh * 7 + th, wc = ww * 7 + tw;
            int ia = (ts < 4) ? 1 : 2;
            int ib = (hh < 49) ? 0 : ((hh < 53) ? 1 : 2);
            int ic = (wc < 49) ? 0 : ((wc < 53) ? 1 : 2);
            lv = ia * 9 + ib * 3 + ic;
        }
        lab[t] = lv;
    }
    __syncthreads();

    const float* bh = g_bias + (size_t)head * NWIN * NWIN;
    const int wm  = (wid & 1) * 32;
    const int wn  = (wid >> 1) * 88;
    const int wnO = (wid >> 1) * 8;

    const int r_off = (lane & 7) + ((lane >> 3) & 1) * 8;
    const int a_hi  = ((lane >> 4) & 1) * 16;
    const int b_n   = (lane & 7) + ((lane >> 4) & 1) * 8;
    const int b_hi  = ((lane >> 3) & 1) * 16;

    const __half2 qsc2 = __floats2half2_rn(QSCALE, QSCALE);

    for (int qt = 0; qt < 6; qt++) {
        int qbase = qt * 64;
        for (int idx = tid; idx < 64 * 4; idx += 256) {
            int m = idx >> 2, ch = (idx & 3) * 8;
            int r = qbase + m;
            uint4 qv = z4;
            if (r < NTOK) {
                qv = *(const uint4*)(base + (size_t)r * (3 * C_) + ch);
                __half2* q2 = (__half2*)&qv;
#pragma unroll
                for (int e = 0; e < 4; e++) q2[e] = __hmul2(q2[e], qsc2);
            }
            *(uint4*)(Qs + m * QSTRH + ch) = qv;
        }
        __syncthreads();

        float c[2][11][4];
#pragma unroll
        for (int mt = 0; mt < 2; mt++)
#pragma unroll
            for (int nt = 0; nt < 11; nt++)
#pragma unroll
                for (int q = 0; q < 4; q++) c[mt][nt][q] = 0.f;

#pragma unroll
        for (int kst = 0; kst < 2; kst++) {
            uint32_t a[2][4], b[11][2];
#pragma unroll
            for (int mt = 0; mt < 2; mt++)
                LDSM4(a[mt][0], a[mt][1], a[mt][2], a[mt][3],
                      qs_s + ((wm + mt * 16 + r_off) * QSTRH + kst * 16) * 2 + a_hi);
#pragma unroll
            for (int p = 0; p < 5; p++)
                LDSM4(b[2 * p][0], b[2 * p][1], b[2 * p + 1][0], b[2 * p + 1][1],
                      ks_s + ((wn + p * 16 + b_n) * KSTRH + kst * 16) * 2 + b_hi);
            LDSM2(b[10][0], b[10][1],
                  ks_s + ((wn + 80 + (lane & 7)) * KSTRH + kst * 16) * 2 + b_hi);
#pragma unroll
            for (int nt = 0; nt < 11; nt++) {
                MMA_F16(c[0][nt], a[0], b[nt]);
                MMA_F16(c[1][nt], a[1], b[nt]);
            }
        }

#pragma unroll
        for (int mt = 0; mt < 2; mt++) {
            int r0 = wm + mt * 16 + (lane >> 2);
#pragma unroll
            for (int nt = 0; nt < 11; nt++) {
                int j0 = wn + nt * 8 + 2 * (lane & 3);
#pragma unroll
                for (int h = 0; h < 2; h++) {
                    int rr = r0 + h * 8;
                    int rg = qbase + rr;
                    float v0 = c[mt][nt][2 * h];
                    float v1 = c[mt][nt][2 * h + 1];
                    if (rg < NTOK && rg > 0) {
                        int lr = lab[rg];
                        if (j0 < NTOK && j0 > 0) {
                            v0 += bh[(rg - 1) * NWIN + (j0 - 1)];
                            if (lr != lab[j0]) v0 -= 100.f;
                        }
                        int j1 = j0 + 1;
                        if (j1 < NTOK) {
                            v1 += bh[(rg - 1) * NWIN + (j1 - 1)];
                            if (lr != lab[j1]) v1 -= 100.f;
                        }
                    }
                    if (j0 >= NTOK)     v0 = -1e30f;
                    if (j0 + 1 >= NTOK) v1 = -1e30f;
                    Ss[rr * SSTR + j0]     = v0;
                    Ss[rr * SSTR + j0 + 1] = v1;
                }
            }
        }
        __syncthreads();

#pragma unroll
        for (int i = 0; i < 8; i++) {
            int rr = wid * 8 + i;
            float s[11];
            float mx = -1e30f;
#pragma unroll
            for (int m = 0; m < 11; m++) {
                s[m] = Ss[rr * SSTR + lane + m * 32];
                mx = fmaxf(mx, s[m]);
            }
            mx = warp_max(mx);
            float sum = 0.f;
#pragma unroll
            for (int m = 0; m < 11; m++) {
                float e = __expf(s[m] - mx);
                s[m] = e; sum += e;
            }
            sum = warp_sum(sum);
            float inv = 1.f / sum;
#pragma unroll
            for (int m = 0; m < 11; m++)
                Ps[rr * PSTR + lane + m * 32] = __float2half_rn(s[m] * inv);
        }
        __syncthreads();

        float o[2][4] = {};
#pragma unroll 2
        for (int kt = 0; kt < 22; kt++) {
            uint32_t b[2];
            LDSM2T(b[0], b[1],
                   vs_s + ((kt * 16 + (lane & 15)) * VSTRH + wnO) * 2);
#pragma unroll
            for (int mt = 0; mt < 2; mt++) {
                uint32_t a[4];
                LDSM4(a[0], a[1], a[2], a[3],
                      ps_s + ((wm + mt * 16 + r_off) * PSTR + kt * 16) * 2 + a_hi);
                MMA_F16(o[mt], a, b);
            }
        }
#pragma unroll
        for (int mt = 0; mt < 2; mt++)
#pragma unroll
            for (int h = 0; h < 2; h++) {
                int rr = qbase + wm + mt * 16 + (lane >> 2) + h * 8;
                if (rr < NTOK) {
                    __half2 hv = __floats2half2_rn(o[mt][2 * h], o[mt][2 * h + 1]);
                    *(__half2*)&g_attnout[((size_t)win * NTOK + rr) * C_ +
                                          head * 32 + wnO + 2 * (lane & 3)] = hv;
                }
            }
        __syncthreads();
    }
}

/* ---------------- FP16 tensor-core GEMM (128x128, kTile 64, 3-stage) ---- */
/* EPI: 0 bias->half Cdh, 1 gelu->half Cdh, 2 +res->float Cd,
        3 swin-unscatter->float.                                            */
#define ASTR 72                  /* halfs; 144 B row stride */
#define ABUF (128*ASTR)
#define STG  (2*ABUF)
#define GEMM_SMEM_BYTES (3 * STG * 2)   /* 110592 */

template<int EPI>
__global__ __launch_bounds__(256, 2) void gemm_tc(const __half* __restrict__ A,
                                                  const __half* __restrict__ Bt,
                                                  const float* __restrict__ bias,
                                                  const float* __restrict__ res,
                                                  float* __restrict__ Cd,
                                                  __half* __restrict__ Cdh,
                                                  float* __restrict__ gtout,
                                                  int Mstore, int N, int K) {
    extern __shared__ float sm[];
    __half* smh = (__half*)sm;
    const int tid = threadIdx.x, lane = tid & 31, wid = tid >> 5;
    const int bm = blockIdx.y * 128, bn = blockIdx.x * 128;
    const int wm = (wid & 1) * 64, wn = (wid >> 1) * 32;
    const uint32_t sm_s = (uint32_t)__cvta_generic_to_shared(smh);

    const int r_off = (lane & 7) + ((lane >> 3) & 1) * 8;
    const int a_hi  = ((lane >> 4) & 1) * 16;
    const int b_n   = (lane & 7) + ((lane >> 4) & 1) * 8;
    const int b_hi  = ((lane >> 3) & 1) * 16;

    float c[4][4][4];
#pragma unroll
    for (int i = 0; i < 4; i++)
#pragma unroll
        for (int j = 0; j < 4; j++)
#pragma unroll
            for (int k = 0; k < 4; k++) c[i][j][k] = 0.f;

    const int NK = K >> 6;

    auto issue = [&](int kt) {
        int p = kt % 3;
        __half* As = smh + p * STG;
        __half* Bs = As + ABUF;
        const __half* Ag = A  + (size_t)bm * K + kt * 64;
        const __half* Bg = Bt + (size_t)bn * K + kt * 64;
#pragma unroll
        for (int i = 0; i < 4; i++) {
            int idx = tid + i * 256;
            int r = idx >> 3, c8 = (idx & 7) * 8;
            cpa16h(As + r * ASTR + c8, Ag + (size_t)r * K + c8);
        }
#pragma unroll
        for (int i = 0; i < 4; i++) {
            int idx = tid + i * 256;
            int r = idx >> 3, c8 = (idx & 7) * 8;
            cpa16h(Bs + r * ASTR + c8, Bg + (size_t)r * K + c8);
        }
        asm volatile("cp.async.commit_group;\n");
    };

    issue(0);
    if (NK > 1) issue(1);

    for (int kt = 0; kt < NK; kt++) {
        if (kt + 1 < NK)
            asm volatile("cp.async.wait_group 1;\n");
        else
            asm volatile("cp.async.wait_group 0;\n");
        __syncthreads();
        if (kt + 2 < NK) issue(kt + 2);

        const int p = kt % 3;
        const uint32_t as_s = sm_s + p * STG * 2;
        const uint32_t bs_s = as_s + ABUF * 2;
#pragma unroll
        for (int ks = 0; ks < 4; ks++) {
            uint32_t a[4][4], b[4][2];
#pragma unroll
            for (int mt = 0; mt < 4; mt++)
                LDSM4(a[mt][0], a[mt][1], a[mt][2], a[mt][3],
                      as_s + ((wm + mt * 16 + r_off) * ASTR + ks * 16) * 2 + a_hi);
#pragma unroll
            for (int pp = 0; pp < 2; pp++)
                LDSM4(b[2 * pp][0], b[2 * pp][1], b[2 * pp + 1][0], b[2 * pp + 1][1],
                      bs_s + ((wn + pp * 16 + b_n) * ASTR + ks * 16) * 2 + b_hi);
#pragma unroll
            for (int mt = 0; mt < 4; mt++)
#pragma unroll
                for (int nt = 0; nt < 4; nt++)
                    MMA_F16(c[mt][nt], a[mt], b[nt]);
        }
    }

    if (EPI == 3) {
#pragma unroll
        for (int mt = 0; mt < 4; mt++)
#pragma unroll
            for (int h = 0; h < 2; h++) {
                int row = bm + wm + mt * 16 + (lane >> 2) + h * 8;
                int win = row / NTOK, t = row % NTOK;
                float* dst;
                const float* xsrc = nullptr;
                if (t == 0) {
                    dst = gtout + (size_t)win * C_;
                } else {
                    int l = unscatter_l(win, t);
                    dst  = Cd  + (size_t)l * C_;
                    xsrc = res + (size_t)l * C_;
                }
#pragma unroll
                for (int nt = 0; nt < 4; nt++) {
                    int col = bn + wn + nt * 8 + 2 * (lane & 3);
                    float2 bb = *(const float2*)&bias[col];
                    float2 v;
                    v.x = c[mt][nt][2 * h]     + bb.x;
                    v.y = c[mt][nt][2 * h + 1] + bb.y;
                    if (xsrc) {
                        float2 rv = *(const float2*)&xsrc[col];
                        v.x += rv.x; v.y += rv.y;
                    }
                    *(float2*)&dst[col] = v;
                }
            }
    } else {
#pragma unroll
        for (int nt = 0; nt < 4; nt++) {
            int col = bn + wn + nt * 8 + 2 * (lane & 3);
            float2 bb = *(const float2*)&bias[col];
#pragma unroll
            for (int mt = 0; mt < 4; mt++) {
                int row0 = bm + wm + mt * 16 + (lane >> 2);
#pragma unroll
                for (int h = 0; h < 2; h++) {
                    int row = row0 + h * 8;
                    if (row < Mstore) {
                        float2 v;
                        v.x = c[mt][nt][2 * h]     + bb.x;
                        v.y = c[mt][nt][2 * h + 1] + bb.y;
                        size_t o = (size_t)row * N + col;
                        if (EPI == 0) {
                            *(__half2*)&Cdh[o] = __floats2half2_rn(v.x, v.y);
                        } else if (EPI == 1) {
                            v.x = gelu_f(v.x); v.y = gelu_f(v.y);
                            *(__half2*)&Cdh[o] = __floats2half2_rn(v.x, v.y);
                        } else {
                            float2 rv = *(const float2*)&res[o];
                            v.x += rv.x; v.y += rv.y;
                            *(float2*)&Cd[o] = v;
                        }
                    }
                }
            }
        }
    }
}

/* ---------------- launch ------------------------------------------------ */
extern "C" void kernel_launch(void* const* d_in, const int* in_sizes, int n_in,
                              void* d_out, int out_size) {
    const float* x     = (const float*)d_in[0];
    const float* gt    = (const float*)d_in[1];
    const float* n1g   = (const float*)d_in[2];
    const float* n1b   = (const float*)d_in[3];
    const float* qkvw  = (const float*)d_in[4];
    const float* qkvb  = (const float*)d_in[5];
    const float* btab  = (const float*)d_in[6];
    const float* projw = (const float*)d_in[7];
    const float* projb = (const float*)d_in[8];
    const float* n2g   = (const float*)d_in[9];
    const float* n2b   = (const float*)d_in[10];
    const float* fc1w  = (const float*)d_in[11];
    const float* fc1b  = (const float*)d_in[12];
    const float* fc2w  = (const float*)d_in[13];
    const float* fc2b  = (const float*)d_in[14];
    float* out = (float*)d_out;

    __half *xc, *qkv, *ao, *ln2b, *hb, *wq, *wp, *w1, *w2;
    float *xres;
    cudaGetSymbolAddress((void**)&xc,   g_xc);
    cudaGetSymbolAddress((void**)&qkv,  g_qkv);
    cudaGetSymbolAddress((void**)&ao,   g_attnout);
    cudaGetSymbolAddress((void**)&xres, g_xres);
    cudaGetSymbolAddress((void**)&ln2b, g_ln2);
    cudaGetSymbolAddress((void**)&hb,   g_hid);
    cudaGetSymbolAddress((void**)&wq,   g_wqkv);
    cudaGetSymbolAddress((void**)&wp,   g_wproj);
    cudaGetSymbolAddress((void**)&w1,   g_wfc1);
    cudaGetSymbolAddress((void**)&w2,   g_wfc2);

    cudaFuncSetAttribute(attn_mma,
                         cudaFuncAttributeMaxDynamicSharedMemorySize,
                         ATT_SMEM);
    cudaFuncSetAttribute(gemm_tc<0>,
                         cudaFuncAttributeMaxDynamicSharedMemorySize,
                         GEMM_SMEM_BYTES);
    cudaFuncSetAttribute(gemm_tc<1>,
                         cudaFuncAttributeMaxDynamicSharedMemorySize,
                         GEMM_SMEM_BYTES);
    cudaFuncSetAttribute(gemm_tc<2>,
                         cudaFuncAttributeMaxDynamicSharedMemorySize,
                         GEMM_SMEM_BYTES);
    cudaFuncSetAttribute(gemm_tc<3>,
                         cudaFuncAttributeMaxDynamicSharedMemorySize,
                         GEMM_SMEM_BYTES);

    dim3 tb(32, 8);
    wtrans_pair<<<dim3((3 * C_) / 32, C_ / 32, 2), tb>>>(
        qkvw, wq, C_, 3 * C_, projw, wp, C_, C_);
    wtrans_pair<<<dim3(HID / 32, HID / 32, 2), tb>>>(
        fc1w, w1, C_, HID, fc2w, w2, HID, C_);
    bias_gt<<<(NWIN * NWIN + NW * C_ + 255) / 256, 256>>>(btab, gt);
    ln1_scatter<<<L_ / 8, 256>>>(x, n1g, n1b);

    gemm_tc<0><<<dim3((3 * C_) / 128, M1 / 128), 256, GEMM_SMEM_BYTES>>>(
        xc, wq, qkvb, nullptr, nullptr, qkv, nullptr, M1, 3 * C_, C_);

    attn_mma<<<NW * HEADS, 256, ATT_SMEM>>>();

    gemm_tc<3><<<dim3(C_ / 128, M1 / 128), 256, GEMM_SMEM_BYTES>>>(
        ao, wp, projb, x, xres, nullptr, out + (size_t)L_ * C_, M1, C_, C_);

    ln2_kernel<<<L_ / 8, 256>>>(n2g, n2b);

    gemm_tc<1><<<dim3(HID / 128, M1 / 128), 256, GEMM_SMEM_BYTES>>>(
        ln2b, w1, fc1b, nullptr, nullptr, hb, nullptr, M1, HID, C_);

    gemm_tc<2><<<dim3(C_ / 128, M1 / 128), 256, GEMM_SMEM_BYTES>>>(
        hb, w2, fc2b, xres, out, nullptr, nullptr, L_, C_, HID);
}

// round 15
// speedup vs baseline: 2.6493x; 1.1606x over previous
#include <cuda_runtime.h>
#include <cuda_fp16.h>
#include <math.h>
#include <stdint.h>

#define S_ 7
#define H_ 56
#define W_ 56
#define WS 7
#define C_ 384
#define HEADS 12
#define NW 64
#define NTOK 344
#define NWIN 343
#define L_ (S_*H_*W_)          /* 21952 */
#define M1 (NW*NTOK)           /* 22016 */
#define HID 1536
#define EPS_LN 1e-5f
#define QSCALE 0.17677669529663687f  /* 32^-0.5 */

/* ---------------- scratch (static device globals; no allocation) -------- */
__device__ __half g_xc     [(size_t)M1 * C_];
__device__ __half g_qkv    [(size_t)M1 * 3 * C_];
__device__ __half g_attnout[(size_t)M1 * C_];
__device__ float  g_xres   [(size_t)L_ * C_];
__device__ __half g_ln2    [(size_t)M1 * C_];
__device__ __half g_hid    [(size_t)M1 * HID];
/* fused bias+mask, 4 window classes, GT row/col zero (never written) */
__device__ __half g_cbias  [(size_t)4 * HEADS * 344 * 344];
__device__ __half g_wqkv   [(size_t)C_ * 3 * C_];  /* W^T [N][K] fp16 */
__device__ __half g_wproj  [(size_t)C_ * C_];
__device__ __half g_wfc1   [(size_t)C_ * HID];
__device__ __half g_wfc2   [(size_t)HID * C_];

/* ---------------- helpers ---------------------------------------------- */
__device__ __forceinline__ float warp_sum(float v) {
    v += __shfl_xor_sync(0xffffffffu, v, 16);
    v += __shfl_xor_sync(0xffffffffu, v, 8);
    v += __shfl_xor_sync(0xffffffffu, v, 4);
    v += __shfl_xor_sync(0xffffffffu, v, 2);
    v += __shfl_xor_sync(0xffffffffu, v, 1);
    return v;
}
__device__ __forceinline__ float warp_max(float v) {
    v = fmaxf(v, __shfl_xor_sync(0xffffffffu, v, 16));
    v = fmaxf(v, __shfl_xor_sync(0xffffffffu, v, 8));
    v = fmaxf(v, __shfl_xor_sync(0xffffffffu, v, 4));
    v = fmaxf(v, __shfl_xor_sync(0xffffffffu, v, 2));
    v = fmaxf(v, __shfl_xor_sync(0xffffffffu, v, 1));
    return v;
}
__device__ __forceinline__ float gelu_f(float v) {
    return 0.5f * v * (1.f + erff(v * 0.7071067811865475f));
}
__device__ __forceinline__ void cpa16h(__half* s, const __half* g) {
    uint32_t sa = (uint32_t)__cvta_generic_to_shared(s);
    asm volatile("cp.async.cg.shared.global [%0], [%1], 16;\n" :: "r"(sa), "l"(g));
}
#define MMA_F16(c4, a4, b2)                                                    \
    asm volatile(                                                              \
        "mma.sync.aligned.m16n8k16.row.col.f32.f16.f16.f32 "                   \
        "{%0,%1,%2,%3}, {%4,%5,%6,%7}, {%8,%9}, {%0,%1,%2,%3};\n"              \
        : "+f"((c4)[0]), "+f"((c4)[1]), "+f"((c4)[2]), "+f"((c4)[3])           \
        : "r"((a4)[0]), "r"((a4)[1]), "r"((a4)[2]), "r"((a4)[3]),              \
          "r"((b2)[0]), "r"((b2)[1]))
#define LDSM4(r0, r1, r2, r3, addr)                                            \
    asm volatile("ldmatrix.sync.aligned.m8n8.x4.shared.b16 {%0,%1,%2,%3}, [%4];" \
                 : "=r"(r0), "=r"(r1), "=r"(r2), "=r"(r3) : "r"(addr))
#define LDSM2(r0, r1, addr)                                                    \
    asm volatile("ldmatrix.sync.aligned.m8n8.x2.shared.b16 {%0,%1}, [%2];"     \
                 : "=r"(r0), "=r"(r1) : "r"(addr))
#define LDSM2T(r0, r1, addr)                                                   \
    asm volatile("ldmatrix.sync.aligned.m8n8.x2.trans.shared.b16 {%0,%1}, [%2];" \
                 : "=r"(r0), "=r"(r1) : "r"(addr))

__device__ __forceinline__ int scatter_row(int l) {
    int s   = l / (H_ * W_);
    int rem = l % (H_ * W_);
    int h   = rem / W_;
    int w   = rem % W_;
    int s2 = (s >= 3) ? s - 3 : s + 4;
    int h2 = (h >= 3) ? h - 3 : h + 53;
    int w2 = (w >= 3) ? w - 3 : w + 53;
    int win = (h2 / WS) * 8 + (w2 / WS);
    int t   = s2 * 49 + (h2 % WS) * 7 + (w2 % WS);
    return win * NTOK + 1 + t;
}
__device__ __forceinline__ int unscatter_l(int win, int t) {
    int t0 = t - 1;
    int ts = t0 / 49, th = (t0 / 7) % 7, tw = t0 % 7;
    int wh = win >> 3, ww = win & 7;
    int h2 = wh * 7 + th, w2 = ww * 7 + tw;
    int s  = (ts <= 3) ? ts + 3 : ts - 4;
    int hh = (h2 <= 52) ? h2 + 3 : h2 - 53;
    int wo = (w2 <= 52) ? w2 + 3 : w2 - 53;
    return (s * H_ + hh) * W_ + wo;
}
/* window-class label of token t0 (0..342) under class bits cls */
__device__ __forceinline__ int lab_cls(int cls, int t0) {
    int ts = t0 / 49, th = (t0 / 7) % 7, tw = t0 % 7;
    int ia = (ts < 4) ? 1 : 2;
    int ib = (cls & 1) ? ((th < 4) ? 1 : 2) : 0;
    int ic = (cls & 2) ? ((tw < 4) ? 1 : 2) : 0;
    return ia * 9 + ib * 3 + ic;
}

/* ---------------- small kernels ----------------------------------------- */
__global__ void wtrans_pair(const float* __restrict__ w0, __half* __restrict__ o0,
                            int K0, int N0,
                            const float* __restrict__ w1, __half* __restrict__ o1,
                            int K1, int N1) {
    __shared__ float t[32][33];
    const float* w = blockIdx.z ? w1 : w0;
    __half*      o = blockIdx.z ? o1 : o0;
    int K = blockIdx.z ? K1 : K0;
    int N = blockIdx.z ? N1 : N0;
    int bn = blockIdx.x * 32, bk = blockIdx.y * 32;
    if (bn >= N || bk >= K) return;
    int tx = threadIdx.x, ty = threadIdx.y;
#pragma unroll
    for (int i = 0; i < 32; i += 8)
        t[ty + i][tx] = w[(size_t)(bk + ty + i) * N + bn + tx];
    __syncthreads();
#pragma unroll
    for (int i = 0; i < 32; i += 8)
        o[(size_t)(bn + ty + i) * K + bk + tx] = __float2half_rn(t[tx][ty + i]);
}

/* fused bias+mask table build + global-token copy */
__global__ void biasgt_build(const float* __restrict__ bt,
                             const float* __restrict__ gt) {
    int idx = blockIdx.x * blockDim.x + threadIdx.x;
    if (idx < NWIN * NWIN) {
        int i = idx / NWIN, j = idx % NWIN;
        int si = i / 49, hi = (i / 7) % 7, wi = i % 7;
        int sj = j / 49, hj = (j / 7) % 7, wj = j % 7;
        int r = (si - sj + 6) * 20 + (hi - hj + 6) * 13 + (wi - wj + 6);
#pragma unroll
        for (int cls = 0; cls < 4; cls++) {
            float mv[HEADS];
            float mask = (lab_cls(cls, i) != lab_cls(cls, j)) ? -100.f : 0.f;
#pragma unroll
            for (int h = 0; h < HEADS; h++)
                mv[h] = bt[r * HEADS + h] + mask;
            size_t base = (((size_t)cls * HEADS) * 344 + (i + 1)) * 344 + (j + 1);
#pragma unroll
            for (int h = 0; h < HEADS; h++)
                g_cbias[base + (size_t)h * 344 * 344] = __float2half_rn(mv[h]);
        }
        return;
    }
    idx -= NWIN * NWIN;
    if (idx < NW * C_) {
        int w = idx / C_, c = idx % C_;
        g_xc[((size_t)w * NTOK) * C_ + c] = __float2half_rn(gt[idx]);
    }
}

/* LN kernels: one warp per token, float4 loads, fp16 stores */
__global__ void ln1_scatter(const float* __restrict__ x,
                            const float* __restrict__ g,
                            const float* __restrict__ b) {
    int gw   = (blockIdx.x * blockDim.x + threadIdx.x) >> 5;
    int lane = threadIdx.x & 31;
    if (gw >= L_) return;
    const float4* xi = (const float4*)(x + (size_t)gw * C_);
    float4 v[3];
    float sum = 0.f;
#pragma unroll
    for (int m = 0; m < 3; m++) {
        v[m] = xi[lane + m * 32];
        sum += v[m].x + v[m].y + v[m].z + v[m].w;
    }
    sum = warp_sum(sum);
    float mu = sum * (1.f / 384.f);
    float vs = 0.f;
#pragma unroll
    for (int m = 0; m < 3; m++) {
        float dx = v[m].x - mu, dy = v[m].y - mu, dz = v[m].z - mu, dw = v[m].w - mu;
        vs += dx * dx + dy * dy + dz * dz + dw * dw;
    }
    vs = warp_sum(vs);
    float rstd = rsqrtf(vs * (1.f / 384.f) + EPS_LN);
    __half* orow = g_xc + (size_t)scatter_row(gw) * C_;
    const float4* g4 = (const float4*)g;
    const float4* b4 = (const float4*)b;
#pragma unroll
    for (int m = 0; m < 3; m++) {
        int c = lane + m * 32;
        float4 gg = g4[c], bb = b4[c];
        __half2 h0 = __floats2half2_rn((v[m].x - mu) * rstd * gg.x + bb.x,
                                       (v[m].y - mu) * rstd * gg.y + bb.y);
        __half2 h1 = __floats2half2_rn((v[m].z - mu) * rstd * gg.z + bb.z,
                                       (v[m].w - mu) * rstd * gg.w + bb.w);
        uint2 pk;
        pk.x = *(uint32_t*)&h0;
        pk.y = *(uint32_t*)&h1;
        *(uint2*)&orow[c * 4] = pk;
    }
}

__global__ void ln2_kernel(const float* __restrict__ g,
                           const float* __restrict__ b) {
    int gw   = (blockIdx.x * blockDim.x + threadIdx.x) >> 5;
    int lane = threadIdx.x & 31;
    if (gw >= L_) return;
    const float4* xi = (const float4*)(g_xres + (size_t)gw * C_);
    float4 v[3];
    float sum = 0.f;
#pragma unroll
    for (int m = 0; m < 3; m++) {
        v[m] = xi[lane + m * 32];
        sum += v[m].x + v[m].y + v[m].z + v[m].w;
    }
    sum = warp_sum(sum);
    float mu = sum * (1.f / 384.f);
    float vs = 0.f;
#pragma unroll
    for (int m = 0; m < 3; m++) {
        float dx = v[m].x - mu, dy = v[m].y - mu, dz = v[m].z - mu, dw = v[m].w - mu;
        vs += dx * dx + dy * dy + dz * dz + dw * dw;
    }
    vs = warp_sum(vs);
    float rstd = rsqrtf(vs * (1.f / 384.f) + EPS_LN);
    __half* orow = g_ln2 + (size_t)gw * C_;
    const float4* g4 = (const float4*)g;
    const float4* b4 = (const float4*)b;
#pragma unroll
    for (int m = 0; m < 3; m++) {
        int c = lane + m * 32;
        float4 gg = g4[c], bb = b4[c];
        __half2 h0 = __floats2half2_rn((v[m].x - mu) * rstd * gg.x + bb.x,
                                       (v[m].y - mu) * rstd * gg.y + bb.y);
        __half2 h1 = __floats2half2_rn((v[m].z - mu) * rstd * gg.z + bb.z,
                                       (v[m].w - mu) * rstd * gg.w + bb.w);
        uint2 pk;
        pk.x = *(uint32_t*)&h0;
        pk.y = *(uint32_t*)&h1;
        *(uint2*)&orow[c * 4] = pk;
    }
}

/* ---------------- attention via fp16 mma + ldmatrix --------------------- */
#define SSTR  356
#define KSTRH 40
#define VSTRH 40
#define PSTR  360
#define QSTRH 40
#define NPAD  352
#define ATT_SMEM (64*SSTR*4 + (NPAD*KSTRH + NPAD*VSTRH + 64*PSTR + 64*QSTRH)*2)

__global__ __launch_bounds__(256, 1) void attn_mma() {
    extern __shared__ float sm[];
    float*  Ss = sm;
    __half* Ks = (__half*)(Ss + 64 * SSTR);
    __half* Vs = Ks + NPAD * KSTRH;
    __half* Ps = Vs + NPAD * VSTRH;
    __half* Qs = Ps + 64 * PSTR;

    int tid = threadIdx.x, lane = tid & 31, wid = tid >> 5;
    int win = blockIdx.x / HEADS, head = blockIdx.x % HEADS;
    const __half* base = g_qkv + (size_t)win * NTOK * (3 * C_) + head * 32;

    uint32_t ks_s = (uint32_t)__cvta_generic_to_shared(Ks);
    uint32_t vs_s = (uint32_t)__cvta_generic_to_shared(Vs);
    uint32_t ps_s = (uint32_t)__cvta_generic_to_shared(Ps);
    uint32_t qs_s = (uint32_t)__cvta_generic_to_shared(Qs);

    const uint4 z4 = {0, 0, 0, 0};
    for (int idx = tid; idx < NPAD * 4; idx += 256) {
        int n = idx >> 2, ch = (idx & 3) * 8;
        uint4 kv = (n < NTOK) ? *(const uint4*)(base + (size_t)n * (3 * C_) + C_ + ch) : z4;
        uint4 vv = (n < NTOK) ? *(const uint4*)(base + (size_t)n * (3 * C_) + 2 * C_ + ch) : z4;
        *(uint4*)(Ks + n * KSTRH + ch) = kv;
        *(uint4*)(Vs + n * VSTRH + ch) = vv;
    }
    __syncthreads();

    int wh = win >> 3, ww = win & 7;
    int cls = ((wh == 7) ? 1 : 0) | ((ww == 7) ? 2 : 0);
    const __half* ct = g_cbias + (((size_t)cls * HEADS + head) * 344) * 344;

    const int wm  = (wid & 1) * 32;
    const int wn  = (wid >> 1) * 88;
    const int wnO = (wid >> 1) * 8;

    const int r_off = (lane & 7) + ((lane >> 3) & 1) * 8;
    const int a_hi  = ((lane >> 4) & 1) * 16;
    const int b_n   = (lane & 7) + ((lane >> 4) & 1) * 8;
    const int b_hi  = ((lane >> 3) & 1) * 16;

    const __half2 qsc2 = __floats2half2_rn(QSCALE, QSCALE);

    for (int qt = 0; qt < 6; qt++) {
        int qbase = qt * 64;
        for (int idx = tid; idx < 64 * 4; idx += 256) {
            int m = idx >> 2, ch = (idx & 3) * 8;
            int r = qbase + m;
            uint4 qv = z4;
            if (r < NTOK) {
                qv = *(const uint4*)(base + (size_t)r * (3 * C_) + ch);
                __half2* q2 = (__half2*)&qv;
#pragma unroll
                for (int e = 0; e < 4; e++) q2[e] = __hmul2(q2[e], qsc2);
            }
            *(uint4*)(Qs + m * QSTRH + ch) = qv;
        }
        __syncthreads();

        float c[2][11][4];
#pragma unroll
        for (int mt = 0; mt < 2; mt++)
#pragma unroll
            for (int nt = 0; nt < 11; nt++)
#pragma unroll
                for (int q = 0; q < 4; q++) c[mt][nt][q] = 0.f;

#pragma unroll
        for (int kst = 0; kst < 2; kst++) {
            uint32_t a[2][4], b[11][2];
#pragma unroll
            for (int mt = 0; mt < 2; mt++)
                LDSM4(a[mt][0], a[mt][1], a[mt][2], a[mt][3],
                      qs_s + ((wm + mt * 16 + r_off) * QSTRH + kst * 16) * 2 + a_hi);
#pragma unroll
            for (int p = 0; p < 5; p++)
                LDSM4(b[2 * p][0], b[2 * p][1], b[2 * p + 1][0], b[2 * p + 1][1],
                      ks_s + ((wn + p * 16 + b_n) * KSTRH + kst * 16) * 2 + b_hi);
            LDSM2(b[10][0], b[10][1],
                  ks_s + ((wn + 80 + (lane & 7)) * KSTRH + kst * 16) * 2 + b_hi);
#pragma unroll
            for (int nt = 0; nt < 11; nt++) {
                MMA_F16(c[0][nt], a[0], b[nt]);
                MMA_F16(c[1][nt], a[1], b[nt]);
            }
        }

        /* ---- store S + fused bias/mask (half2 table) ---- */
#pragma unroll
        for (int mt = 0; mt < 2; mt++) {
            int r0 = wm + mt * 16 + (lane >> 2);
#pragma unroll
            for (int nt = 0; nt < 11; nt++) {
                int j0 = wn + nt * 8 + 2 * (lane & 3);
#pragma unroll
                for (int h = 0; h < 2; h++) {
                    int rr = r0 + h * 8;
                    int rg = qbase + rr;
                    float v0 = c[mt][nt][2 * h];
                    float v1 = c[mt][nt][2 * h + 1];
                    if (rg < NTOK) {
                        if (j0 + 1 < NTOK) {
                            __half2 t2 = *(const __half2*)&ct[rg * 344 + j0];
                            v0 += __low2float(t2);
                            v1 += __high2float(t2);
                        } else if (j0 < NTOK) {
                            v0 += __half2float(ct[rg * 344 + j0]);
                        }
                    }
                    if (j0 >= NTOK)     v0 = -1e30f;
                    if (j0 + 1 >= NTOK) v1 = -1e30f;
                    Ss[rr * SSTR + j0]     = v0;
                    Ss[rr * SSTR + j0 + 1] = v1;
                }
            }
        }
        __syncthreads();

#pragma unroll
        for (int i = 0; i < 8; i++) {
            int rr = wid * 8 + i;
            float s[11];
            float mx = -1e30f;
#pragma unroll
            for (int m = 0; m < 11; m++) {
                s[m] = Ss[rr * SSTR + lane + m * 32];
                mx = fmaxf(mx, s[m]);
            }
            mx = warp_max(mx);
            float sum = 0.f;
#pragma unroll
            for (int m = 0; m < 11; m++) {
                float e = __expf(s[m] - mx);
                s[m] = e; sum += e;
            }
            sum = warp_sum(sum);
            float inv = 1.f / sum;
#pragma unroll
            for (int m = 0; m < 11; m++)
                Ps[rr * PSTR + lane + m * 32] = __float2half_rn(s[m] * inv);
        }
        __syncthreads();

        float o[2][4] = {};
#pragma unroll 2
        for (int kt = 0; kt < 22; kt++) {
            uint32_t b[2];
            LDSM2T(b[0], b[1],
                   vs_s + ((kt * 16 + (lane & 15)) * VSTRH + wnO) * 2);
#pragma unroll
            for (int mt = 0; mt < 2; mt++) {
                uint32_t a[4];
                LDSM4(a[0], a[1], a[2], a[3],
                      ps_s + ((wm + mt * 16 + r_off) * PSTR + kt * 16) * 2 + a_hi);
                MMA_F16(o[mt], a, b);
            }
        }
#pragma unroll
        for (int mt = 0; mt < 2; mt++)
#pragma unroll
            for (int h = 0; h < 2; h++) {
                int rr = qbase + wm + mt * 16 + (lane >> 2) + h * 8;
                if (rr < NTOK) {
                    __half2 hv = __floats2half2_rn(o[mt][2 * h], o[mt][2 * h + 1]);
                    *(__half2*)&g_attnout[((size_t)win * NTOK + rr) * C_ +
                                          head * 32 + wnO + 2 * (lane & 3)] = hv;
                }
            }
        __syncthreads();
    }
}

/* ---------------- FP16 tensor-core GEMM (128x128, kTile 64, 3-stage) ---- */
#define ASTR 72                  /* halfs; 144 B row stride */
#define ABUF (128*ASTR)
#define STG  (2*ABUF)
#define GEMM_SMEM_BYTES (3 * STG * 2)   /* 110592 */

template<int EPI>
__global__ __launch_bounds__(256, 2) void gemm_tc(const __half* __restrict__ A,
                                                  const __half* __restrict__ Bt,
                                                  const float* __restrict__ bias,
                                                  const float* __restrict__ res,
                                                  float* __restrict__ Cd,
                                                  __half* __restrict__ Cdh,
                                                  float* __restrict__ gtout,
                                                  int Mstore, int N, int K) {
    extern __shared__ float sm[];
    __half* smh = (__half*)sm;
    const int tid = threadIdx.x, lane = tid & 31, wid = tid >> 5;
    const int bm = blockIdx.y * 128, bn = blockIdx.x * 128;
    const int wm = (wid & 1) * 64, wn = (wid >> 1) * 32;
    const uint32_t sm_s = (uint32_t)__cvta_generic_to_shared(smh);

    const int r_off = (lane & 7) + ((lane >> 3) & 1) * 8;
    const int a_hi  = ((lane >> 4) & 1) * 16;
    const int b_n   = (lane & 7) + ((lane >> 4) & 1) * 8;
    const int b_hi  = ((lane >> 3) & 1) * 16;

    float c[4][4][4];
#pragma unroll
    for (int i = 0; i < 4; i++)
#pragma unroll
        for (int j = 0; j < 4; j++)
#pragma unroll
            for (int k = 0; k < 4; k++) c[i][j][k] = 0.f;

    const int NK = K >> 6;

    auto issue = [&](int kt) {
        int p = kt % 3;
        __half* As = smh + p * STG;
        __half* Bs = As + ABUF;
        const __half* Ag = A  + (size_t)bm * K + kt * 64;
        const __half* Bg = Bt + (size_t)bn * K + kt * 64;
#pragma unroll
        for (int i = 0; i < 4; i++) {
            int idx = tid + i * 256;
            int r = idx >> 3, c8 = (idx & 7) * 8;
            cpa16h(As + r * ASTR + c8, Ag + (size_t)r * K + c8);
        }
#pragma unroll
        for (int i = 0; i < 4; i++) {
            int idx = tid + i * 256;
            int r = idx >> 3, c8 = (idx & 7) * 8;
            cpa16h(Bs + r * ASTR + c8, Bg + (size_t)r * K + c8);
        }
        asm volatile("cp.async.commit_group;\n");
    };

    issue(0);
    if (NK > 1) issue(1);

    for (int kt = 0; kt < NK; kt++) {
        if (kt + 1 < NK)
            asm volatile("cp.async.wait_group 1;\n");
        else
            asm volatile("cp.async.wait_group 0;\n");
        __syncthreads();
        if (kt + 2 < NK) issue(kt + 2);

        const int p = kt % 3;
        const uint32_t as_s = sm_s + p * STG * 2;
        const uint32_t bs_s = as_s + ABUF * 2;
#pragma unroll
        for (int ks = 0; ks < 4; ks++) {
            uint32_t a[4][4], b[4][2];
#pragma unroll
            for (int mt = 0; mt < 4; mt++)
                LDSM4(a[mt][0], a[mt][1], a[mt][2], a[mt][3],
                      as_s + ((wm + mt * 16 + r_off) * ASTR + ks * 16) * 2 + a_hi);
#pragma unroll
            for (int pp = 0; pp < 2; pp++)
                LDSM4(b[2 * pp][0], b[2 * pp][1], b[2 * pp + 1][0], b[2 * pp + 1][1],
                      bs_s + ((wn + pp * 16 + b_n) * ASTR + ks * 16) * 2 + b_hi);
#pragma unroll
            for (int mt = 0; mt < 4; mt++)
#pragma unroll
                for (int nt = 0; nt < 4; nt++)
                    MMA_F16(c[mt][nt], a[mt], b[nt]);
        }
    }

    if (EPI == 3) {
#pragma unroll
        for (int mt = 0; mt < 4; mt++)
#pragma unroll
            for (int h = 0; h < 2; h++) {
                int row = bm + wm + mt * 16 + (lane >> 2) + h * 8;
                int win = row / NTOK, t = row % NTOK;
                float* dst;
                const float* xsrc = nullptr;
                if (t == 0) {
                    dst = gtout + (size_t)win * C_;
                } else {
                    int l = unscatter_l(win, t);
                    dst  = Cd  + (size_t)l * C_;
                    xsrc = res + (size_t)l * C_;
                }
#pragma unroll
                for (int nt = 0; nt < 4; nt++) {
                    int col = bn + wn + nt * 8 + 2 * (lane & 3);
                    float2 bb = *(const float2*)&bias[col];
                    float2 v;
                    v.x = c[mt][nt][2 * h]     + bb.x;
                    v.y = c[mt][nt][2 * h + 1] + bb.y;
                    if (xsrc) {
                        float2 rv = *(const float2*)&xsrc[col];
                        v.x += rv.x; v.y += rv.y;
                    }
                    *(float2*)&dst[col] = v;
                }
            }
    } else {
#pragma unroll
        for (int nt = 0; nt < 4; nt++) {
            int col = bn + wn + nt * 8 + 2 * (lane & 3);
            float2 bb = *(const float2*)&bias[col];
#pragma unroll
            for (int mt = 0; mt < 4; mt++) {
                int row0 = bm + wm + mt * 16 + (lane >> 2);
#pragma unroll
                for (int h = 0; h < 2; h++) {
                    int row = row0 + h * 8;
                    if (row < Mstore) {
                        float2 v;
                        v.x = c[mt][nt][2 * h]     + bb.x;
                        v.y = c[mt][nt][2 * h + 1] + bb.y;
                        size_t o = (size_t)row * N + col;
                        if (EPI == 0) {
                            *(__half2*)&Cdh[o] = __floats2half2_rn(v.x, v.y);
                        } else if (EPI == 1) {
                            v.x = gelu_f(v.x); v.y = gelu_f(v.y);
                            *(__half2*)&Cdh[o] = __floats2half2_rn(v.x, v.y);
                        } else {
                            float2 rv = *(const float2*)&res[o];
                            v.x += rv.x; v.y += rv.y;
                            *(float2*)&Cd[o] = v;
                        }
                    }
                }
            }
        }
    }
}

/* ---------------- launch ------------------------------------------------ */
extern "C" void kernel_launch(void* const* d_in, const int* in_sizes, int n_in,
                              void* d_out, int out_size) {
    const float* x     = (const float*)d_in[0];
    const float* gt    = (const float*)d_in[1];
    const float* n1g   = (const float*)d_in[2];
    const float* n1b   = (const float*)d_in[3];
    const float* qkvw  = (const float*)d_in[4];
    const float* qkvb  = (const float*)d_in[5];
    const float* btab  = (const float*)d_in[6];
    const float* projw = (const float*)d_in[7];
    const float* projb = (const float*)d_in[8];
    const float* n2g   = (const float*)d_in[9];
    const float* n2b   = (const float*)d_in[10];
    const float* fc1w  = (const float*)d_in[11];
    const float* fc1b  = (const float*)d_in[12];
    const float* fc2w  = (const float*)d_in[13];
    const float* fc2b  = (const float*)d_in[14];
    float* out = (float*)d_out;

    __half *xc, *qkv, *ao, *ln2b, *hb, *wq, *wp, *w1, *w2;
    float *xres;
    cudaGetSymbolAddress((void**)&xc,   g_xc);
    cudaGetSymbolAddress((void**)&qkv,  g_qkv);
    cudaGetSymbolAddress((void**)&ao,   g_attnout);
    cudaGetSymbolAddress((void**)&xres, g_xres);
    cudaGetSymbolAddress((void**)&ln2b, g_ln2);
    cudaGetSymbolAddress((void**)&hb,   g_hid);
    cudaGetSymbolAddress((void**)&wq,   g_wqkv);
    cudaGetSymbolAddress((void**)&wp,   g_wproj);
    cudaGetSymbolAddress((void**)&w1,   g_wfc1);
    cudaGetSymbolAddress((void**)&w2,   g_wfc2);

    cudaFuncSetAttribute(attn_mma,
                         cudaFuncAttributeMaxDynamicSharedMemorySize,
                         ATT_SMEM);
    cudaFuncSetAttribute(gemm_tc<0>,
                         cudaFuncAttributeMaxDynamicSharedMemorySize,
                         GEMM_SMEM_BYTES);
    cudaFuncSetAttribute(gemm_tc<1>,
                         cudaFuncAttributeMaxDynamicSharedMemorySize,
                         GEMM_SMEM_BYTES);
    cudaFuncSetAttribute(gemm_tc<2>,
                         cudaFuncAttributeMaxDynamicSharedMemorySize,
                         GEMM_SMEM_BYTES);
    cudaFuncSetAttribute(gemm_tc<3>,
                         cudaFuncAttributeMaxDynamicSharedMemorySize,
                         GEMM_SMEM_BYTES);

    dim3 tb(32, 8);
    /* order chosen so the qkv GEMM sits at capture index 3 for ncu */
    ln1_scatter <<<L_ / 8, 256>>>(x, n1g, n1b);                       /* 0 */
    biasgt_build<<<(NWIN * NWIN + NW * C_ + 255) / 256, 256>>>(btab, gt); /* 1 */
    wtrans_pair <<<dim3((3 * C_) / 32, C_ / 32, 2), tb>>>(
        qkvw, wq, C_, 3 * C_, projw, wp, C_, C_);                     /* 2 */

    gemm_tc<0><<<dim3((3 * C_) / 128, M1 / 128), 256, GEMM_SMEM_BYTES>>>(
        xc, wq, qkvb, nullptr, nullptr, qkv, nullptr, M1, 3 * C_, C_); /* 3 */

    wtrans_pair<<<dim3(HID / 32, HID / 32, 2), tb>>>(
        fc1w, w1, C_, HID, fc2w, w2, HID, C_);                        /* 4 */

    attn_mma<<<NW * HEADS, 256, ATT_SMEM>>>();                        /* 5 */

    gemm_tc<3><<<dim3(C_ / 128, M1 / 128), 256, GEMM_SMEM_BYTES>>>(
        ao, wp, projb, x, xres, nullptr, out + (size_t)L_ * C_, M1, C_, C_);

    ln2_kernel<<<L_ / 8, 256>>>(n2g, n2b);

    gemm_tc<1><<<dim3(HID / 128, M1 / 128), 256, GEMM_SMEM_BYTES>>>(
        ln2b, w1, fc1b, nullptr, nullptr, hb, nullptr, M1, HID, C_);

    gemm_tc<2><<<dim3(C_ / 128, M1 / 128), 256, GEMM_SMEM_BYTES>>>(
        hb, w2, fc2b, xres, out, nullptr, nullptr, L_, C_, HID);
}

// round 16
// speedup vs baseline: 2.9818x; 1.1255x over previous
#include <cuda_runtime.h>
#include <cuda_fp16.h>
#include <math.h>
#include <stdint.h>

#define S_ 7
#define H_ 56
#define W_ 56
#define WS 7
#define C_ 384
#define HEADS 12
#define NW 64
#define NTOK 344
#define NWIN 343
#define L_ (S_*H_*W_)          /* 21952 */
#define M1 (NW*NTOK)           /* 22016 */
#define HID 1536
#define EPS_LN 1e-5f
#define QSCALE 0.17677669529663687f  /* 32^-0.5 */

/* ---------------- scratch (static device globals; no allocation) -------- */
__device__ __half g_xc     [(size_t)M1 * C_];
__device__ __half g_qkv    [(size_t)M1 * 3 * C_];
__device__ __half g_attnout[(size_t)M1 * C_];
__device__ float  g_xres   [(size_t)L_ * C_];
__device__ __half g_ln2    [(size_t)M1 * C_];
__device__ __half g_hid    [(size_t)M1 * HID];
/* fused bias+mask, 4 window classes, GT row/col zero (never written) */
__device__ __half g_cbias  [(size_t)4 * HEADS * 344 * 344];
__device__ __half g_wqkv   [(size_t)C_ * 3 * C_];  /* W^T [N][K] fp16 */
__device__ __half g_wproj  [(size_t)C_ * C_];
__device__ __half g_wfc1   [(size_t)C_ * HID];
__device__ __half g_wfc2   [(size_t)HID * C_];

/* ---------------- helpers ---------------------------------------------- */
__device__ __forceinline__ float warp_sum(float v) {
    v += __shfl_xor_sync(0xffffffffu, v, 16);
    v += __shfl_xor_sync(0xffffffffu, v, 8);
    v += __shfl_xor_sync(0xffffffffu, v, 4);
    v += __shfl_xor_sync(0xffffffffu, v, 2);
    v += __shfl_xor_sync(0xffffffffu, v, 1);
    return v;
}
__device__ __forceinline__ float warp_max(float v) {
    v = fmaxf(v, __shfl_xor_sync(0xffffffffu, v, 16));
    v = fmaxf(v, __shfl_xor_sync(0xffffffffu, v, 8));
    v = fmaxf(v, __shfl_xor_sync(0xffffffffu, v, 4));
    v = fmaxf(v, __shfl_xor_sync(0xffffffffu, v, 2));
    v = fmaxf(v, __shfl_xor_sync(0xffffffffu, v, 1));
    return v;
}
__device__ __forceinline__ float gelu_f(float v) {
    return 0.5f * v * (1.f + erff(v * 0.7071067811865475f));
}
__device__ __forceinline__ void cpa16h(__half* s, const __half* g) {
    uint32_t sa = (uint32_t)__cvta_generic_to_shared(s);
    asm volatile("cp.async.cg.shared.global [%0], [%1], 16;\n" :: "r"(sa), "l"(g));
}
#define MMA_F16(c4, a4, b2)                                                    \
    asm volatile(                                                              \
        "mma.sync.aligned.m16n8k16.row.col.f32.f16.f16.f32 "                   \
        "{%0,%1,%2,%3}, {%4,%5,%6,%7}, {%8,%9}, {%0,%1,%2,%3};\n"              \
        : "+f"((c4)[0]), "+f"((c4)[1]), "+f"((c4)[2]), "+f"((c4)[3])           \
        : "r"((a4)[0]), "r"((a4)[1]), "r"((a4)[2]), "r"((a4)[3]),              \
          "r"((b2)[0]), "r"((b2)[1]))
#define LDSM4(r0, r1, r2, r3, addr)                                            \
    asm volatile("ldmatrix.sync.aligned.m8n8.x4.shared.b16 {%0,%1,%2,%3}, [%4];" \
                 : "=r"(r0), "=r"(r1), "=r"(r2), "=r"(r3) : "r"(addr))
#define LDSM2(r0, r1, addr)                                                    \
    asm volatile("ldmatrix.sync.aligned.m8n8.x2.shared.b16 {%0,%1}, [%2];"     \
                 : "=r"(r0), "=r"(r1) : "r"(addr))
#define LDSM2T(r0, r1, addr)                                                   \
    asm volatile("ldmatrix.sync.aligned.m8n8.x2.trans.shared.b16 {%0,%1}, [%2];" \
                 : "=r"(r0), "=r"(r1) : "r"(addr))

__device__ __forceinline__ int scatter_row(int l) {
    int s   = l / (H_ * W_);
    int rem = l % (H_ * W_);
    int h   = rem / W_;
    int w   = rem % W_;
    int s2 = (s >= 3) ? s - 3 : s + 4;
    int h2 = (h >= 3) ? h - 3 : h + 53;
    int w2 = (w >= 3) ? w - 3 : w + 53;
    int win = (h2 / WS) * 8 + (w2 / WS);
    int t   = s2 * 49 + (h2 % WS) * 7 + (w2 % WS);
    return win * NTOK + 1 + t;
}
__device__ __forceinline__ int unscatter_l(int win, int t) {
    int t0 = t - 1;
    int ts = t0 / 49, th = (t0 / 7) % 7, tw = t0 % 7;
    int wh = win >> 3, ww = win & 7;
    int h2 = wh * 7 + th, w2 = ww * 7 + tw;
    int s  = (ts <= 3) ? ts + 3 : ts - 4;
    int hh = (h2 <= 52) ? h2 + 3 : h2 - 53;
    int wo = (w2 <= 52) ? w2 + 3 : w2 - 53;
    return (s * H_ + hh) * W_ + wo;
}
__device__ __forceinline__ int lab_cls(int cls, int t0) {
    int ts = t0 / 49, th = (t0 / 7) % 7, tw = t0 % 7;
    int ia = (ts < 4) ? 1 : 2;
    int ib = (cls & 1) ? ((th < 4) ? 1 : 2) : 0;
    int ic = (cls & 2) ? ((tw < 4) ? 1 : 2) : 0;
    return ia * 9 + ib * 3 + ic;
}

/* ---------------- small kernels ----------------------------------------- */
__global__ void wtrans_pair(const float* __restrict__ w0, __half* __restrict__ o0,
                            int K0, int N0,
                            const float* __restrict__ w1, __half* __restrict__ o1,
                            int K1, int N1) {
    __shared__ float t[32][33];
    const float* w = blockIdx.z ? w1 : w0;
    __half*      o = blockIdx.z ? o1 : o0;
    int K = blockIdx.z ? K1 : K0;
    int N = blockIdx.z ? N1 : N0;
    int bn = blockIdx.x * 32, bk = blockIdx.y * 32;
    if (bn >= N || bk >= K) return;
    int tx = threadIdx.x, ty = threadIdx.y;
#pragma unroll
    for (int i = 0; i < 32; i += 8)
        t[ty + i][tx] = w[(size_t)(bk + ty + i) * N + bn + tx];
    __syncthreads();
#pragma unroll
    for (int i = 0; i < 32; i += 8)
        o[(size_t)(bn + ty + i) * K + bk + tx] = __float2half_rn(t[tx][ty + i]);
}

/* coalesced fused bias+mask table build + global-token copy.
   one thread per (cls, head, i, j): j fastest -> coalesced 2B stores. */
#define CB_TOT (4 * HEADS * NWIN * NWIN)
__global__ void biasgt_build(const float* __restrict__ bt,
                             const float* __restrict__ gt) {
    int idx = blockIdx.x * blockDim.x + threadIdx.x;
    if (idx < CB_TOT) {
        int j   = idx % NWIN;
        int t   = idx / NWIN;
        int i   = t % NWIN;
        t /= NWIN;
        int h   = t % HEADS;
        int cls = t / HEADS;
        int si = i / 49, hi = (i / 7) % 7, wi = i % 7;
        int sj = j / 49, hj = (j / 7) % 7, wj = j % 7;
        int r = (si - sj + 6) * 20 + (hi - hj + 6) * 13 + (wi - wj + 6);
        float v = bt[r * HEADS + h];
        if (lab_cls(cls, i) != lab_cls(cls, j)) v -= 100.f;
        g_cbias[(((size_t)(cls * HEADS + h)) * 344 + (i + 1)) * 344 + (j + 1)] =
            __float2half_rn(v);
        return;
    }
    idx -= CB_TOT;
    if (idx < NW * C_) {
        int w = idx / C_, c = idx % C_;
        g_xc[((size_t)w * NTOK) * C_ + c] = __float2half_rn(gt[idx]);
    }
}

/* LN kernels: one warp per token, float4 loads, fp16 stores */
__global__ void ln1_scatter(const float* __restrict__ x,
                            const float* __restrict__ g,
                            const float* __restrict__ b) {
    int gw   = (blockIdx.x * blockDim.x + threadIdx.x) >> 5;
    int lane = threadIdx.x & 31;
    if (gw >= L_) return;
    const float4* xi = (const float4*)(x + (size_t)gw * C_);
    float4 v[3];
    float sum = 0.f;
#pragma unroll
    for (int m = 0; m < 3; m++) {
        v[m] = xi[lane + m * 32];
        sum += v[m].x + v[m].y + v[m].z + v[m].w;
    }
    sum = warp_sum(sum);
    float mu = sum * (1.f / 384.f);
    float vs = 0.f;
#pragma unroll
    for (int m = 0; m < 3; m++) {
        float dx = v[m].x - mu, dy = v[m].y - mu, dz = v[m].z - mu, dw = v[m].w - mu;
        vs += dx * dx + dy * dy + dz * dz + dw * dw;
    }
    vs = warp_sum(vs);
    float rstd = rsqrtf(vs * (1.f / 384.f) + EPS_LN);
    __half* orow = g_xc + (size_t)scatter_row(gw) * C_;
    const float4* g4 = (const float4*)g;
    const float4* b4 = (const float4*)b;
#pragma unroll
    for (int m = 0; m < 3; m++) {
        int c = lane + m * 32;
        float4 gg = g4[c], bb = b4[c];
        __half2 h0 = __floats2half2_rn((v[m].x - mu) * rstd * gg.x + bb.x,
                                       (v[m].y - mu) * rstd * gg.y + bb.y);
        __half2 h1 = __floats2half2_rn((v[m].z - mu) * rstd * gg.z + bb.z,
                                       (v[m].w - mu) * rstd * gg.w + bb.w);
        uint2 pk;
        pk.x = *(uint32_t*)&h0;
        pk.y = *(uint32_t*)&h1;
        *(uint2*)&orow[c * 4] = pk;
    }
}

__global__ void ln2_kernel(const float* __restrict__ g,
                           const float* __restrict__ b) {
    int gw   = (blockIdx.x * blockDim.x + threadIdx.x) >> 5;
    int lane = threadIdx.x & 31;
    if (gw >= L_) return;
    const float4* xi = (const float4*)(g_xres + (size_t)gw * C_);
    float4 v[3];
    float sum = 0.f;
#pragma unroll
    for (int m = 0; m < 3; m++) {
        v[m] = xi[lane + m * 32];
        sum += v[m].x + v[m].y + v[m].z + v[m].w;
    }
    sum = warp_sum(sum);
    float mu = sum * (1.f / 384.f);
    float vs = 0.f;
#pragma unroll
    for (int m = 0; m < 3; m++) {
        float dx = v[m].x - mu, dy = v[m].y - mu, dz = v[m].z - mu, dw = v[m].w - mu;
        vs += dx * dx + dy * dy + dz * dz + dw * dw;
    }
    vs = warp_sum(vs);
    float rstd = rsqrtf(vs * (1.f / 384.f) + EPS_LN);
    __half* orow = g_ln2 + (size_t)gw * C_;
    const float4* g4 = (const float4*)g;
    const float4* b4 = (const float4*)b;
#pragma unroll
    for (int m = 0; m < 3; m++) {
        int c = lane + m * 32;
        float4 gg = g4[c], bb = b4[c];
        __half2 h0 = __floats2half2_rn((v[m].x - mu) * rstd * gg.x + bb.x,
                                       (v[m].y - mu) * rstd * gg.y + bb.y);
        __half2 h1 = __floats2half2_rn((v[m].z - mu) * rstd * gg.z + bb.z,
                                       (v[m].w - mu) * rstd * gg.w + bb.w);
        uint2 pk;
        pk.x = *(uint32_t*)&h0;
        pk.y = *(uint32_t*)&h1;
        *(uint2*)&orow[c * 4] = pk;
    }
}

/* ---------------- attention: fp16 mma, S stored fp16, occupancy 2 ------- */
#define KSTRH 40
#define VSTRH 40
#define PSTR  360
#define QSTRH 40
#define NPAD  352
#define ATT_SMEM ((NPAD*KSTRH + NPAD*VSTRH + 64*PSTR + 64*QSTRH)*2)  /* 107520 */

__global__ __launch_bounds__(256, 2) void attn_mma() {
    extern __shared__ float sm[];
    __half* Ks = (__half*)sm;
    __half* Vs = Ks + NPAD * KSTRH;
    __half* Ps = Vs + NPAD * VSTRH;
    __half* Qs = Ps + 64 * PSTR;

    int tid = threadIdx.x, lane = tid & 31, wid = tid >> 5;
    int win = blockIdx.x / HEADS, head = blockIdx.x % HEADS;
    const __half* base = g_qkv + (size_t)win * NTOK * (3 * C_) + head * 32;

    uint32_t ks_s = (uint32_t)__cvta_generic_to_shared(Ks);
    uint32_t vs_s = (uint32_t)__cvta_generic_to_shared(Vs);
    uint32_t ps_s = (uint32_t)__cvta_generic_to_shared(Ps);
    uint32_t qs_s = (uint32_t)__cvta_generic_to_shared(Qs);

    const uint4 z4 = {0, 0, 0, 0};
    for (int idx = tid; idx < NPAD * 4; idx += 256) {
        int n = idx >> 2, ch = (idx & 3) * 8;
        uint4 kv = (n < NTOK) ? *(const uint4*)(base + (size_t)n * (3 * C_) + C_ + ch) : z4;
        uint4 vv = (n < NTOK) ? *(const uint4*)(base + (size_t)n * (3 * C_) + 2 * C_ + ch) : z4;
        *(uint4*)(Ks + n * KSTRH + ch) = kv;
        *(uint4*)(Vs + n * VSTRH + ch) = vv;
    }
    __syncthreads();

    int wh = win >> 3, ww = win & 7;
    int cls = ((wh == 7) ? 1 : 0) | ((ww == 7) ? 2 : 0);
    const __half* ct = g_cbias + (((size_t)cls * HEADS + head) * 344) * 344;

    const int wm  = (wid & 1) * 32;
    const int wn  = (wid >> 1) * 88;
    const int wnO = (wid >> 1) * 8;

    const int r_off = (lane & 7) + ((lane >> 3) & 1) * 8;
    const int a_hi  = ((lane >> 4) & 1) * 16;
    const int b_n   = (lane & 7) + ((lane >> 4) & 1) * 8;
    const int b_hi  = ((lane >> 3) & 1) * 16;

    const __half2 qsc2 = __floats2half2_rn(QSCALE, QSCALE);

    for (int qt = 0; qt < 6; qt++) {
        int qbase = qt * 64;
        for (int idx = tid; idx < 64 * 4; idx += 256) {
            int m = idx >> 2, ch = (idx & 3) * 8;
            int r = qbase + m;
            uint4 qv = z4;
            if (r < NTOK) {
                qv = *(const uint4*)(base + (size_t)r * (3 * C_) + ch);
                __half2* q2 = (__half2*)&qv;
#pragma unroll
                for (int e = 0; e < 4; e++) q2[e] = __hmul2(q2[e], qsc2);
            }
            *(uint4*)(Qs + m * QSTRH + ch) = qv;
        }
        __syncthreads();

        float c[2][11][4];
#pragma unroll
        for (int mt = 0; mt < 2; mt++)
#pragma unroll
            for (int nt = 0; nt < 11; nt++)
#pragma unroll
                for (int q = 0; q < 4; q++) c[mt][nt][q] = 0.f;

#pragma unroll
        for (int kst = 0; kst < 2; kst++) {
            uint32_t a[2][4], b[11][2];
#pragma unroll
            for (int mt = 0; mt < 2; mt++)
                LDSM4(a[mt][0], a[mt][1], a[mt][2], a[mt][3],
                      qs_s + ((wm + mt * 16 + r_off) * QSTRH + kst * 16) * 2 + a_hi);
#pragma unroll
            for (int p = 0; p < 5; p++)
                LDSM4(b[2 * p][0], b[2 * p][1], b[2 * p + 1][0], b[2 * p + 1][1],
                      ks_s + ((wn + p * 16 + b_n) * KSTRH + kst * 16) * 2 + b_hi);
            LDSM2(b[10][0], b[10][1],
                  ks_s + ((wn + 80 + (lane & 7)) * KSTRH + kst * 16) * 2 + b_hi);
#pragma unroll
            for (int nt = 0; nt < 11; nt++) {
                MMA_F16(c[0][nt], a[0], b[nt]);
                MMA_F16(c[1][nt], a[1], b[nt]);
            }
        }

        /* ---- store S (fp16) + fused bias/mask table ---- */
#pragma unroll
        for (int mt = 0; mt < 2; mt++) {
            int r0 = wm + mt * 16 + (lane >> 2);
#pragma unroll
            for (int nt = 0; nt < 11; nt++) {
                int j0 = wn + nt * 8 + 2 * (lane & 3);
#pragma unroll
                for (int h = 0; h < 2; h++) {
                    int rr = r0 + h * 8;
                    int rg = qbase + rr;
                    float v0 = c[mt][nt][2 * h];
                    float v1 = c[mt][nt][2 * h + 1];
                    if (rg < NTOK) {
                        if (j0 + 1 < NTOK) {
                            __half2 t2 = *(const __half2*)&ct[rg * 344 + j0];
                            v0 += __low2float(t2);
                            v1 += __high2float(t2);
                        } else if (j0 < NTOK) {
                            v0 += __half2float(ct[rg * 344 + j0]);
                        }
                    }
                    if (j0 >= NTOK)     v0 = -30000.f;
                    if (j0 + 1 >= NTOK) v1 = -30000.f;
                    *(__half2*)&Ps[rr * PSTR + j0] = __floats2half2_rn(v0, v1);
                }
            }
        }
        __syncthreads();

        /* ---- softmax in place on Ps (fp32 math) ---- */
#pragma unroll
        for (int i = 0; i < 8; i++) {
            int rr = wid * 8 + i;
            float s[11];
            float mx = -1e30f;
#pragma unroll
            for (int m = 0; m < 11; m++) {
                s[m] = __half2float(Ps[rr * PSTR + lane + m * 32]);
                mx = fmaxf(mx, s[m]);
            }
            mx = warp_max(mx);
            float sum = 0.f;
#pragma unroll
            for (int m = 0; m < 11; m++) {
                float e = __expf(s[m] - mx);
                s[m] = e; sum += e;
            }
            sum = warp_sum(sum);
            float inv = 1.f / sum;
#pragma unroll
            for (int m = 0; m < 11; m++)
                Ps[rr * PSTR + lane + m * 32] = __float2half_rn(s[m] * inv);
        }
        __syncthreads();

        /* ---- O = P V ---- */
        float o[2][4] = {};
#pragma unroll 2
        for (int kt = 0; kt < 22; kt++) {
            uint32_t b[2];
            LDSM2T(b[0], b[1],
                   vs_s + ((kt * 16 + (lane & 15)) * VSTRH + wnO) * 2);
#pragma unroll
            for (int mt = 0; mt < 2; mt++) {
                uint32_t a[4];
                LDSM4(a[0], a[1], a[2], a[3],
                      ps_s + ((wm + mt * 16 + r_off) * PSTR + kt * 16) * 2 + a_hi);
                MMA_F16(o[mt], a, b);
            }
        }
#pragma unroll
        for (int mt = 0; mt < 2; mt++)
#pragma unroll
            for (int h = 0; h < 2; h++) {
                int rr = qbase + wm + mt * 16 + (lane >> 2) + h * 8;
                if (rr < NTOK) {
                    __half2 hv = __floats2half2_rn(o[mt][2 * h], o[mt][2 * h + 1]);
                    *(__half2*)&g_attnout[((size_t)win * NTOK + rr) * C_ +
                                          head * 32 + wnO + 2 * (lane & 3)] = hv;
                }
            }
        __syncthreads();
    }
}

/* ---------------- FP16 tensor-core GEMM (128x128, kTile 64, 3-stage) ---- */
#define ASTR 72                  /* halfs; 144 B row stride */
#define ABUF (128*ASTR)
#define STG  (2*ABUF)
#define GEMM_SMEM_BYTES (3 * STG * 2)   /* 110592 */

template<int EPI>
__global__ __launch_bounds__(256, 2) void gemm_tc(const __half* __restrict__ A,
                                                  const __half* __restrict__ Bt,
                                                  const float* __restrict__ bias,
                                                  const float* __restrict__ res,
                                                  float* __restrict__ Cd,
                                                  __half* __restrict__ Cdh,
                                                  float* __restrict__ gtout,
                                                  int Mstore, int N, int K) {
    extern __shared__ float sm[];
    __half* smh = (__half*)sm;
    const int tid = threadIdx.x, lane = tid & 31, wid = tid >> 5;
    const int bm = blockIdx.y * 128, bn = blockIdx.x * 128;
    const int wm = (wid & 1) * 64, wn = (wid >> 1) * 32;
    const uint32_t sm_s = (uint32_t)__cvta_generic_to_shared(smh);

    const int r_off = (lane & 7) + ((lane >> 3) & 1) * 8;
    const int a_hi  = ((lane >> 4) & 1) * 16;
    const int b_n   = (lane & 7) + ((lane >> 4) & 1) * 8;
    const int b_hi  = ((lane >> 3) & 1) * 16;

    float c[4][4][4];
#pragma unroll
    for (int i = 0; i < 4; i++)
#pragma unroll
        for (int j = 0; j < 4; j++)
#pragma unroll
            for (int k = 0; k < 4; k++) c[i][j][k] = 0.f;

    const int NK = K >> 6;

    auto issue = [&](int kt) {
        int p = kt % 3;
        __half* As = smh + p * STG;
        __half* Bs = As + ABUF;
        const __half* Ag = A  + (size_t)bm * K + kt * 64;
        const __half* Bg = Bt + (size_t)bn * K + kt * 64;
#pragma unroll
        for (int i = 0; i < 4; i++) {
            int idx = tid + i * 256;
            int r = idx >> 3, c8 = (idx & 7) * 8;
            cpa16h(As + r * ASTR + c8, Ag + (size_t)r * K + c8);
        }
#pragma unroll
        for (int i = 0; i < 4; i++) {
            int idx = tid + i * 256;
            int r = idx >> 3, c8 = (idx & 7) * 8;
            cpa16h(Bs + r * ASTR + c8, Bg + (size_t)r * K + c8);
        }
        asm volatile("cp.async.commit_group;\n");
    };

    issue(0);
    if (NK > 1) issue(1);

    for (int kt = 0; kt < NK; kt++) {
        if (kt + 1 < NK)
            asm volatile("cp.async.wait_group 1;\n");
        else
            asm volatile("cp.async.wait_group 0;\n");
        __syncthreads();
        if (kt + 2 < NK) issue(kt + 2);

        const int p = kt % 3;
        const uint32_t as_s = sm_s + p * STG * 2;
        const uint32_t bs_s = as_s + ABUF * 2;
#pragma unroll
        for (int ks = 0; ks < 4; ks++) {
            uint32_t a[4][4], b[4][2];
#pragma unroll
            for (int mt = 0; mt < 4; mt++)
                LDSM4(a[mt][0], a[mt][1], a[mt][2], a[mt][3],
                      as_s + ((wm + mt * 16 + r_off) * ASTR + ks * 16) * 2 + a_hi);
#pragma unroll
            for (int pp = 0; pp < 2; pp++)
                LDSM4(b[2 * pp][0], b[2 * pp][1], b[2 * pp + 1][0], b[2 * pp + 1][1],
                      bs_s + ((wn + pp * 16 + b_n) * ASTR + ks * 16) * 2 + b_hi);
#pragma unroll
            for (int mt = 0; mt < 4; mt++)
#pragma unroll
                for (int nt = 0; nt < 4; nt++)
                    MMA_F16(c[mt][nt], a[mt], b[nt]);
        }
    }

    if (EPI == 3) {
#pragma unroll
        for (int mt = 0; mt < 4; mt++)
#pragma unroll
            for (int h = 0; h < 2; h++) {
                int row = bm + wm + mt * 16 + (lane >> 2) + h * 8;
                int win = row / NTOK, t = row % NTOK;
                float* dst;
                const float* xsrc = nullptr;
                if (t == 0) {
                    dst = gtout + (size_t)win * C_;
                } else {
                    int l = unscatter_l(win, t);
                    dst  = Cd  + (size_t)l * C_;
                    xsrc = res + (size_t)l * C_;
                }
#pragma unroll
                for (int nt = 0; nt < 4; nt++) {
                    int col = bn + wn + nt * 8 + 2 * (lane & 3);
                    float2 bb = *(const float2*)&bias[col];
                    float2 v;
                    v.x = c[mt][nt][2 * h]     + bb.x;
                    v.y = c[mt][nt][2 * h + 1] + bb.y;
                    if (xsrc) {
                        float2 rv = *(const float2*)&xsrc[col];
                        v.x += rv.x; v.y += rv.y;
                    }
                    *(float2*)&dst[col] = v;
                }
            }
    } else {
#pragma unroll
        for (int nt = 0; nt < 4; nt++) {
            int col = bn + wn + nt * 8 + 2 * (lane & 3);
            float2 bb = *(const float2*)&bias[col];
#pragma unroll
            for (int mt = 0; mt < 4; mt++) {
                int row0 = bm + wm + mt * 16 + (lane >> 2);
#pragma unroll
                for (int h = 0; h < 2; h++) {
                    int row = row0 + h * 8;
                    if (row < Mstore) {
                        float2 v;
                        v.x = c[mt][nt][2 * h]     + bb.x;
                        v.y = c[mt][nt][2 * h + 1] + bb.y;
                        size_t o = (size_t)row * N + col;
                        if (EPI == 0) {
                            *(__half2*)&Cdh[o] = __floats2half2_rn(v.x, v.y);
                        } else if (EPI == 1) {
                            v.x = gelu_f(v.x); v.y = gelu_f(v.y);
                            *(__half2*)&Cdh[o] = __floats2half2_rn(v.x, v.y);
                        } else {
                            float2 rv = *(const float2*)&res[o];
                            v.x += rv.x; v.y += rv.y;
                            *(float2*)&Cd[o] = v;
                        }
                    }
                }
            }
        }
    }
}

/* ---------------- launch ------------------------------------------------ */
extern "C" void kernel_launch(void* const* d_in, const int* in_sizes, int n_in,
                              void* d_out, int out_size) {
    const float* x     = (const float*)d_in[0];
    const float* gt    = (const float*)d_in[1];
    const float* n1g   = (const float*)d_in[2];
    const float* n1b   = (const float*)d_in[3];
    const float* qkvw  = (const float*)d_in[4];
    const float* qkvb  = (const float*)d_in[5];
    const float* btab  = (const float*)d_in[6];
    const float* projw = (const float*)d_in[7];
    const float* projb = (const float*)d_in[8];
    const float* n2g   = (const float*)d_in[9];
    const float* n2b   = (const float*)d_in[10];
    const float* fc1w  = (const float*)d_in[11];
    const float* fc1b  = (const float*)d_in[12];
    const float* fc2w  = (const float*)d_in[13];
    const float* fc2b  = (const float*)d_in[14];
    float* out = (float*)d_out;

    __half *xc, *qkv, *ao, *ln2b, *hb, *wq, *wp, *w1, *w2;
    float *xres;
    cudaGetSymbolAddress((void**)&xc,   g_xc);
    cudaGetSymbolAddress((void**)&qkv,  g_qkv);
    cudaGetSymbolAddress((void**)&ao,   g_attnout);
    cudaGetSymbolAddress((void**)&xres, g_xres);
    cudaGetSymbolAddress((void**)&ln2b, g_ln2);
    cudaGetSymbolAddress((void**)&hb,   g_hid);
    cudaGetSymbolAddress((void**)&wq,   g_wqkv);
    cudaGetSymbolAddress((void**)&wp,   g_wproj);
    cudaGetSymbolAddress((void**)&w1,   g_wfc1);
    cudaGetSymbolAddress((void**)&w2,   g_wfc2);

    cudaFuncSetAttribute(attn_mma,
                         cudaFuncAttributeMaxDynamicSharedMemorySize,
                         ATT_SMEM);
    cudaFuncSetAttribute(gemm_tc<0>,
                         cudaFuncAttributeMaxDynamicSharedMemorySize,
                         GEMM_SMEM_BYTES);
    cudaFuncSetAttribute(gemm_tc<1>,
                         cudaFuncAttributeMaxDynamicSharedMemorySize,
                         GEMM_SMEM_BYTES);
    cudaFuncSetAttribute(gemm_tc<2>,
                         cudaFuncAttributeMaxDynamicSharedMemorySize,
                         GEMM_SMEM_BYTES);
    cudaFuncSetAttribute(gemm_tc<3>,
                         cudaFuncAttributeMaxDynamicSharedMemorySize,
                         GEMM_SMEM_BYTES);

    dim3 tb(32, 8);
    ln1_scatter <<<L_ / 8, 256>>>(x, n1g, n1b);                       /* 0 */
    biasgt_build<<<(CB_TOT + NW * C_ + 255) / 256, 256>>>(btab, gt);  /* 1 */
    wtrans_pair <<<dim3((3 * C_) / 32, C_ / 32, 2), tb>>>(
        qkvw, wq, C_, 3 * C_, projw, wp, C_, C_);                     /* 2 */

    gemm_tc<0><<<dim3((3 * C_) / 128, M1 / 128), 256, GEMM_SMEM_BYTES>>>(
        xc, wq, qkvb, nullptr, nullptr, qkv, nullptr, M1, 3 * C_, C_); /* 3 */

    wtrans_pair<<<dim3(HID / 32, HID / 32, 2), tb>>>(
        fc1w, w1, C_, HID, fc2w, w2, HID, C_);                        /* 4 */

    attn_mma<<<NW * HEADS, 256, ATT_SMEM>>>();                        /* 5 */

    gemm_tc<3><<<dim3(C_ / 128, M1 / 128), 256, GEMM_SMEM_BYTES>>>(
        ao, wp, projb, x, xres, nullptr, out + (size_t)L_ * C_, M1, C_, C_);

    ln2_kernel<<<L_ / 8, 256>>>(n2g, n2b);

    gemm_tc<1><<<dim3(HID / 128, M1 / 128), 256, GEMM_SMEM_BYTES>>>(
        ln2b, w1, fc1b, nullptr, nullptr, hb, nullptr, M1, HID, C_);

    gemm_tc<2><<<dim3(C_ / 128, M1 / 128), 256, GEMM_SMEM_BYTES>>>(
        hb, w2, fc2b, xres, out, nullptr, nullptr, L_, C_, HID);
}